// round 1
// baseline (speedup 1.0000x reference)
#include <cuda_runtime.h>
#include <math.h>

// Problem constants
#define Bc  2
#define Sc  2048
#define Dc  1024
#define Hc  16
#define DHc 64
#define Mrows (Bc*Sc)          // 4096

// Scratch (device globals: no allocation allowed)
__device__ float g_Q [Bc*Hc*Sc*DHc];   // [B,H,S,DH]
__device__ float g_K [Bc*Hc*Sc*DHc];
__device__ float g_V [Bc*Hc*Sc*DHc];
__device__ float g_AO[Bc*Sc*Dc];       // attention output, [B,S,D]

// ---------------------------------------------------------------------------
// SGEMM: C = A[M,K] @ W[K,N] + bias, BM=128 BN=64 BK=16, 256 thr, TM=8 TN=4
// MODE 0: C row-major [M,N].  MODE 1: scatter into [B,H,S,DH] head layout.
// ---------------------------------------------------------------------------
template <int MODE>
__global__ __launch_bounds__(256, 4)
void gemm_kernel(const float* __restrict__ A, const float* __restrict__ W,
                 const float* __restrict__ bias, float* __restrict__ C,
                 int M, int N, int K)
{
    __shared__ float As[16][128];   // [k][m] (transposed)
    __shared__ float Bs[16][64];    // [k][n]

    const int tid = threadIdx.x;
    const int tr  = tid >> 4;       // 0..15  (row group, 8 rows each)
    const int tc  = tid & 15;       // 0..15  (col group, 4 cols each)
    const int m0  = blockIdx.y * 128;
    const int n0  = blockIdx.x * 64;

    float acc[8][4];
#pragma unroll
    for (int i = 0; i < 8; i++)
#pragma unroll
        for (int j = 0; j < 4; j++) acc[i][j] = 0.f;

    const float* Ag = A + m0 * K;

    for (int k0 = 0; k0 < K; k0 += 16) {
        // A tile: 128x16, 512 float4 slots, 2 per thread, store transposed
#pragma unroll
        for (int t = 0; t < 2; t++) {
            int s  = tid + t * 256;
            int r  = s >> 2;
            int c4 = (s & 3) * 4;
            float4 v = *(const float4*)(Ag + r * K + k0 + c4);
            As[c4 + 0][r] = v.x; As[c4 + 1][r] = v.y;
            As[c4 + 2][r] = v.z; As[c4 + 3][r] = v.w;
        }
        // B tile: 16x64, 256 float4 slots, 1 per thread, natural layout
        {
            int r  = tid >> 4;
            int c4 = (tid & 15) * 4;
            *(float4*)(&Bs[r][c4]) = *(const float4*)(W + (k0 + r) * N + n0 + c4);
        }
        __syncthreads();

#pragma unroll
        for (int k = 0; k < 16; k++) {
            float a[8], b[4];
            *(float4*)(a)     = *(const float4*)(&As[k][tr * 8]);
            *(float4*)(a + 4) = *(const float4*)(&As[k][tr * 8 + 4]);
            *(float4*)(b)     = *(const float4*)(&Bs[k][tc * 4]);
#pragma unroll
            for (int i = 0; i < 8; i++)
#pragma unroll
                for (int j = 0; j < 4; j++) acc[i][j] += a[i] * b[j];
        }
        __syncthreads();
    }

    // Epilogue (vectorized; BN=64 == DH so a 4-col chunk never crosses a head)
    const int colb = n0 + tc * 4;
    float4 bv = *(const float4*)(bias + colb);
#pragma unroll
    for (int i = 0; i < 8; i++) {
        int row = m0 + tr * 8 + i;
        float4 o;
        o.x = acc[i][0] + bv.x; o.y = acc[i][1] + bv.y;
        o.z = acc[i][2] + bv.z; o.w = acc[i][3] + bv.w;
        if (MODE == 0) {
            *(float4*)(C + row * N + colb) = o;
        } else {
            int bb = row >> 11, s = row & (Sc - 1);
            int h  = colb >> 6, dh = colb & 63;
            *(float4*)(C + (((bb * Hc + h) * Sc + s) * DHc) + dh) = o;
        }
    }
}

// ---------------------------------------------------------------------------
// Flash attention (fp32, causal). Block: 64 q-rows x one (b,h). 256 threads.
// Dynamic smem 64KB: Qt[d][r], Ks[d][c], Vs[k][dh], Pt[k][r] each 64x64.
// ---------------------------------------------------------------------------
__global__ __launch_bounds__(256)
void attn_kernel(float* __restrict__ out)
{
    extern __shared__ float sm[];
    float* Qt = sm;                 // [d][r]
    float* Ks = sm + 4096;          // [d][c]
    float* Vs = sm + 8192;          // [k][dh]
    float* Pt = sm + 12288;         // [k][r]

    const int tid = threadIdx.x;
    const int tr  = tid >> 4;       // q-row group (4 rows)
    const int tc  = tid & 15;       // col group (4 cols)
    const int qt  = blockIdx.x;     // q tile index 0..31
    const int bh  = blockIdx.y;     // 0..31
    const int q0  = qt * 64;

    const float* Qg = g_Q + bh * (Sc * DHc);
    const float* Kg = g_K + bh * (Sc * DHc);
    const float* Vg = g_V + bh * (Sc * DHc);

    // Load Q tile transposed
#pragma unroll
    for (int t = 0; t < 4; t++) {
        int slot = tid + t * 256;
        int r = slot >> 4, c4 = (slot & 15) * 4;
        float4 v = *(const float4*)(Qg + (q0 + r) * DHc + c4);
        Qt[(c4 + 0) * 64 + r] = v.x; Qt[(c4 + 1) * 64 + r] = v.y;
        Qt[(c4 + 2) * 64 + r] = v.z; Qt[(c4 + 3) * 64 + r] = v.w;
    }

    float m_i[4], l_i[4], acc[4][4];
#pragma unroll
    for (int i = 0; i < 4; i++) {
        m_i[i] = -1e30f; l_i[i] = 0.f;
#pragma unroll
        for (int j = 0; j < 4; j++) acc[i][j] = 0.f;
    }

    const int nkt = qt + 1;                 // causal: only tiles with k0 <= q end
    for (int kt = 0; kt < nkt; kt++) {
        const int k0 = kt * 64;
        // Load K transposed + V natural
#pragma unroll
        for (int t = 0; t < 4; t++) {
            int slot = tid + t * 256;
            int r = slot >> 4, c4 = (slot & 15) * 4;
            float4 v = *(const float4*)(Kg + (k0 + r) * DHc + c4);
            Ks[(c4 + 0) * 64 + r] = v.x; Ks[(c4 + 1) * 64 + r] = v.y;
            Ks[(c4 + 2) * 64 + r] = v.z; Ks[(c4 + 3) * 64 + r] = v.w;
            float4 w = *(const float4*)(Vg + (k0 + r) * DHc + c4);
            *(float4*)(Vs + r * 64 + c4) = w;
        }
        __syncthreads();

        // S = Q @ K^T (4x4 micro-tile)
        float s[4][4];
#pragma unroll
        for (int i = 0; i < 4; i++)
#pragma unroll
            for (int j = 0; j < 4; j++) s[i][j] = 0.f;
#pragma unroll 8
        for (int d = 0; d < 64; d++) {
            float4 a = *(const float4*)(Qt + d * 64 + tr * 4);
            float4 b = *(const float4*)(Ks + d * 64 + tc * 4);
            float av[4] = {a.x, a.y, a.z, a.w};
            float bv[4] = {b.x, b.y, b.z, b.w};
#pragma unroll
            for (int i = 0; i < 4; i++)
#pragma unroll
                for (int j = 0; j < 4; j++) s[i][j] += av[i] * bv[j];
        }

        // scale + causal mask
        const float scale = 0.125f;   // 1/sqrt(64)
#pragma unroll
        for (int i = 0; i < 4; i++) {
            int qrow = q0 + tr * 4 + i;
#pragma unroll
            for (int j = 0; j < 4; j++) {
                int kcol = k0 + tc * 4 + j;
                s[i][j] = (kcol <= qrow) ? s[i][j] * scale : -1e30f;
            }
        }

        // online softmax update per row (reduce across 16-lane half-warp)
#pragma unroll
        for (int i = 0; i < 4; i++) {
            float mx = fmaxf(fmaxf(s[i][0], s[i][1]), fmaxf(s[i][2], s[i][3]));
#pragma unroll
            for (int off = 8; off >= 1; off >>= 1)
                mx = fmaxf(mx, __shfl_xor_sync(0xffffffffu, mx, off, 16));
            float mnew = fmaxf(m_i[i], mx);
            float corr = __expf(m_i[i] - mnew);
            float rs = 0.f;
#pragma unroll
            for (int j = 0; j < 4; j++) {
                float p = __expf(s[i][j] - mnew);
                s[i][j] = p;
                rs += p;
            }
#pragma unroll
            for (int off = 8; off >= 1; off >>= 1)
                rs += __shfl_xor_sync(0xffffffffu, rs, off, 16);
            l_i[i] = l_i[i] * corr + rs;
            m_i[i] = mnew;
#pragma unroll
            for (int j = 0; j < 4; j++) acc[i][j] *= corr;
        }

        // write P transposed: Pt[c][r]
#pragma unroll
        for (int j = 0; j < 4; j++)
#pragma unroll
            for (int i = 0; i < 4; i++)
                Pt[(tc * 4 + j) * 64 + (tr * 4 + i)] = s[i][j];
        __syncthreads();

        // O += P @ V
#pragma unroll 8
        for (int k = 0; k < 64; k++) {
            float4 a = *(const float4*)(Pt + k * 64 + tr * 4);
            float4 b = *(const float4*)(Vs + k * 64 + tc * 4);
            float av[4] = {a.x, a.y, a.z, a.w};
            float bv[4] = {b.x, b.y, b.z, b.w};
#pragma unroll
            for (int i = 0; i < 4; i++)
#pragma unroll
                for (int j = 0; j < 4; j++) acc[i][j] += av[i] * bv[j];
        }
        __syncthreads();   // protect Ks/Vs/Pt before next iteration
    }

    // epilogue: normalize, write [B,S,D]
    const int b = bh >> 4, h = bh & 15;
#pragma unroll
    for (int i = 0; i < 4; i++) {
        int srow = q0 + tr * 4 + i;
        float inv = 1.f / l_i[i];
        float4 o;
        o.x = acc[i][0] * inv; o.y = acc[i][1] * inv;
        o.z = acc[i][2] * inv; o.w = acc[i][3] * inv;
        *(float4*)(out + (b * Sc + srow) * Dc + h * DHc + tc * 4) = o;
    }
}

// ---------------------------------------------------------------------------
extern "C" void kernel_launch(void* const* d_in, const int* in_sizes, int n_in,
                              void* d_out, int out_size)
{
    const float* x  = (const float*)d_in[0];
    // d_in[1] = causal mask (implemented analytically, unused)
    const float* Wq = (const float*)d_in[2];
    const float* bq = (const float*)d_in[3];
    const float* Wk = (const float*)d_in[4];
    const float* bk = (const float*)d_in[5];
    const float* Wv = (const float*)d_in[6];
    const float* bv = (const float*)d_in[7];
    const float* Wo = (const float*)d_in[8];
    const float* bo = (const float*)d_in[9];
    float* out = (float*)d_out;

    float *Qp, *Kp, *Vp, *AOp;
    cudaGetSymbolAddress((void**)&Qp,  g_Q);
    cudaGetSymbolAddress((void**)&Kp,  g_K);
    cudaGetSymbolAddress((void**)&Vp,  g_V);
    cudaGetSymbolAddress((void**)&AOp, g_AO);

    dim3 ggrid(Dc / 64, Mrows / 128);   // (16, 32)

    gemm_kernel<1><<<ggrid, 256>>>(x, Wq, bq, Qp, Mrows, Dc, Dc);
    gemm_kernel<1><<<ggrid, 256>>>(x, Wk, bk, Kp, Mrows, Dc, Dc);
    gemm_kernel<1><<<ggrid, 256>>>(x, Wv, bv, Vp, Mrows, Dc, Dc);

    cudaFuncSetAttribute(attn_kernel,
                         cudaFuncAttributeMaxDynamicSharedMemorySize, 65536);
    attn_kernel<<<dim3(Sc / 64, Bc * Hc), 256, 65536>>>(AOp);

    gemm_kernel<0><<<ggrid, 256>>>(AOp, Wo, bo, out, Mrows, Dc, Dc);
}

// round 3
// speedup vs baseline: 1.0023x; 1.0023x over previous
#include <cuda_runtime.h>
#include <math.h>

// Problem constants
#define Bc  2
#define Sc  2048
#define Dc  1024
#define Hc  16
#define DHc 64
#define Mrows (Bc*Sc)          // 4096

// Scratch (device globals: no allocation allowed)
__device__ float g_Q [Bc*Hc*Sc*DHc];   // [B,H,S,DH]
__device__ float g_K [Bc*Hc*Sc*DHc];
__device__ float g_V [Bc*Hc*Sc*DHc];
__device__ float g_AO[Bc*Sc*Dc];       // attention output, [B,S,D]

// ---------------------------------------------------------------------------
// SGEMM: C = A[M,K] @ W[K,N] + bias, BM=128 BN=64 BK=16, 256 thr, TM=8 TN=4
// MODE 0: C row-major [M,N].  MODE 1: scatter into [B,H,S,DH] head layout.
// ---------------------------------------------------------------------------
template <int MODE>
__global__ __launch_bounds__(256, 4)
void gemm_kernel(const float* __restrict__ A, const float* __restrict__ W,
                 const float* __restrict__ bias, float* __restrict__ C,
                 int M, int N, int K)
{
    __shared__ float As[16][128];   // [k][m] (transposed)
    __shared__ float Bs[16][64];    // [k][n]

    const int tid = threadIdx.x;
    const int tr  = tid >> 4;       // 0..15  (row group, 8 rows each)
    const int tc  = tid & 15;       // 0..15  (col group, 4 cols each)
    const int m0  = blockIdx.y * 128;
    const int n0  = blockIdx.x * 64;

    float acc[8][4];
#pragma unroll
    for (int i = 0; i < 8; i++)
#pragma unroll
        for (int j = 0; j < 4; j++) acc[i][j] = 0.f;

    const float* Ag = A + m0 * K;

    for (int k0 = 0; k0 < K; k0 += 16) {
        // A tile: 128x16, 512 float4 slots, 2 per thread, store transposed
#pragma unroll
        for (int t = 0; t < 2; t++) {
            int s  = tid + t * 256;
            int r  = s >> 2;
            int c4 = (s & 3) * 4;
            float4 v = *(const float4*)(Ag + r * K + k0 + c4);
            As[c4 + 0][r] = v.x; As[c4 + 1][r] = v.y;
            As[c4 + 2][r] = v.z; As[c4 + 3][r] = v.w;
        }
        // B tile: 16x64, 256 float4 slots, 1 per thread, natural layout
        {
            int r  = tid >> 4;
            int c4 = (tid & 15) * 4;
            *(float4*)(&Bs[r][c4]) = *(const float4*)(W + (k0 + r) * N + n0 + c4);
        }
        __syncthreads();

#pragma unroll
        for (int k = 0; k < 16; k++) {
            float a[8], b[4];
            *(float4*)(a)     = *(const float4*)(&As[k][tr * 8]);
            *(float4*)(a + 4) = *(const float4*)(&As[k][tr * 8 + 4]);
            *(float4*)(b)     = *(const float4*)(&Bs[k][tc * 4]);
#pragma unroll
            for (int i = 0; i < 8; i++)
#pragma unroll
                for (int j = 0; j < 4; j++) acc[i][j] += a[i] * b[j];
        }
        __syncthreads();
    }

    // Epilogue (vectorized; BN=64 == DH so a 4-col chunk never crosses a head)
    const int colb = n0 + tc * 4;
    float4 bv = *(const float4*)(bias + colb);
#pragma unroll
    for (int i = 0; i < 8; i++) {
        int row = m0 + tr * 8 + i;
        float4 o;
        o.x = acc[i][0] + bv.x; o.y = acc[i][1] + bv.y;
        o.z = acc[i][2] + bv.z; o.w = acc[i][3] + bv.w;
        if (MODE == 0) {
            *(float4*)(C + row * N + colb) = o;
        } else {
            int bb = row >> 11, s = row & (Sc - 1);
            int h  = colb >> 6, dh = colb & 63;
            *(float4*)(C + (((bb * Hc + h) * Sc + s) * DHc) + dh) = o;
        }
    }
}

// ---------------------------------------------------------------------------
// Flash attention (fp32, causal). Block: 64 q-rows x one (b,h). 256 threads.
// Dynamic smem 64KB: Qt[d][r], Ks[d][c], Vs[k][dh], Pt[k][r] each 64x64.
// ---------------------------------------------------------------------------
__global__ __launch_bounds__(256)
void attn_kernel(float* __restrict__ out)
{
    extern __shared__ float sm[];
    float* Qt = sm;                 // [d][r]
    float* Ks = sm + 4096;          // [d][c]
    float* Vs = sm + 8192;          // [k][dh]
    float* Pt = sm + 12288;         // [k][r]

    const int tid = threadIdx.x;
    const int tr  = tid >> 4;       // q-row group (4 rows)
    const int tc  = tid & 15;       // col group (4 cols)
    const int qt  = blockIdx.x;     // q tile index 0..31
    const int bh  = blockIdx.y;     // 0..31
    const int q0  = qt * 64;

    const float* Qg = g_Q + bh * (Sc * DHc);
    const float* Kg = g_K + bh * (Sc * DHc);
    const float* Vg = g_V + bh * (Sc * DHc);

    // Load Q tile transposed
#pragma unroll
    for (int t = 0; t < 4; t++) {
        int slot = tid + t * 256;
        int r = slot >> 4, c4 = (slot & 15) * 4;
        float4 v = *(const float4*)(Qg + (q0 + r) * DHc + c4);
        Qt[(c4 + 0) * 64 + r] = v.x; Qt[(c4 + 1) * 64 + r] = v.y;
        Qt[(c4 + 2) * 64 + r] = v.z; Qt[(c4 + 3) * 64 + r] = v.w;
    }

    float m_i[4], l_i[4], acc[4][4];
#pragma unroll
    for (int i = 0; i < 4; i++) {
        m_i[i] = -1e30f; l_i[i] = 0.f;
#pragma unroll
        for (int j = 0; j < 4; j++) acc[i][j] = 0.f;
    }

    const int nkt = qt + 1;                 // causal: only tiles with k0 <= q end
    for (int kt = 0; kt < nkt; kt++) {
        const int k0 = kt * 64;
        // Load K transposed + V natural
#pragma unroll
        for (int t = 0; t < 4; t++) {
            int slot = tid + t * 256;
            int r = slot >> 4, c4 = (slot & 15) * 4;
            float4 v = *(const float4*)(Kg + (k0 + r) * DHc + c4);
            Ks[(c4 + 0) * 64 + r] = v.x; Ks[(c4 + 1) * 64 + r] = v.y;
            Ks[(c4 + 2) * 64 + r] = v.z; Ks[(c4 + 3) * 64 + r] = v.w;
            float4 w = *(const float4*)(Vg + (k0 + r) * DHc + c4);
            *(float4*)(Vs + r * 64 + c4) = w;
        }
        __syncthreads();

        // S = Q @ K^T (4x4 micro-tile)
        float s[4][4];
#pragma unroll
        for (int i = 0; i < 4; i++)
#pragma unroll
            for (int j = 0; j < 4; j++) s[i][j] = 0.f;
#pragma unroll 8
        for (int d = 0; d < 64; d++) {
            float4 a = *(const float4*)(Qt + d * 64 + tr * 4);
            float4 b = *(const float4*)(Ks + d * 64 + tc * 4);
            float av[4] = {a.x, a.y, a.z, a.w};
            float bv[4] = {b.x, b.y, b.z, b.w};
#pragma unroll
            for (int i = 0; i < 4; i++)
#pragma unroll
                for (int j = 0; j < 4; j++) s[i][j] += av[i] * bv[j];
        }

        // scale + causal mask
        const float scale = 0.125f;   // 1/sqrt(64)
#pragma unroll
        for (int i = 0; i < 4; i++) {
            int qrow = q0 + tr * 4 + i;
#pragma unroll
            for (int j = 0; j < 4; j++) {
                int kcol = k0 + tc * 4 + j;
                s[i][j] = (kcol <= qrow) ? s[i][j] * scale : -1e30f;
            }
        }

        // online softmax update per row (reduce across 16-lane half-warp)
#pragma unroll
        for (int i = 0; i < 4; i++) {
            float mx = fmaxf(fmaxf(s[i][0], s[i][1]), fmaxf(s[i][2], s[i][3]));
#pragma unroll
            for (int off = 8; off >= 1; off >>= 1)
                mx = fmaxf(mx, __shfl_xor_sync(0xffffffffu, mx, off, 16));
            float mnew = fmaxf(m_i[i], mx);
            float corr = __expf(m_i[i] - mnew);
            float rs = 0.f;
#pragma unroll
            for (int j = 0; j < 4; j++) {
                float p = __expf(s[i][j] - mnew);
                s[i][j] = p;
                rs += p;
            }
#pragma unroll
            for (int off = 8; off >= 1; off >>= 1)
                rs += __shfl_xor_sync(0xffffffffu, rs, off, 16);
            l_i[i] = l_i[i] * corr + rs;
            m_i[i] = mnew;
#pragma unroll
            for (int j = 0; j < 4; j++) acc[i][j] *= corr;
        }

        // write P transposed: Pt[c][r]
#pragma unroll
        for (int j = 0; j < 4; j++)
#pragma unroll
            for (int i = 0; i < 4; i++)
                Pt[(tc * 4 + j) * 64 + (tr * 4 + i)] = s[i][j];
        __syncthreads();

        // O += P @ V
#pragma unroll 8
        for (int k = 0; k < 64; k++) {
            float4 a = *(const float4*)(Pt + k * 64 + tr * 4);
            float4 b = *(const float4*)(Vs + k * 64 + tc * 4);
            float av[4] = {a.x, a.y, a.z, a.w};
            float bv[4] = {b.x, b.y, b.z, b.w};
#pragma unroll
            for (int i = 0; i < 4; i++)
#pragma unroll
                for (int j = 0; j < 4; j++) acc[i][j] += av[i] * bv[j];
        }
        __syncthreads();   // protect Ks/Vs/Pt before next iteration
    }

    // epilogue: normalize, write [B,S,D]
    const int b = bh >> 4, h = bh & 15;
#pragma unroll
    for (int i = 0; i < 4; i++) {
        int srow = q0 + tr * 4 + i;
        float inv = 1.f / l_i[i];
        float4 o;
        o.x = acc[i][0] * inv; o.y = acc[i][1] * inv;
        o.z = acc[i][2] * inv; o.w = acc[i][3] * inv;
        *(float4*)(out + (b * Sc + srow) * Dc + h * DHc + tc * 4) = o;
    }
}

// ---------------------------------------------------------------------------
extern "C" void kernel_launch(void* const* d_in, const int* in_sizes, int n_in,
                              void* d_out, int out_size)
{
    const float* x  = (const float*)d_in[0];
    // d_in[1] = causal mask (implemented analytically, unused)
    const float* Wq = (const float*)d_in[2];
    const float* bq = (const float*)d_in[3];
    const float* Wk = (const float*)d_in[4];
    const float* bk = (const float*)d_in[5];
    const float* Wv = (const float*)d_in[6];
    const float* bv = (const float*)d_in[7];
    const float* Wo = (const float*)d_in[8];
    const float* bo = (const float*)d_in[9];
    float* out = (float*)d_out;

    float *Qp, *Kp, *Vp, *AOp;
    cudaGetSymbolAddress((void**)&Qp,  g_Q);
    cudaGetSymbolAddress((void**)&Kp,  g_K);
    cudaGetSymbolAddress((void**)&Vp,  g_V);
    cudaGetSymbolAddress((void**)&AOp, g_AO);

    dim3 ggrid(Dc / 64, Mrows / 128);   // (16, 32)

    gemm_kernel<1><<<ggrid, 256>>>(x, Wq, bq, Qp, Mrows, Dc, Dc);
    gemm_kernel<1><<<ggrid, 256>>>(x, Wk, bk, Kp, Mrows, Dc, Dc);
    gemm_kernel<1><<<ggrid, 256>>>(x, Wv, bv, Vp, Mrows, Dc, Dc);

    cudaFuncSetAttribute(attn_kernel,
                         cudaFuncAttributeMaxDynamicSharedMemorySize, 65536);
    attn_kernel<<<dim3(Sc / 64, Bc * Hc), 256, 65536>>>(AOp);

    gemm_kernel<0><<<ggrid, 256>>>(AOp, Wo, bo, out, Mrows, Dc, Dc);
}

// round 5
// speedup vs baseline: 1.4209x; 1.4176x over previous
#include <cuda_runtime.h>
#include <cuda_bf16.h>
#include <cstdint>
#include <math.h>

#define Bc  2
#define Sc  2048
#define Dc  1024
#define Hc  16
#define DHc 64
#define Mrows (Bc*Sc)          // 4096

__device__ float g_Q [Bc*Hc*Sc*DHc];
__device__ float g_K [Bc*Hc*Sc*DHc];
__device__ float g_V [Bc*Hc*Sc*DHc];
__device__ float g_AO[Bc*Sc*Dc];
__device__ float g_WT[4][Dc*Dc];       // W^T: [n][k]

// ---------------- helpers ----------------
__device__ __forceinline__ uint32_t smem_u32(const void* p) {
    uint32_t a;
    asm("{ .reg .u64 t; cvta.to.shared.u64 t, %1; cvt.u32.u64 %0, t; }" : "=r"(a) : "l"(p));
    return a;
}
__device__ __forceinline__ void ldsm4(uint32_t* r, uint32_t addr) {
    asm volatile("ldmatrix.sync.aligned.m8n8.x4.shared.b16 {%0,%1,%2,%3}, [%4];"
        : "=r"(r[0]), "=r"(r[1]), "=r"(r[2]), "=r"(r[3]) : "r"(addr));
}
__device__ __forceinline__ void mma16816(float* d, const uint32_t* a,
                                         uint32_t b0, uint32_t b1) {
    asm volatile("mma.sync.aligned.m16n8k16.row.col.f32.bf16.bf16.f32 "
        "{%0,%1,%2,%3}, {%4,%5,%6,%7}, {%8,%9}, {%0,%1,%2,%3};"
        : "+f"(d[0]), "+f"(d[1]), "+f"(d[2]), "+f"(d[3])
        : "r"(a[0]), "r"(a[1]), "r"(a[2]), "r"(a[3]), "r"(b0), "r"(b1));
}
__device__ __forceinline__ uint32_t pack2bf(float x, float y) {
    __nv_bfloat162 h = __floats2bfloat162_rn(x, y);
    return *(uint32_t*)&h;
}

// ---------------- transpose 1024x1024 ----------------
__global__ void transpose_kernel(const float* __restrict__ src, float* __restrict__ dst)
{
    __shared__ float t[32][33];
    int x = blockIdx.x * 32 + threadIdx.x, y = blockIdx.y * 32 + threadIdx.y;
#pragma unroll
    for (int i = 0; i < 32; i += 8) t[threadIdx.y + i][threadIdx.x] = src[(y + i) * Dc + x];
    __syncthreads();
    x = blockIdx.y * 32 + threadIdx.x; y = blockIdx.x * 32 + threadIdx.y;
#pragma unroll
    for (int i = 0; i < 32; i += 8) dst[(y + i) * Dc + x] = t[threadIdx.x][threadIdx.y + i];
}

// ---------------------------------------------------------------------------
// bf16 split-mma GEMM: C[4096,1024] = A[m][k] @ W + bias,  Bm = W^T ([n][k]).
// Tile 128x128, BK=32, 256 thr (8 warps, 2x4). 2-stage smem double buffer.
// smem tiles bf16, row stride 48 elems (96B, 16B-aligned for ldmatrix).
// Per stage: Ahi | Alo | Bhi | Blo, each 128*48*2 = 12288B -> 49152B/stage.
// MODE 0: C row-major.  MODE 1: scatter to [B,H,S,DH].
// ---------------------------------------------------------------------------
#define TILE_B  12288u
#define STAGE_B 49152u

template <int MODE>
__global__ __launch_bounds__(256)
void gemm_mma(const float* __restrict__ A, const float* __restrict__ Bm,
              const float* __restrict__ bias, float* __restrict__ C)
{
    extern __shared__ unsigned char smraw[];
    const uint32_t sb = smem_u32(smraw);

    const int tid = threadIdx.x;
    const int wid = tid >> 5, lid = tid & 31;
    const int wr = wid >> 2, wc = wid & 3;          // warp 2x4 grid
    const int m0 = blockIdx.y * 128, n0 = blockIdx.x * 128;

    const float* Ag = A  + (size_t)m0 * Dc;
    const float* Bg = Bm + (size_t)n0 * Dc;

    float acc[4][4][4];
#pragma unroll
    for (int mt = 0; mt < 4; mt++)
#pragma unroll
        for (int nt = 0; nt < 4; nt++)
#pragma unroll
            for (int e = 0; e < 4; e++) acc[mt][nt][e] = 0.f;

    // per-thread gmem staging slots
    const int srow = tid >> 3;              // 0..31  (+t*32)
    const int sc4  = (tid & 7) * 4;         // 0,4,...,28

    float4 ra[4], rb[4];

    auto LDG = [&](int c) {
#pragma unroll
        for (int t = 0; t < 4; t++) {
            int r = srow + t * 32;
            ra[t] = *(const float4*)(Ag + (size_t)r * Dc + c * 32 + sc4);
            rb[t] = *(const float4*)(Bg + (size_t)r * Dc + c * 32 + sc4);
        }
    };
    auto STS = [&](int st) {
        const uint32_t base = (uint32_t)st * STAGE_B;
#pragma unroll
        for (int t = 0; t < 4; t++) {
            int r = srow + t * 32;
            uint32_t off = base + ((uint32_t)r * 48u + (uint32_t)sc4) * 2u;
            // A hi/lo
            float4 v = ra[t];
            float hx = __bfloat162float(__float2bfloat16_rn(v.x));
            float hy = __bfloat162float(__float2bfloat16_rn(v.y));
            float hz = __bfloat162float(__float2bfloat16_rn(v.z));
            float hw = __bfloat162float(__float2bfloat16_rn(v.w));
            *(uint2*)(smraw + off) =
                make_uint2(pack2bf(hx, hy), pack2bf(hz, hw));
            *(uint2*)(smraw + off + TILE_B) =
                make_uint2(pack2bf(v.x - hx, v.y - hy), pack2bf(v.z - hz, v.w - hw));
            // B hi/lo
            v = rb[t];
            hx = __bfloat162float(__float2bfloat16_rn(v.x));
            hy = __bfloat162float(__float2bfloat16_rn(v.y));
            hz = __bfloat162float(__float2bfloat16_rn(v.z));
            hw = __bfloat162float(__float2bfloat16_rn(v.w));
            *(uint2*)(smraw + off + 2u * TILE_B) =
                make_uint2(pack2bf(hx, hy), pack2bf(hz, hw));
            *(uint2*)(smraw + off + 3u * TILE_B) =
                make_uint2(pack2bf(v.x - hx, v.y - hy), pack2bf(v.z - hz, v.w - hw));
        }
    };

    LDG(0);
    STS(0);
    __syncthreads();

    const int lrow = lid & 15;
    const int lko  = (lid >> 4) << 3;

    for (int c = 0; c < 32; c++) {
        const int st = c & 1;
        if (c < 31) LDG(c + 1);

        const uint32_t base = sb + (uint32_t)st * STAGE_B;
#pragma unroll
        for (int ks = 0; ks < 2; ks++) {
            const uint32_t lk = (uint32_t)(ks * 16 + lko);
            uint32_t af[4][4], al[4][4], bf2[2][4], bl2[2][4];
#pragma unroll
            for (int mt = 0; mt < 4; mt++) {
                uint32_t ad = base + ((uint32_t)(wr * 64 + mt * 16 + lrow) * 48u + lk) * 2u;
                ldsm4(af[mt], ad);
                ldsm4(al[mt], ad + TILE_B);
            }
#pragma unroll
            for (int nt2 = 0; nt2 < 2; nt2++) {
                uint32_t bd = base + 2u * TILE_B +
                              ((uint32_t)(wc * 32 + nt2 * 16 + lrow) * 48u + lk) * 2u;
                ldsm4(bf2[nt2], bd);
                ldsm4(bl2[nt2], bd + TILE_B);
            }
#pragma unroll
            for (int mt = 0; mt < 4; mt++)
#pragma unroll
                for (int n8 = 0; n8 < 4; n8++) {
                    const int nt2 = n8 >> 1, sel = n8 & 1;
                    mma16816(acc[mt][n8], af[mt], bf2[nt2][sel], bf2[nt2][sel + 2]);
                    mma16816(acc[mt][n8], af[mt], bl2[nt2][sel], bl2[nt2][sel + 2]);
                    mma16816(acc[mt][n8], al[mt], bf2[nt2][sel], bf2[nt2][sel + 2]);
                }
        }

        if (c < 31) {
            __syncthreads();          // everyone done computing stage st^1's prior use
            STS((c + 1) & 1);
            __syncthreads();          // new stage visible
        }
    }

    // epilogue
    const int gid = lid >> 2, tig = lid & 3;
#pragma unroll
    for (int mt = 0; mt < 4; mt++) {
#pragma unroll
        for (int nt = 0; nt < 4; nt++) {
            int row = m0 + wr * 64 + mt * 16 + gid;
            int col = n0 + wc * 32 + nt * 8 + tig * 2;
            float bx = bias[col], by = bias[col + 1];
            float2 v0 = make_float2(acc[mt][nt][0] + bx, acc[mt][nt][1] + by);
            float2 v1 = make_float2(acc[mt][nt][2] + bx, acc[mt][nt][3] + by);
            if (MODE == 0) {
                *(float2*)(C + (size_t)row * Dc + col) = v0;
                *(float2*)(C + (size_t)(row + 8) * Dc + col) = v1;
            } else {
                int h = col >> 6, dh = col & 63;
                int bb = row >> 11, s = row & (Sc - 1);
                size_t p0 = ((size_t)(bb * Hc + h) * Sc + s) * DHc + dh;
                size_t p1 = ((size_t)(bb * Hc + h) * Sc + (s + 8)) * DHc + dh;
                // row+8 has same bb (rows within a 128-tile never cross batch: 2048 % 128 == 0)
                *(float2*)(C + p0) = v0;
                *(float2*)(C + p1) = v1;
            }
        }
    }
}

// ---------------------------------------------------------------------------
// Flash attention fp32, causal. q-tile 128 x one (b,h), k-tile 64.
// 128 threads, 8x8 micro-tile. Dyn smem 96KB. 2 CTA/SM.
// ---------------------------------------------------------------------------
__global__ __launch_bounds__(128)
void attn_kernel(float* __restrict__ out)
{
    extern __shared__ float sm[];
    float* Qt = sm;            // [d][r] 64x128
    float* Ks = sm + 8192;     // [d][c] 64x64
    float* Vs = sm + 12288;    // [k][dh] 64x64
    float* Pt = sm + 16384;    // [k][r] 64x128

    const int tid = threadIdx.x;
    const int tr = tid >> 3;   // 0..15, 8 rows each
    const int tc = tid & 7;    // 0..7,  8 cols each
    const int qt = blockIdx.x; // 0..15
    const int bh = blockIdx.y;
    const int q0 = qt * 128;

    const float* Qg = g_Q + (size_t)bh * (Sc * DHc);
    const float* Kg = g_K + (size_t)bh * (Sc * DHc);
    const float* Vg = g_V + (size_t)bh * (Sc * DHc);

#pragma unroll
    for (int t = 0; t < 16; t++) {
        int s = tid + t * 128;
        int r = s >> 4, c4 = (s & 15) * 4;
        float4 v = *(const float4*)(Qg + (size_t)(q0 + r) * DHc + c4);
        Qt[(c4 + 0) * 128 + r] = v.x; Qt[(c4 + 1) * 128 + r] = v.y;
        Qt[(c4 + 2) * 128 + r] = v.z; Qt[(c4 + 3) * 128 + r] = v.w;
    }

    float m_i[8], l_i[8], acc[8][8];
#pragma unroll
    for (int i = 0; i < 8; i++) {
        m_i[i] = -1e30f; l_i[i] = 0.f;
#pragma unroll
        for (int j = 0; j < 8; j++) acc[i][j] = 0.f;
    }

    const int nkt = 2 * (qt + 1);
    for (int kt = 0; kt < nkt; kt++) {
        const int k0 = kt * 64;
#pragma unroll
        for (int t = 0; t < 8; t++) {
            int s = tid + t * 128;
            int r = s >> 4, c4 = (s & 15) * 4;
            float4 v = *(const float4*)(Kg + (size_t)(k0 + r) * DHc + c4);
            Ks[(c4 + 0) * 64 + r] = v.x; Ks[(c4 + 1) * 64 + r] = v.y;
            Ks[(c4 + 2) * 64 + r] = v.z; Ks[(c4 + 3) * 64 + r] = v.w;
            float4 w = *(const float4*)(Vg + (size_t)(k0 + r) * DHc + c4);
            *(float4*)(Vs + r * 64 + c4) = w;
        }
        __syncthreads();

        float s8[8][8];
#pragma unroll
        for (int i = 0; i < 8; i++)
#pragma unroll
            for (int j = 0; j < 8; j++) s8[i][j] = 0.f;
#pragma unroll 4
        for (int d = 0; d < 64; d++) {
            float a[8], b[8];
            *(float4*)(a)     = *(const float4*)(Qt + d * 128 + tr * 8);
            *(float4*)(a + 4) = *(const float4*)(Qt + d * 128 + tr * 8 + 4);
            *(float4*)(b)     = *(const float4*)(Ks + d * 64 + tc * 8);
            *(float4*)(b + 4) = *(const float4*)(Ks + d * 64 + tc * 8 + 4);
#pragma unroll
            for (int i = 0; i < 8; i++)
#pragma unroll
                for (int j = 0; j < 8; j++) s8[i][j] += a[i] * b[j];
        }

        const float scale = 0.125f;
#pragma unroll
        for (int i = 0; i < 8; i++) {
            int qrow = q0 + tr * 8 + i;
#pragma unroll
            for (int j = 0; j < 8; j++) {
                int kcol = k0 + tc * 8 + j;
                s8[i][j] = (kcol <= qrow) ? s8[i][j] * scale : -1e30f;
            }
        }

#pragma unroll
        for (int i = 0; i < 8; i++) {
            float mx = s8[i][0];
#pragma unroll
            for (int j = 1; j < 8; j++) mx = fmaxf(mx, s8[i][j]);
#pragma unroll
            for (int off = 4; off >= 1; off >>= 1)
                mx = fmaxf(mx, __shfl_xor_sync(0xffffffffu, mx, off, 8));
            float mnew = fmaxf(m_i[i], mx);
            float corr = __expf(m_i[i] - mnew);
            float rs = 0.f;
#pragma unroll
            for (int j = 0; j < 8; j++) {
                float p = __expf(s8[i][j] - mnew);
                s8[i][j] = p; rs += p;
            }
#pragma unroll
            for (int off = 4; off >= 1; off >>= 1)
                rs += __shfl_xor_sync(0xffffffffu, rs, off, 8);
            l_i[i] = l_i[i] * corr + rs;
            m_i[i] = mnew;
#pragma unroll
            for (int j = 0; j < 8; j++) acc[i][j] *= corr;
        }

#pragma unroll
        for (int j = 0; j < 8; j++)
#pragma unroll
            for (int i = 0; i < 8; i++)
                Pt[(tc * 8 + j) * 128 + (tr * 8 + i)] = s8[i][j];
        __syncthreads();

#pragma unroll 4
        for (int k = 0; k < 64; k++) {
            float a[8], b[8];
            *(float4*)(a)     = *(const float4*)(Pt + k * 128 + tr * 8);
            *(float4*)(a + 4) = *(const float4*)(Pt + k * 128 + tr * 8 + 4);
            *(float4*)(b)     = *(const float4*)(Vs + k * 64 + tc * 8);
            *(float4*)(b + 4) = *(const float4*)(Vs + k * 64 + tc * 8 + 4);
#pragma unroll
            for (int i = 0; i < 8; i++)
#pragma unroll
                for (int j = 0; j < 8; j++) acc[i][j] += a[i] * b[j];
        }
        __syncthreads();
    }

    const int b = bh >> 4, h = bh & 15;
#pragma unroll
    for (int i = 0; i < 8; i++) {
        int srow = q0 + tr * 8 + i;
        float inv = 1.f / l_i[i];
        float4 o0, o1;
        o0.x = acc[i][0] * inv; o0.y = acc[i][1] * inv;
        o0.z = acc[i][2] * inv; o0.w = acc[i][3] * inv;
        o1.x = acc[i][4] * inv; o1.y = acc[i][5] * inv;
        o1.z = acc[i][6] * inv; o1.w = acc[i][7] * inv;
        float* dst = out + ((size_t)b * Sc + srow) * Dc + h * DHc + tc * 8;
        *(float4*)(dst)     = o0;
        *(float4*)(dst + 4) = o1;
    }
}

// ---------------------------------------------------------------------------
extern "C" void kernel_launch(void* const* d_in, const int* in_sizes, int n_in,
                              void* d_out, int out_size)
{
    const float* x  = (const float*)d_in[0];
    const float* Wq = (const float*)d_in[2];
    const float* bq = (const float*)d_in[3];
    const float* Wk = (const float*)d_in[4];
    const float* bk = (const float*)d_in[5];
    const float* Wv = (const float*)d_in[6];
    const float* bv = (const float*)d_in[7];
    const float* Wo = (const float*)d_in[8];
    const float* bo = (const float*)d_in[9];
    float* out = (float*)d_out;

    float *Qp, *Kp, *Vp, *AOp, *WTp;
    cudaGetSymbolAddress((void**)&Qp,  g_Q);
    cudaGetSymbolAddress((void**)&Kp,  g_K);
    cudaGetSymbolAddress((void**)&Vp,  g_V);
    cudaGetSymbolAddress((void**)&AOp, g_AO);
    cudaGetSymbolAddress((void**)&WTp, g_WT);

    dim3 tb(32, 8), tg(32, 32);
    transpose_kernel<<<tg, tb>>>(Wq, WTp + 0 * Dc * Dc);
    transpose_kernel<<<tg, tb>>>(Wk, WTp + 1 * Dc * Dc);
    transpose_kernel<<<tg, tb>>>(Wv, WTp + 2 * Dc * Dc);
    transpose_kernel<<<tg, tb>>>(Wo, WTp + 3 * Dc * Dc);

    const int gsmem = 2 * STAGE_B;   // 98304
    cudaFuncSetAttribute(gemm_mma<0>, cudaFuncAttributeMaxDynamicSharedMemorySize, gsmem);
    cudaFuncSetAttribute(gemm_mma<1>, cudaFuncAttributeMaxDynamicSharedMemorySize, gsmem);
    cudaFuncSetAttribute(attn_kernel, cudaFuncAttributeMaxDynamicSharedMemorySize, 98304);

    dim3 ggrid(Dc / 128, Mrows / 128);   // (8, 32)
    gemm_mma<1><<<ggrid, 256, gsmem>>>(x, WTp + 0 * Dc * Dc, bq, Qp);
    gemm_mma<1><<<ggrid, 256, gsmem>>>(x, WTp + 1 * Dc * Dc, bk, Kp);
    gemm_mma<1><<<ggrid, 256, gsmem>>>(x, WTp + 2 * Dc * Dc, bv, Vp);

    attn_kernel<<<dim3(Sc / 128, Bc * Hc), 128, 98304>>>(AOp);

    gemm_mma<0><<<ggrid, 256, gsmem>>>(AOp, WTp + 3 * Dc * Dc, bo, out);
}

// round 6
// speedup vs baseline: 2.5775x; 1.8141x over previous
#include <cuda_runtime.h>
#include <cuda_bf16.h>
#include <cstdint>
#include <math.h>

#define Bc  2
#define Sc  2048
#define Dc  1024
#define Hc  16
#define DHc 64
#define Mrows (Bc*Sc)          // 4096

__device__ float g_Q [Bc*Hc*Sc*DHc];
__device__ float g_K [Bc*Hc*Sc*DHc];
__device__ float g_V [Bc*Hc*Sc*DHc];
__device__ float g_AO[Bc*Sc*Dc];
__device__ float g_WT[4][Dc*Dc];       // W^T: [n][k]

// ---------------- helpers ----------------
__device__ __forceinline__ uint32_t smem_u32(const void* p) {
    uint32_t a;
    asm("{ .reg .u64 t; cvta.to.shared.u64 t, %1; cvt.u32.u64 %0, t; }" : "=r"(a) : "l"(p));
    return a;
}
__device__ __forceinline__ void ldsm4(uint32_t* r, uint32_t addr) {
    asm volatile("ldmatrix.sync.aligned.m8n8.x4.shared.b16 {%0,%1,%2,%3}, [%4];"
        : "=r"(r[0]), "=r"(r[1]), "=r"(r[2]), "=r"(r[3]) : "r"(addr));
}
__device__ __forceinline__ void ldsm4t(uint32_t* r, uint32_t addr) {
    asm volatile("ldmatrix.sync.aligned.m8n8.x4.trans.shared.b16 {%0,%1,%2,%3}, [%4];"
        : "=r"(r[0]), "=r"(r[1]), "=r"(r[2]), "=r"(r[3]) : "r"(addr));
}
__device__ __forceinline__ void mma16816(float* d, const uint32_t* a,
                                         uint32_t b0, uint32_t b1) {
    asm volatile("mma.sync.aligned.m16n8k16.row.col.f32.bf16.bf16.f32 "
        "{%0,%1,%2,%3}, {%4,%5,%6,%7}, {%8,%9}, {%0,%1,%2,%3};"
        : "+f"(d[0]), "+f"(d[1]), "+f"(d[2]), "+f"(d[3])
        : "r"(a[0]), "r"(a[1]), "r"(a[2]), "r"(a[3]), "r"(b0), "r"(b1));
}
__device__ __forceinline__ uint32_t pack2bf(float x, float y) {
    __nv_bfloat162 h = __floats2bfloat162_rn(x, y);
    return *(uint32_t*)&h;
}
__device__ __forceinline__ void split2(float x, float y, uint32_t& hi, uint32_t& lo) {
    float hx = __bfloat162float(__float2bfloat16_rn(x));
    float hy = __bfloat162float(__float2bfloat16_rn(y));
    hi = pack2bf(hx, hy);
    lo = pack2bf(x - hx, y - hy);
}

// ---------------- transpose 1024x1024 ----------------
__global__ void transpose_kernel(const float* __restrict__ src, float* __restrict__ dst)
{
    __shared__ float t[32][33];
    int x = blockIdx.x * 32 + threadIdx.x, y = blockIdx.y * 32 + threadIdx.y;
#pragma unroll
    for (int i = 0; i < 32; i += 8) t[threadIdx.y + i][threadIdx.x] = src[(y + i) * Dc + x];
    __syncthreads();
    x = blockIdx.y * 32 + threadIdx.x; y = blockIdx.x * 32 + threadIdx.y;
#pragma unroll
    for (int i = 0; i < 32; i += 8) dst[(y + i) * Dc + x] = t[threadIdx.x][threadIdx.y + i];
}

// ---------------------------------------------------------------------------
// bf16 split-mma GEMM (unchanged from R5 passing version)
// ---------------------------------------------------------------------------
#define TILE_B  12288u
#define STAGE_B 49152u

template <int MODE>
__global__ __launch_bounds__(256)
void gemm_mma(const float* __restrict__ A, const float* __restrict__ Bm,
              const float* __restrict__ bias, float* __restrict__ C)
{
    extern __shared__ unsigned char smraw[];
    const uint32_t sb = smem_u32(smraw);

    const int tid = threadIdx.x;
    const int wid = tid >> 5, lid = tid & 31;
    const int wr = wid >> 2, wc = wid & 3;
    const int m0 = blockIdx.y * 128, n0 = blockIdx.x * 128;

    const float* Ag = A  + (size_t)m0 * Dc;
    const float* Bg = Bm + (size_t)n0 * Dc;

    float acc[4][4][4];
#pragma unroll
    for (int mt = 0; mt < 4; mt++)
#pragma unroll
        for (int nt = 0; nt < 4; nt++)
#pragma unroll
            for (int e = 0; e < 4; e++) acc[mt][nt][e] = 0.f;

    const int srow = tid >> 3;
    const int sc4  = (tid & 7) * 4;

    float4 ra[4], rb[4];

    auto LDG = [&](int c) {
#pragma unroll
        for (int t = 0; t < 4; t++) {
            int r = srow + t * 32;
            ra[t] = *(const float4*)(Ag + (size_t)r * Dc + c * 32 + sc4);
            rb[t] = *(const float4*)(Bg + (size_t)r * Dc + c * 32 + sc4);
        }
    };
    auto STS = [&](int st) {
        const uint32_t base = (uint32_t)st * STAGE_B;
#pragma unroll
        for (int t = 0; t < 4; t++) {
            int r = srow + t * 32;
            uint32_t off = base + ((uint32_t)r * 48u + (uint32_t)sc4) * 2u;
            float4 v = ra[t];
            uint32_t h0, l0, h1, l1;
            split2(v.x, v.y, h0, l0); split2(v.z, v.w, h1, l1);
            *(uint2*)(smraw + off)          = make_uint2(h0, h1);
            *(uint2*)(smraw + off + TILE_B) = make_uint2(l0, l1);
            v = rb[t];
            split2(v.x, v.y, h0, l0); split2(v.z, v.w, h1, l1);
            *(uint2*)(smraw + off + 2u * TILE_B) = make_uint2(h0, h1);
            *(uint2*)(smraw + off + 3u * TILE_B) = make_uint2(l0, l1);
        }
    };

    LDG(0);
    STS(0);
    __syncthreads();

    const int lrow = lid & 15;
    const int lko  = (lid >> 4) << 3;

    for (int c = 0; c < 32; c++) {
        const int st = c & 1;
        if (c < 31) LDG(c + 1);

        const uint32_t base = sb + (uint32_t)st * STAGE_B;
#pragma unroll
        for (int ks = 0; ks < 2; ks++) {
            const uint32_t lk = (uint32_t)(ks * 16 + lko);
            uint32_t af[4][4], al[4][4], bf2[2][4], bl2[2][4];
#pragma unroll
            for (int mt = 0; mt < 4; mt++) {
                uint32_t ad = base + ((uint32_t)(wr * 64 + mt * 16 + lrow) * 48u + lk) * 2u;
                ldsm4(af[mt], ad);
                ldsm4(al[mt], ad + TILE_B);
            }
#pragma unroll
            for (int nt2 = 0; nt2 < 2; nt2++) {
                uint32_t bd = base + 2u * TILE_B +
                              ((uint32_t)(wc * 32 + nt2 * 16 + lrow) * 48u + lk) * 2u;
                ldsm4(bf2[nt2], bd);
                ldsm4(bl2[nt2], bd + TILE_B);
            }
#pragma unroll
            for (int mt = 0; mt < 4; mt++)
#pragma unroll
                for (int n8 = 0; n8 < 4; n8++) {
                    const int nt2 = n8 >> 1, sel = n8 & 1;
                    mma16816(acc[mt][n8], af[mt], bf2[nt2][sel], bf2[nt2][sel + 2]);
                    mma16816(acc[mt][n8], af[mt], bl2[nt2][sel], bl2[nt2][sel + 2]);
                    mma16816(acc[mt][n8], al[mt], bf2[nt2][sel], bf2[nt2][sel + 2]);
                }
        }

        if (c < 31) {
            __syncthreads();
            STS((c + 1) & 1);
            __syncthreads();
        }
    }

    const int gid = lid >> 2, tig = lid & 3;
#pragma unroll
    for (int mt = 0; mt < 4; mt++) {
#pragma unroll
        for (int nt = 0; nt < 4; nt++) {
            int row = m0 + wr * 64 + mt * 16 + gid;
            int col = n0 + wc * 32 + nt * 8 + tig * 2;
            float bx = bias[col], by = bias[col + 1];
            float2 v0 = make_float2(acc[mt][nt][0] + bx, acc[mt][nt][1] + by);
            float2 v1 = make_float2(acc[mt][nt][2] + bx, acc[mt][nt][3] + by);
            if (MODE == 0) {
                *(float2*)(C + (size_t)row * Dc + col) = v0;
                *(float2*)(C + (size_t)(row + 8) * Dc + col) = v1;
            } else {
                int h = col >> 6, dh = col & 63;
                int bb = row >> 11, s = row & (Sc - 1);
                size_t p0 = ((size_t)(bb * Hc + h) * Sc + s) * DHc + dh;
                size_t p1 = ((size_t)(bb * Hc + h) * Sc + (s + 8)) * DHc + dh;
                *(float2*)(C + p0) = v0;
                *(float2*)(C + p1) = v1;
            }
        }
    }
}

// ---------------------------------------------------------------------------
// Flash attention via bf16 split mma. CTA: 128 q-rows x one (b,h), 256 thr.
// k-tile 128. Smem (stride 72 bf16 rows): Qhi Qlo Khi Klo Vhi Vlo, 18KB each.
// ---------------------------------------------------------------------------
#define AT_STRIDE 72u
#define AT_TILE   18432u   // 128*72*2

__global__ __launch_bounds__(256, 1)
void attn_mma(float* __restrict__ out)
{
    extern __shared__ unsigned char smraw[];
    const uint32_t sb = smem_u32(smraw);
    const uint32_t QHI = 0, QLO = AT_TILE, KHI = 2*AT_TILE, KLO = 3*AT_TILE,
                   VHI = 4*AT_TILE, VLO = 5*AT_TILE;

    const int tid = threadIdx.x;
    const int wid = tid >> 5, lid = tid & 31;
    const int gid = lid >> 2, tig = lid & 3;
    const int lrow = lid & 15, lko = (lid >> 4) << 3;
    const int qt = blockIdx.x;       // 0..15
    const int bh = blockIdx.y;       // 0..31
    const int q0 = qt * 128;

    const float* Qg = g_Q + (size_t)bh * (Sc * DHc);
    const float* Kg = g_K + (size_t)bh * (Sc * DHc);
    const float* Vg = g_V + (size_t)bh * (Sc * DHc);

    // --- load Q tile (128x64 fp32) -> Qhi/Qlo smem ---
    {
        const int r = tid >> 4, c4 = (tid & 15) * 4;
#pragma unroll
        for (int t = 0; t < 8; t++) {
            int rr = r + t * 16;
            float4 v = *(const float4*)(Qg + (size_t)(q0 + rr) * DHc + c4);
            uint32_t h0, l0, h1, l1;
            split2(v.x, v.y, h0, l0); split2(v.z, v.w, h1, l1);
            uint32_t off = ((uint32_t)rr * AT_STRIDE + (uint32_t)c4) * 2u;
            *(uint2*)(smraw + QHI + off) = make_uint2(h0, h1);
            *(uint2*)(smraw + QLO + off) = make_uint2(l0, l1);
        }
    }
    __syncthreads();

    // --- Q fragments (warp strip rows wid*16..+15), 4 k-steps ---
    uint32_t qh[4][4], ql[4][4];
#pragma unroll
    for (int ks = 0; ks < 4; ks++) {
        uint32_t ad = sb + QHI + ((uint32_t)(wid * 16 + lrow) * AT_STRIDE +
                                  (uint32_t)(ks * 16 + lko)) * 2u;
        ldsm4(qh[ks], ad);
        ldsm4(ql[ks], ad + AT_TILE);
    }

    float m_i[2] = {-1e30f, -1e30f}, l_i[2] = {0.f, 0.f};
    float oacc[8][4];
#pragma unroll
    for (int n8 = 0; n8 < 8; n8++)
#pragma unroll
        for (int e = 0; e < 4; e++) oacc[n8][e] = 0.f;

    const int r16 = tid >> 4, c4g = (tid & 15) * 4;

    for (int kt = 0; kt <= qt; kt++) {
        const int k0 = kt * 128;

        // stage K,V in regs
        float4 rk[8], rv[8];
#pragma unroll
        for (int t = 0; t < 8; t++) {
            int rr = r16 + t * 16;
            rk[t] = *(const float4*)(Kg + (size_t)(k0 + rr) * DHc + c4g);
            rv[t] = *(const float4*)(Vg + (size_t)(k0 + rr) * DHc + c4g);
        }
        __syncthreads();   // prior iteration's ldmatrix reads are done
#pragma unroll
        for (int t = 0; t < 8; t++) {
            int rr = r16 + t * 16;
            uint32_t off = ((uint32_t)rr * AT_STRIDE + (uint32_t)c4g) * 2u;
            uint32_t h0, l0, h1, l1;
            split2(rk[t].x, rk[t].y, h0, l0); split2(rk[t].z, rk[t].w, h1, l1);
            *(uint2*)(smraw + KHI + off) = make_uint2(h0, h1);
            *(uint2*)(smraw + KLO + off) = make_uint2(l0, l1);
            split2(rv[t].x, rv[t].y, h0, l0); split2(rv[t].z, rv[t].w, h1, l1);
            *(uint2*)(smraw + VHI + off) = make_uint2(h0, h1);
            *(uint2*)(smraw + VLO + off) = make_uint2(l0, l1);
        }
        __syncthreads();

        // --- S = Q K^T : 16 n8-tiles ---
        float sacc[16][4];
#pragma unroll
        for (int j = 0; j < 16; j++)
#pragma unroll
            for (int e = 0; e < 4; e++) sacc[j][e] = 0.f;

#pragma unroll
        for (int ks = 0; ks < 4; ks++) {
#pragma unroll
            for (int nt2 = 0; nt2 < 8; nt2++) {
                uint32_t bh4[4], bl4[4];
                uint32_t bd = sb + KHI + ((uint32_t)(nt2 * 16 + lrow) * AT_STRIDE +
                                          (uint32_t)(ks * 16 + lko)) * 2u;
                ldsm4(bh4, bd);
                ldsm4(bl4, bd + AT_TILE);
#pragma unroll
                for (int sel = 0; sel < 2; sel++) {
                    const int j = nt2 * 2 + sel;
                    mma16816(sacc[j], qh[ks], bh4[sel], bh4[sel + 2]);
                    mma16816(sacc[j], qh[ks], bl4[sel], bl4[sel + 2]);
                    mma16816(sacc[j], ql[ks], bh4[sel], bh4[sel + 2]);
                }
            }
        }

        // --- scale + causal mask (diagonal tile only) ---
        const float scale = 0.125f;
        if (kt == qt) {
#pragma unroll
            for (int j = 0; j < 16; j++)
#pragma unroll
                for (int e = 0; e < 4; e++) {
                    int row = wid * 16 + gid + ((e >> 1) << 3);
                    int col = j * 8 + tig * 2 + (e & 1);
                    sacc[j][e] = (col <= row) ? sacc[j][e] * scale : -1e30f;
                }
        } else {
#pragma unroll
            for (int j = 0; j < 16; j++)
#pragma unroll
                for (int e = 0; e < 4; e++) sacc[j][e] *= scale;
        }

        // --- online softmax (rows gid, gid+8 of strip) ---
#pragma unroll
        for (int hrow = 0; hrow < 2; hrow++) {
            const int e0 = hrow * 2;
            float mx = sacc[0][e0];
#pragma unroll
            for (int j = 0; j < 16; j++) {
                mx = fmaxf(mx, sacc[j][e0]);
                mx = fmaxf(mx, sacc[j][e0 + 1]);
            }
            mx = fmaxf(mx, __shfl_xor_sync(0xffffffffu, mx, 1));
            mx = fmaxf(mx, __shfl_xor_sync(0xffffffffu, mx, 2));
            float mnew = fmaxf(m_i[hrow], mx);
            float corr = __expf(m_i[hrow] - mnew);
            float rs = 0.f;
#pragma unroll
            for (int j = 0; j < 16; j++) {
                float p0 = __expf(sacc[j][e0]     - mnew);
                float p1 = __expf(sacc[j][e0 + 1] - mnew);
                sacc[j][e0] = p0; sacc[j][e0 + 1] = p1;
                rs += p0 + p1;
            }
            rs += __shfl_xor_sync(0xffffffffu, rs, 1);
            rs += __shfl_xor_sync(0xffffffffu, rs, 2);
            l_i[hrow] = l_i[hrow] * corr + rs;
            m_i[hrow] = mnew;
#pragma unroll
            for (int n8 = 0; n8 < 8; n8++) {
                oacc[n8][e0]     *= corr;
                oacc[n8][e0 + 1] *= corr;
            }
        }

        // --- O += P V : 8 k16-steps over the 128 k-cols ---
#pragma unroll
        for (int ks2 = 0; ks2 < 8; ks2++) {
            uint32_t pa[4], pl[4];
            split2(sacc[2*ks2][0],     sacc[2*ks2][1],     pa[0], pl[0]);
            split2(sacc[2*ks2][2],     sacc[2*ks2][3],     pa[1], pl[1]);
            split2(sacc[2*ks2+1][0],   sacc[2*ks2+1][1],   pa[2], pl[2]);
            split2(sacc[2*ks2+1][2],   sacc[2*ks2+1][3],   pa[3], pl[3]);

            const int mat = lid >> 3, rin = lid & 7;
            const uint32_t vrow = (uint32_t)(ks2 * 16 + (mat & 1) * 8 + rin);
#pragma unroll
            for (int n2 = 0; n2 < 4; n2++) {
                uint32_t vh4[4], vl4[4];
                uint32_t vd = sb + VHI + (vrow * AT_STRIDE +
                               (uint32_t)(n2 * 16 + (mat >> 1) * 8)) * 2u;
                ldsm4t(vh4, vd);
                ldsm4t(vl4, vd + AT_TILE);
#pragma unroll
                for (int sel = 0; sel < 2; sel++) {
                    const int n8 = n2 * 2 + sel;
                    mma16816(oacc[n8], pa, vh4[sel * 2], vh4[sel * 2 + 1]);
                    mma16816(oacc[n8], pl, vh4[sel * 2], vh4[sel * 2 + 1]);
                    mma16816(oacc[n8], pa, vl4[sel * 2], vl4[sel * 2 + 1]);
                }
            }
        }
    }

    // --- epilogue: normalize + write [B,S,D] ---
    const int b = bh >> 4, h = bh & 15;
    const float inv0 = 1.f / l_i[0], inv1 = 1.f / l_i[1];
    const int row0 = q0 + wid * 16 + gid;
#pragma unroll
    for (int n8 = 0; n8 < 8; n8++) {
        const int col = h * DHc + n8 * 8 + tig * 2;
        *(float2*)(out + ((size_t)b * Sc + row0) * Dc + col) =
            make_float2(oacc[n8][0] * inv0, oacc[n8][1] * inv0);
        *(float2*)(out + ((size_t)b * Sc + row0 + 8) * Dc + col) =
            make_float2(oacc[n8][2] * inv1, oacc[n8][3] * inv1);
    }
}

// ---------------------------------------------------------------------------
extern "C" void kernel_launch(void* const* d_in, const int* in_sizes, int n_in,
                              void* d_out, int out_size)
{
    const float* x  = (const float*)d_in[0];
    const float* Wq = (const float*)d_in[2];
    const float* bq = (const float*)d_in[3];
    const float* Wk = (const float*)d_in[4];
    const float* bk = (const float*)d_in[5];
    const float* Wv = (const float*)d_in[6];
    const float* bv = (const float*)d_in[7];
    const float* Wo = (const float*)d_in[8];
    const float* bo = (const float*)d_in[9];
    float* out = (float*)d_out;

    float *Qp, *Kp, *Vp, *AOp, *WTp;
    cudaGetSymbolAddress((void**)&Qp,  g_Q);
    cudaGetSymbolAddress((void**)&Kp,  g_K);
    cudaGetSymbolAddress((void**)&Vp,  g_V);
    cudaGetSymbolAddress((void**)&AOp, g_AO);
    cudaGetSymbolAddress((void**)&WTp, g_WT);

    dim3 tb(32, 8), tg(32, 32);
    transpose_kernel<<<tg, tb>>>(Wq, WTp + 0 * Dc * Dc);
    transpose_kernel<<<tg, tb>>>(Wk, WTp + 1 * Dc * Dc);
    transpose_kernel<<<tg, tb>>>(Wv, WTp + 2 * Dc * Dc);
    transpose_kernel<<<tg, tb>>>(Wo, WTp + 3 * Dc * Dc);

    const int gsmem = 2 * STAGE_B;   // 98304
    cudaFuncSetAttribute(gemm_mma<0>, cudaFuncAttributeMaxDynamicSharedMemorySize, gsmem);
    cudaFuncSetAttribute(gemm_mma<1>, cudaFuncAttributeMaxDynamicSharedMemorySize, gsmem);
    cudaFuncSetAttribute(attn_mma, cudaFuncAttributeMaxDynamicSharedMemorySize, 6 * AT_TILE);

    dim3 ggrid(Dc / 128, Mrows / 128);   // (8, 32)
    gemm_mma<1><<<ggrid, 256, gsmem>>>(x, WTp + 0 * Dc * Dc, bq, Qp);
    gemm_mma<1><<<ggrid, 256, gsmem>>>(x, WTp + 1 * Dc * Dc, bk, Kp);
    gemm_mma<1><<<ggrid, 256, gsmem>>>(x, WTp + 2 * Dc * Dc, bv, Vp);

    attn_mma<<<dim3(Sc / 128, Bc * Hc), 256, 6 * AT_TILE>>>(AOp);

    gemm_mma<0><<<ggrid, 256, gsmem>>>(AOp, WTp + 3 * Dc * Dc, bo, out);
}

// round 7
// speedup vs baseline: 2.6678x; 1.0350x over previous
#include <cuda_runtime.h>
#include <cuda_bf16.h>
#include <cstdint>

#define Bc  2
#define Sc  2048
#define Dc  1024
#define Hc  16
#define DHc 64
#define Mrows (Bc*Sc)          // 4096
typedef __nv_bfloat16 bf16;

// ---------------- device scratch (no allocation allowed) ----------------
__device__ bf16 g_xh [Mrows*Dc], g_xl [Mrows*Dc];
__device__ bf16 g_Wh [4*Dc*Dc],  g_Wl [4*Dc*Dc];       // W^T hi/lo, [n][k]
__device__ bf16 g_Qh [Bc*Hc*Sc*DHc], g_Ql [Bc*Hc*Sc*DHc];
__device__ bf16 g_Kh [Bc*Hc*Sc*DHc], g_Kl [Bc*Hc*Sc*DHc];
__device__ bf16 g_Vh [Bc*Hc*Sc*DHc], g_Vl [Bc*Hc*Sc*DHc];
__device__ bf16 g_AOh[Mrows*Dc], g_AOl[Mrows*Dc];

// ---------------- helpers ----------------
__device__ __forceinline__ uint32_t smem_u32(const void* p) {
    uint32_t a;
    asm("{ .reg .u64 t; cvta.to.shared.u64 t, %1; cvt.u32.u64 %0, t; }" : "=r"(a) : "l"(p));
    return a;
}
__device__ __forceinline__ void ldsm4(uint32_t* r, uint32_t addr) {
    asm volatile("ldmatrix.sync.aligned.m8n8.x4.shared.b16 {%0,%1,%2,%3}, [%4];"
        : "=r"(r[0]), "=r"(r[1]), "=r"(r[2]), "=r"(r[3]) : "r"(addr));
}
__device__ __forceinline__ void ldsm4t(uint32_t* r, uint32_t addr) {
    asm volatile("ldmatrix.sync.aligned.m8n8.x4.trans.shared.b16 {%0,%1,%2,%3}, [%4];"
        : "=r"(r[0]), "=r"(r[1]), "=r"(r[2]), "=r"(r[3]) : "r"(addr));
}
__device__ __forceinline__ void mma16816(float* d, const uint32_t* a,
                                         uint32_t b0, uint32_t b1) {
    asm volatile("mma.sync.aligned.m16n8k16.row.col.f32.bf16.bf16.f32 "
        "{%0,%1,%2,%3}, {%4,%5,%6,%7}, {%8,%9}, {%0,%1,%2,%3};"
        : "+f"(d[0]), "+f"(d[1]), "+f"(d[2]), "+f"(d[3])
        : "r"(a[0]), "r"(a[1]), "r"(a[2]), "r"(a[3]), "r"(b0), "r"(b1));
}
__device__ __forceinline__ uint32_t pack2bf(float x, float y) {
    __nv_bfloat162 h = __floats2bfloat162_rn(x, y);
    return *(uint32_t*)&h;
}
__device__ __forceinline__ void split2(float x, float y, uint32_t& hi, uint32_t& lo) {
    float hx = __bfloat162float(__float2bfloat16_rn(x));
    float hy = __bfloat162float(__float2bfloat16_rn(y));
    hi = pack2bf(hx, hy);
    lo = pack2bf(x - hx, y - hy);
}
__device__ __forceinline__ void cpa16(uint32_t s, const void* g) {
    asm volatile("cp.async.cg.shared.global [%0], [%1], 16;" :: "r"(s), "l"(g));
}
__device__ __forceinline__ void cpa_commit() {
    asm volatile("cp.async.commit_group;" ::: "memory");
}
template<int N>
__device__ __forceinline__ void cpa_wait() {
    asm volatile("cp.async.wait_group %0;" :: "n"(N) : "memory");
}

// ---------------- prep: split x to bf16 hi/lo ----------------
__global__ void split_x_kernel(const float* __restrict__ src)
{
    size_t i = ((size_t)blockIdx.x * 256 + threadIdx.x) * 4;
    float4 v = *(const float4*)(src + i);
    uint32_t h0, l0, h1, l1;
    split2(v.x, v.y, h0, l0); split2(v.z, v.w, h1, l1);
    *(uint2*)(g_xh + i) = make_uint2(h0, h1);
    *(uint2*)(g_xl + i) = make_uint2(l0, l1);
}

// ---------------- prep: transpose + split W ----------------
__global__ void transpose_split_kernel(const float* __restrict__ src, int wsel)
{
    __shared__ float t[32][33];
    bf16* dh = g_Wh + (size_t)wsel * Dc * Dc;
    bf16* dl = g_Wl + (size_t)wsel * Dc * Dc;
    int x = blockIdx.x * 32 + threadIdx.x;   // n
    int y = blockIdx.y * 32 + threadIdx.y;   // k
#pragma unroll
    for (int i = 0; i < 32; i += 8) t[threadIdx.y + i][threadIdx.x] = src[(y + i) * Dc + x];
    __syncthreads();
    x = blockIdx.y * 32 + threadIdx.x;       // k
    y = blockIdx.x * 32 + threadIdx.y;       // n
#pragma unroll
    for (int i = 0; i < 32; i += 8) {
        float v = t[threadIdx.x][threadIdx.y + i];
        bf16 h = __float2bfloat16_rn(v);
        dh[(size_t)(y + i) * Dc + x] = h;
        dl[(size_t)(y + i) * Dc + x] = __float2bfloat16_rn(v - __bfloat162float(h));
    }
}

// ---------------------------------------------------------------------------
// bf16 split-mma GEMM with cp.async 3-stage pipeline.
// Tile 128x128, BK=32, 256 thr (8 warps 2x4). smem rows stride 40 bf16 (80B).
// MODE 1: fused QKV (grid.x=24: wsel=x>>3), out = hi/lo bf16 head layout.
// MODE 0: AO @ Wo^T + bo -> fp32 out (grid.x=8).
// ---------------------------------------------------------------------------
#define GT_TILE  10240u    // 128*40*2
#define GT_STAGE 40960u    // 4 tiles

template <int MODE>
__global__ __launch_bounds__(256)
void gemm_mma(const float* __restrict__ b0, const float* __restrict__ b1,
              const float* __restrict__ b2, float* __restrict__ outf)
{
    extern __shared__ unsigned char smraw[];
    const uint32_t sb = smem_u32(smraw);
    const int tid = threadIdx.x;
    const int wid = tid >> 5, lid = tid & 31;
    const int wr = wid >> 2, wc = wid & 3;
    const int m0 = blockIdx.y * 128;

    int wsel, n0;
    const bf16 *Ah_, *Al_, *Bh_, *Bl_;
    const float* bias;
    if (MODE == 1) {
        wsel = blockIdx.x >> 3; n0 = (blockIdx.x & 7) * 128;
        Ah_ = g_xh; Al_ = g_xl;
        Bh_ = g_Wh + (size_t)wsel * Dc * Dc; Bl_ = g_Wl + (size_t)wsel * Dc * Dc;
        bias = (wsel == 0) ? b0 : (wsel == 1) ? b1 : b2;
    } else {
        wsel = 3; n0 = blockIdx.x * 128;
        Ah_ = g_AOh; Al_ = g_AOl;
        Bh_ = g_Wh + (size_t)3 * Dc * Dc; Bl_ = g_Wl + (size_t)3 * Dc * Dc;
        bias = b0;
    }

    auto issue = [&](int c, int st) {
#pragma unroll
        for (int j = 0; j < 8; j++) {
            const int tile = j >> 1;                 // 0 Ah 1 Al 2 Bh 3 Bl
            const int idx = (j & 1) * 256 + tid;     // 0..511
            const int row = idx >> 2, ch = idx & 3;
            const bf16* g;
            if (tile == 0)      g = Ah_ + (size_t)(m0 + row) * Dc + c * 32 + ch * 8;
            else if (tile == 1) g = Al_ + (size_t)(m0 + row) * Dc + c * 32 + ch * 8;
            else if (tile == 2) g = Bh_ + (size_t)(n0 + row) * Dc + c * 32 + ch * 8;
            else                g = Bl_ + (size_t)(n0 + row) * Dc + c * 32 + ch * 8;
            cpa16(sb + (uint32_t)st * GT_STAGE +
                  (uint32_t)(tile * (int)GT_TILE + row * 80 + ch * 16), g);
        }
        cpa_commit();
    };

    float acc[4][4][4];
#pragma unroll
    for (int mt = 0; mt < 4; mt++)
#pragma unroll
        for (int nt = 0; nt < 4; nt++)
#pragma unroll
            for (int e = 0; e < 4; e++) acc[mt][nt][e] = 0.f;

    issue(0, 0);
    issue(1, 1);

    const int lrow = lid & 15;
    const int lko  = (lid >> 4) << 3;

    for (int c = 0; c < 32; c++) {
        if (c < 31) { cpa_wait<1>(); } else { cpa_wait<0>(); }
        __syncthreads();
        if (c < 30) issue(c + 2, (c + 2) % 3);

        const uint32_t base = sb + (uint32_t)(c % 3) * GT_STAGE;
#pragma unroll
        for (int ks = 0; ks < 2; ks++) {
            const uint32_t lk = (uint32_t)(ks * 16 + lko);
            uint32_t af[4][4], al[4][4], bf2[2][4], bl2[2][4];
#pragma unroll
            for (int mt = 0; mt < 4; mt++) {
                uint32_t ad = base + ((uint32_t)(wr * 64 + mt * 16 + lrow) * 40u + lk) * 2u;
                ldsm4(af[mt], ad);
                ldsm4(al[mt], ad + GT_TILE);
            }
#pragma unroll
            for (int nt2 = 0; nt2 < 2; nt2++) {
                uint32_t bd = base + 2u * GT_TILE +
                              ((uint32_t)(wc * 32 + nt2 * 16 + lrow) * 40u + lk) * 2u;
                ldsm4(bf2[nt2], bd);
                ldsm4(bl2[nt2], bd + GT_TILE);
            }
#pragma unroll
            for (int mt = 0; mt < 4; mt++)
#pragma unroll
                for (int n8 = 0; n8 < 4; n8++) {
                    const int nt2 = n8 >> 1, sel = n8 & 1;
                    mma16816(acc[mt][n8], af[mt], bf2[nt2][sel], bf2[nt2][sel + 2]);
                    mma16816(acc[mt][n8], af[mt], bl2[nt2][sel], bl2[nt2][sel + 2]);
                    mma16816(acc[mt][n8], al[mt], bf2[nt2][sel], bf2[nt2][sel + 2]);
                }
        }
    }

    // epilogue
    bf16* Oh = (wsel == 0) ? g_Qh : (wsel == 1) ? g_Kh : g_Vh;
    bf16* Ol = (wsel == 0) ? g_Ql : (wsel == 1) ? g_Kl : g_Vl;
    const int gid = lid >> 2, tig = lid & 3;
#pragma unroll
    for (int mt = 0; mt < 4; mt++) {
#pragma unroll
        for (int nt = 0; nt < 4; nt++) {
            int row = m0 + wr * 64 + mt * 16 + gid;
            int col = n0 + wc * 32 + nt * 8 + tig * 2;
            float bx = bias[col], by = bias[col + 1];
            float v00 = acc[mt][nt][0] + bx, v01 = acc[mt][nt][1] + by;
            float v10 = acc[mt][nt][2] + bx, v11 = acc[mt][nt][3] + by;
            if (MODE == 0) {
                *(float2*)(outf + (size_t)row * Dc + col) = make_float2(v00, v01);
                *(float2*)(outf + (size_t)(row + 8) * Dc + col) = make_float2(v10, v11);
            } else {
                int h = col >> 6, dh = col & 63;
                int bb = row >> 11, s = row & (Sc - 1);
                size_t p0 = ((size_t)(bb * Hc + h) * Sc + s) * DHc + dh;
                size_t p1 = ((size_t)(bb * Hc + h) * Sc + (s + 8)) * DHc + dh;
                uint32_t uh, ul;
                split2(v00, v01, uh, ul);
                *(uint32_t*)(Oh + p0) = uh; *(uint32_t*)(Ol + p0) = ul;
                split2(v10, v11, uh, ul);
                *(uint32_t*)(Oh + p1) = uh; *(uint32_t*)(Ol + p1) = ul;
            }
        }
    }
}

// ---------------------------------------------------------------------------
// Flash attention, bf16 split mma, pre-split inputs, double-buffered cp.async.
// CTA: 128 q-rows x one (b,h), 256 thr. k-tile 128.
// smem: 2 buffers x {Kh,Kl,Vh,Vl} tiles 128 x (stride 72) bf16 = 8*18432.
// Q staged once in buffer 1's Kh/Kl area.
// ---------------------------------------------------------------------------
#define AT_STRIDE 72u
#define AT_TILE   18432u   // 128*72*2

__global__ __launch_bounds__(256, 1)
void attn_mma()
{
    extern __shared__ unsigned char smraw[];
    const uint32_t sb = smem_u32(smraw);

    const int tid = threadIdx.x;
    const int wid = tid >> 5, lid = tid & 31;
    const int gid = lid >> 2, tig = lid & 3;
    const int lrow = lid & 15, lko = (lid >> 4) << 3;
    const int qt = blockIdx.x;       // 0..15
    const int bh = blockIdx.y;       // 0..31
    const int q0 = qt * 128;
    const size_t hb = (size_t)bh * (Sc * DHc);

    // --- stage Q (hi/lo) into buffer 1 tiles 0,1 via cp.async ---
#pragma unroll
    for (int j = 0; j < 8; j++) {
        const int tile = j >> 2;                  // 0 Qh, 1 Ql
        const int idx = (j & 3) * 256 + tid;      // 0..1023
        const int row = idx >> 3, ch = idx & 7;
        const bf16* g = (tile ? g_Ql : g_Qh) + hb + (size_t)(q0 + row) * DHc + ch * 8;
        cpa16(sb + (uint32_t)((4 + tile) * (int)AT_TILE + row * 144 + ch * 16), g);
    }
    cpa_commit();
    cpa_wait<0>();
    __syncthreads();

    uint32_t qh[4][4], ql[4][4];
#pragma unroll
    for (int ks = 0; ks < 4; ks++) {
        uint32_t ad = sb + 4u * AT_TILE + ((uint32_t)(wid * 16 + lrow) * AT_STRIDE +
                                           (uint32_t)(ks * 16 + lko)) * 2u;
        ldsm4(qh[ks], ad);
        ldsm4(ql[ks], ad + AT_TILE);
    }

    auto issue_kv = [&](int kt, int buf) {
        const uint32_t bb = sb + (uint32_t)buf * (4u * AT_TILE);
        const int k0 = kt * 128;
#pragma unroll
        for (int j = 0; j < 16; j++) {
            const int tile = j >> 2;              // 0 Kh 1 Kl 2 Vh 3 Vl
            const int idx = (j & 3) * 256 + tid;
            const int row = idx >> 3, ch = idx & 7;
            const bf16* g;
            if (tile == 0)      g = g_Kh;
            else if (tile == 1) g = g_Kl;
            else if (tile == 2) g = g_Vh;
            else                g = g_Vl;
            g += hb + (size_t)(k0 + row) * DHc + ch * 8;
            cpa16(bb + (uint32_t)(tile * (int)AT_TILE + row * 144 + ch * 16), g);
        }
        cpa_commit();
    };

    issue_kv(0, 0);

    float m_i[2] = {-1e30f, -1e30f}, l_i[2] = {0.f, 0.f};
    float oacc[8][4];
#pragma unroll
    for (int n8 = 0; n8 < 8; n8++)
#pragma unroll
        for (int e = 0; e < 4; e++) oacc[n8][e] = 0.f;

    for (int kt = 0; kt <= qt; kt++) {
        cpa_wait<0>();
        __syncthreads();
        if (kt < qt) issue_kv(kt + 1, (kt + 1) & 1);

        const uint32_t bb = sb + (uint32_t)(kt & 1) * (4u * AT_TILE);

        // --- S = Q K^T : 16 n8-tiles ---
        float sacc[16][4];
#pragma unroll
        for (int j = 0; j < 16; j++)
#pragma unroll
            for (int e = 0; e < 4; e++) sacc[j][e] = 0.f;

#pragma unroll
        for (int ks = 0; ks < 4; ks++) {
#pragma unroll
            for (int nt2 = 0; nt2 < 8; nt2++) {
                uint32_t bh4[4], bl4[4];
                uint32_t bd = bb + ((uint32_t)(nt2 * 16 + lrow) * AT_STRIDE +
                                    (uint32_t)(ks * 16 + lko)) * 2u;
                ldsm4(bh4, bd);
                ldsm4(bl4, bd + AT_TILE);
#pragma unroll
                for (int sel = 0; sel < 2; sel++) {
                    const int j = nt2 * 2 + sel;
                    mma16816(sacc[j], qh[ks], bh4[sel], bh4[sel + 2]);
                    mma16816(sacc[j], qh[ks], bl4[sel], bl4[sel + 2]);
                    mma16816(sacc[j], ql[ks], bh4[sel], bh4[sel + 2]);
                }
            }
        }

        // --- scale + causal mask ---
        const float scale = 0.125f;
        if (kt == qt) {
#pragma unroll
            for (int j = 0; j < 16; j++)
#pragma unroll
                for (int e = 0; e < 4; e++) {
                    int row = wid * 16 + gid + ((e >> 1) << 3);
                    int col = j * 8 + tig * 2 + (e & 1);
                    sacc[j][e] = (col <= row) ? sacc[j][e] * scale : -1e30f;
                }
        } else {
#pragma unroll
            for (int j = 0; j < 16; j++)
#pragma unroll
                for (int e = 0; e < 4; e++) sacc[j][e] *= scale;
        }

        // --- online softmax ---
#pragma unroll
        for (int hrow = 0; hrow < 2; hrow++) {
            const int e0 = hrow * 2;
            float mx = sacc[0][e0];
#pragma unroll
            for (int j = 0; j < 16; j++) {
                mx = fmaxf(mx, sacc[j][e0]);
                mx = fmaxf(mx, sacc[j][e0 + 1]);
            }
            mx = fmaxf(mx, __shfl_xor_sync(0xffffffffu, mx, 1));
            mx = fmaxf(mx, __shfl_xor_sync(0xffffffffu, mx, 2));
            float mnew = fmaxf(m_i[hrow], mx);
            float corr = __expf(m_i[hrow] - mnew);
            float rs = 0.f;
#pragma unroll
            for (int j = 0; j < 16; j++) {
                float p0 = __expf(sacc[j][e0]     - mnew);
                float p1 = __expf(sacc[j][e0 + 1] - mnew);
                sacc[j][e0] = p0; sacc[j][e0 + 1] = p1;
                rs += p0 + p1;
            }
            rs += __shfl_xor_sync(0xffffffffu, rs, 1);
            rs += __shfl_xor_sync(0xffffffffu, rs, 2);
            l_i[hrow] = l_i[hrow] * corr + rs;
            m_i[hrow] = mnew;
#pragma unroll
            for (int n8 = 0; n8 < 8; n8++) {
                oacc[n8][e0]     *= corr;
                oacc[n8][e0 + 1] *= corr;
            }
        }

        // --- O += P V ---
#pragma unroll
        for (int ks2 = 0; ks2 < 8; ks2++) {
            uint32_t pa[4], pl[4];
            split2(sacc[2*ks2][0],   sacc[2*ks2][1],   pa[0], pl[0]);
            split2(sacc[2*ks2][2],   sacc[2*ks2][3],   pa[1], pl[1]);
            split2(sacc[2*ks2+1][0], sacc[2*ks2+1][1], pa[2], pl[2]);
            split2(sacc[2*ks2+1][2], sacc[2*ks2+1][3], pa[3], pl[3]);

            const int mat = lid >> 3, rin = lid & 7;
            const uint32_t vrow = (uint32_t)(ks2 * 16 + (mat & 1) * 8 + rin);
#pragma unroll
            for (int n2 = 0; n2 < 4; n2++) {
                uint32_t vh4[4], vl4[4];
                uint32_t vd = bb + 2u * AT_TILE +
                              (vrow * AT_STRIDE + (uint32_t)(n2 * 16 + (mat >> 1) * 8)) * 2u;
                ldsm4t(vh4, vd);
                ldsm4t(vl4, vd + AT_TILE);
#pragma unroll
                for (int sel = 0; sel < 2; sel++) {
                    const int n8 = n2 * 2 + sel;
                    mma16816(oacc[n8], pa, vh4[sel * 2], vh4[sel * 2 + 1]);
                    mma16816(oacc[n8], pl, vh4[sel * 2], vh4[sel * 2 + 1]);
                    mma16816(oacc[n8], pa, vl4[sel * 2], vl4[sel * 2 + 1]);
                }
            }
        }
    }

    // --- epilogue: normalize + write AO hi/lo ([B,S,D]) ---
    const int b = bh >> 4, h = bh & 15;
    const float inv0 = 1.f / l_i[0], inv1 = 1.f / l_i[1];
    const int row0 = q0 + wid * 16 + gid;
#pragma unroll
    for (int n8 = 0; n8 < 8; n8++) {
        const int col = h * DHc + n8 * 8 + tig * 2;
        size_t p0 = ((size_t)b * Sc + row0) * Dc + col;
        size_t p1 = ((size_t)b * Sc + row0 + 8) * Dc + col;
        uint32_t uh, ul;
        split2(oacc[n8][0] * inv0, oacc[n8][1] * inv0, uh, ul);
        *(uint32_t*)(g_AOh + p0) = uh; *(uint32_t*)(g_AOl + p0) = ul;
        split2(oacc[n8][2] * inv1, oacc[n8][3] * inv1, uh, ul);
        *(uint32_t*)(g_AOh + p1) = uh; *(uint32_t*)(g_AOl + p1) = ul;
    }
}

// ---------------------------------------------------------------------------
extern "C" void kernel_launch(void* const* d_in, const int* in_sizes, int n_in,
                              void* d_out, int out_size)
{
    const float* x  = (const float*)d_in[0];
    const float* Wq = (const float*)d_in[2];
    const float* bq = (const float*)d_in[3];
    const float* Wk = (const float*)d_in[4];
    const float* bk = (const float*)d_in[5];
    const float* Wv = (const float*)d_in[6];
    const float* bv = (const float*)d_in[7];
    const float* Wo = (const float*)d_in[8];
    const float* bo = (const float*)d_in[9];
    float* out = (float*)d_out;

    // prep: split x, transpose+split weights
    split_x_kernel<<<Mrows * Dc / 1024, 256>>>(x);
    dim3 tb(32, 8), tg(32, 32);
    transpose_split_kernel<<<tg, tb>>>(Wq, 0);
    transpose_split_kernel<<<tg, tb>>>(Wk, 1);
    transpose_split_kernel<<<tg, tb>>>(Wv, 2);
    transpose_split_kernel<<<tg, tb>>>(Wo, 3);

    const int gsmem = 3 * GT_STAGE;     // 122880
    const int asmem = 8 * AT_TILE;      // 147456
    cudaFuncSetAttribute(gemm_mma<0>, cudaFuncAttributeMaxDynamicSharedMemorySize, gsmem);
    cudaFuncSetAttribute(gemm_mma<1>, cudaFuncAttributeMaxDynamicSharedMemorySize, gsmem);
    cudaFuncSetAttribute(attn_mma, cudaFuncAttributeMaxDynamicSharedMemorySize, asmem);

    // fused QKV projection
    gemm_mma<1><<<dim3(24, 32), 256, gsmem>>>(bq, bk, bv, nullptr);

    // attention
    attn_mma<<<dim3(Sc / 128, Bc * Hc), 256, asmem>>>();

    // output projection
    gemm_mma<0><<<dim3(8, 32), 256, gsmem>>>(bo, nullptr, nullptr, out);
}

// round 8
// speedup vs baseline: 2.9265x; 1.0970x over previous
#include <cuda_runtime.h>
#include <cuda_bf16.h>
#include <cstdint>

#define Bc  2
#define Sc  2048
#define Dc  1024
#define Hc  16
#define DHc 64
#define Mrows (Bc*Sc)          // 4096
typedef __nv_bfloat16 bf16;

// ---------------- device scratch (no allocation allowed) ----------------
__device__ bf16 g_xh [Mrows*Dc], g_xl [Mrows*Dc];
__device__ bf16 g_Wh [4*Dc*Dc],  g_Wl [4*Dc*Dc];       // W^T hi/lo, [n][k]
__device__ bf16 g_Qh [Bc*Hc*Sc*DHc], g_Ql [Bc*Hc*Sc*DHc];
__device__ bf16 g_Kh [Bc*Hc*Sc*DHc], g_Kl [Bc*Hc*Sc*DHc];
__device__ bf16 g_Vh [Bc*Hc*Sc*DHc], g_Vl [Bc*Hc*Sc*DHc];
__device__ bf16 g_AOh[Mrows*Dc], g_AOl[Mrows*Dc];
__device__ int  g_tick;

// ---------------- helpers ----------------
__device__ __forceinline__ uint32_t smem_u32(const void* p) {
    uint32_t a;
    asm("{ .reg .u64 t; cvta.to.shared.u64 t, %1; cvt.u32.u64 %0, t; }" : "=r"(a) : "l"(p));
    return a;
}
__device__ __forceinline__ void ldsm4(uint32_t* r, uint32_t addr) {
    asm volatile("ldmatrix.sync.aligned.m8n8.x4.shared.b16 {%0,%1,%2,%3}, [%4];"
        : "=r"(r[0]), "=r"(r[1]), "=r"(r[2]), "=r"(r[3]) : "r"(addr));
}
__device__ __forceinline__ void ldsm4t(uint32_t* r, uint32_t addr) {
    asm volatile("ldmatrix.sync.aligned.m8n8.x4.trans.shared.b16 {%0,%1,%2,%3}, [%4];"
        : "=r"(r[0]), "=r"(r[1]), "=r"(r[2]), "=r"(r[3]) : "r"(addr));
}
__device__ __forceinline__ void mma16816(float* d, const uint32_t* a,
                                         uint32_t b0, uint32_t b1) {
    asm volatile("mma.sync.aligned.m16n8k16.row.col.f32.bf16.bf16.f32 "
        "{%0,%1,%2,%3}, {%4,%5,%6,%7}, {%8,%9}, {%0,%1,%2,%3};"
        : "+f"(d[0]), "+f"(d[1]), "+f"(d[2]), "+f"(d[3])
        : "r"(a[0]), "r"(a[1]), "r"(a[2]), "r"(a[3]), "r"(b0), "r"(b1));
}
__device__ __forceinline__ uint32_t pack2bf(float x, float y) {
    __nv_bfloat162 h = __floats2bfloat162_rn(x, y);
    return *(uint32_t*)&h;
}
__device__ __forceinline__ void split2(float x, float y, uint32_t& hi, uint32_t& lo) {
    float hx = __bfloat162float(__float2bfloat16_rn(x));
    float hy = __bfloat162float(__float2bfloat16_rn(y));
    hi = pack2bf(hx, hy);
    lo = pack2bf(x - hx, y - hy);
}
__device__ __forceinline__ float ex2f(float x) {
    float y;
    asm("ex2.approx.f32 %0, %1;" : "=f"(y) : "f"(x));
    return y;
}
__device__ __forceinline__ void cpa16(uint32_t s, const void* g) {
    asm volatile("cp.async.cg.shared.global [%0], [%1], 16;" :: "r"(s), "l"(g));
}
__device__ __forceinline__ void cpa_commit() {
    asm volatile("cp.async.commit_group;" ::: "memory");
}
template<int N>
__device__ __forceinline__ void cpa_wait() {
    asm volatile("cp.async.wait_group %0;" :: "n"(N) : "memory");
}

// ---------------- prep: split x to bf16 hi/lo (+ticket reset) ----------------
__global__ void split_x_kernel(const float* __restrict__ src)
{
    if (blockIdx.x == 0 && threadIdx.x == 0) g_tick = 0;
    size_t i = ((size_t)blockIdx.x * 256 + threadIdx.x) * 4;
    float4 v = *(const float4*)(src + i);
    uint32_t h0, l0, h1, l1;
    split2(v.x, v.y, h0, l0); split2(v.z, v.w, h1, l1);
    *(uint2*)(g_xh + i) = make_uint2(h0, h1);
    *(uint2*)(g_xl + i) = make_uint2(l0, l1);
}

// ---------------- prep: transpose + split W ----------------
__global__ void transpose_split_kernel(const float* __restrict__ src, int wsel)
{
    __shared__ float t[32][33];
    bf16* dh = g_Wh + (size_t)wsel * Dc * Dc;
    bf16* dl = g_Wl + (size_t)wsel * Dc * Dc;
    int x = blockIdx.x * 32 + threadIdx.x;
    int y = blockIdx.y * 32 + threadIdx.y;
#pragma unroll
    for (int i = 0; i < 32; i += 8) t[threadIdx.y + i][threadIdx.x] = src[(y + i) * Dc + x];
    __syncthreads();
    x = blockIdx.y * 32 + threadIdx.x;
    y = blockIdx.x * 32 + threadIdx.y;
#pragma unroll
    for (int i = 0; i < 32; i += 8) {
        float v = t[threadIdx.x][threadIdx.y + i];
        bf16 h = __float2bfloat16_rn(v);
        dh[(size_t)(y + i) * Dc + x] = h;
        dl[(size_t)(y + i) * Dc + x] = __float2bfloat16_rn(v - __bfloat162float(h));
    }
}

// ---------------------------------------------------------------------------
// bf16 split-mma GEMM, cp.async 4-stage pipeline. Tile 128x128, BK=32, 256 thr.
// MODE 1: fused QKV (grid.x=24), bf16 hi/lo head-layout out.
// MODE 0: AO @ Wo^T + bo -> fp32 out (grid.x=8).
// ---------------------------------------------------------------------------
#define GT_TILE  10240u    // 128*40*2
#define GT_STAGE 40960u    // 4 tiles

template <int MODE>
__global__ __launch_bounds__(256)
void gemm_mma(const float* __restrict__ b0, const float* __restrict__ b1,
              const float* __restrict__ b2, float* __restrict__ outf)
{
    extern __shared__ unsigned char smraw[];
    const uint32_t sb = smem_u32(smraw);
    const int tid = threadIdx.x;
    const int wid = tid >> 5, lid = tid & 31;
    const int wr = wid >> 2, wc = wid & 3;
    const int m0 = blockIdx.y * 128;

    int wsel, n0;
    const bf16 *Ah_, *Al_, *Bh_, *Bl_;
    const float* bias;
    if (MODE == 1) {
        wsel = blockIdx.x >> 3; n0 = (blockIdx.x & 7) * 128;
        Ah_ = g_xh; Al_ = g_xl;
        Bh_ = g_Wh + (size_t)wsel * Dc * Dc; Bl_ = g_Wl + (size_t)wsel * Dc * Dc;
        bias = (wsel == 0) ? b0 : (wsel == 1) ? b1 : b2;
    } else {
        wsel = 3; n0 = blockIdx.x * 128;
        Ah_ = g_AOh; Al_ = g_AOl;
        Bh_ = g_Wh + (size_t)3 * Dc * Dc; Bl_ = g_Wl + (size_t)3 * Dc * Dc;
        bias = b0;
    }

    auto issue = [&](int c, int st) {
#pragma unroll
        for (int j = 0; j < 8; j++) {
            const int tile = j >> 1;                 // 0 Ah 1 Al 2 Bh 3 Bl
            const int idx = (j & 1) * 256 + tid;
            const int row = idx >> 2, ch = idx & 3;
            const bf16* g;
            if (tile == 0)      g = Ah_ + (size_t)(m0 + row) * Dc + c * 32 + ch * 8;
            else if (tile == 1) g = Al_ + (size_t)(m0 + row) * Dc + c * 32 + ch * 8;
            else if (tile == 2) g = Bh_ + (size_t)(n0 + row) * Dc + c * 32 + ch * 8;
            else                g = Bl_ + (size_t)(n0 + row) * Dc + c * 32 + ch * 8;
            cpa16(sb + (uint32_t)st * GT_STAGE +
                  (uint32_t)(tile * (int)GT_TILE + row * 80 + ch * 16), g);
        }
        cpa_commit();
    };

    float acc[4][4][4];
#pragma unroll
    for (int mt = 0; mt < 4; mt++)
#pragma unroll
        for (int nt = 0; nt < 4; nt++)
#pragma unroll
            for (int e = 0; e < 4; e++) acc[mt][nt][e] = 0.f;

    issue(0, 0);
    issue(1, 1);
    issue(2, 2);

    const int lrow = lid & 15;
    const int lko  = (lid >> 4) << 3;

    for (int c = 0; c < 32; c++) {
        if (c <= 29)      { cpa_wait<2>(); }
        else if (c == 30) { cpa_wait<1>(); }
        else              { cpa_wait<0>(); }
        __syncthreads();
        if (c < 29) issue(c + 3, (c + 3) & 3);

        const uint32_t base = sb + (uint32_t)(c & 3) * GT_STAGE;
#pragma unroll
        for (int ks = 0; ks < 2; ks++) {
            const uint32_t lk = (uint32_t)(ks * 16 + lko);
            uint32_t af[4][4], al[4][4], bf2[2][4], bl2[2][4];
#pragma unroll
            for (int mt = 0; mt < 4; mt++) {
                uint32_t ad = base + ((uint32_t)(wr * 64 + mt * 16 + lrow) * 40u + lk) * 2u;
                ldsm4(af[mt], ad);
                ldsm4(al[mt], ad + GT_TILE);
            }
#pragma unroll
            for (int nt2 = 0; nt2 < 2; nt2++) {
                uint32_t bd = base + 2u * GT_TILE +
                              ((uint32_t)(wc * 32 + nt2 * 16 + lrow) * 40u + lk) * 2u;
                ldsm4(bf2[nt2], bd);
                ldsm4(bl2[nt2], bd + GT_TILE);
            }
#pragma unroll
            for (int mt = 0; mt < 4; mt++)
#pragma unroll
                for (int n8 = 0; n8 < 4; n8++) {
                    const int nt2 = n8 >> 1, sel = n8 & 1;
                    mma16816(acc[mt][n8], af[mt], bf2[nt2][sel], bf2[nt2][sel + 2]);
                    mma16816(acc[mt][n8], af[mt], bl2[nt2][sel], bl2[nt2][sel + 2]);
                    mma16816(acc[mt][n8], al[mt], bf2[nt2][sel], bf2[nt2][sel + 2]);
                }
        }
    }

    // epilogue
    bf16* Oh = (wsel == 0) ? g_Qh : (wsel == 1) ? g_Kh : g_Vh;
    bf16* Ol = (wsel == 0) ? g_Ql : (wsel == 1) ? g_Kl : g_Vl;
    const int gid = lid >> 2, tig = lid & 3;
#pragma unroll
    for (int mt = 0; mt < 4; mt++) {
#pragma unroll
        for (int nt = 0; nt < 4; nt++) {
            int row = m0 + wr * 64 + mt * 16 + gid;
            int col = n0 + wc * 32 + nt * 8 + tig * 2;
            float bx = bias[col], by = bias[col + 1];
            float v00 = acc[mt][nt][0] + bx, v01 = acc[mt][nt][1] + by;
            float v10 = acc[mt][nt][2] + bx, v11 = acc[mt][nt][3] + by;
            if (MODE == 0) {
                *(float2*)(outf + (size_t)row * Dc + col) = make_float2(v00, v01);
                *(float2*)(outf + (size_t)(row + 8) * Dc + col) = make_float2(v10, v11);
            } else {
                int h = col >> 6, dh = col & 63;
                int bb = row >> 11, s = row & (Sc - 1);
                size_t p0 = ((size_t)(bb * Hc + h) * Sc + s) * DHc + dh;
                size_t p1 = ((size_t)(bb * Hc + h) * Sc + (s + 8)) * DHc + dh;
                uint32_t uh, ul;
                split2(v00, v01, uh, ul);
                *(uint32_t*)(Oh + p0) = uh; *(uint32_t*)(Ol + p0) = ul;
                split2(v10, v11, uh, ul);
                *(uint32_t*)(Oh + p1) = uh; *(uint32_t*)(Ol + p1) = ul;
            }
        }
    }
}

// ---------------------------------------------------------------------------
// Persistent ticket-scheduled flash attention (bf16 split mma, pre-split I/O).
// Work item = (qt, bh), heavy-first (qt descending). 256 thr, 1 CTA/SM.
// ---------------------------------------------------------------------------
#define AT_STRIDE 72u
#define AT_TILE   18432u   // 128*72*2
#define N_ITEMS   512      // 16 qt * 32 bh

__global__ __launch_bounds__(256, 1)
void attn_mma()
{
    extern __shared__ unsigned char smraw[];
    __shared__ int s_item;
    const uint32_t sb = smem_u32(smraw);

    const int tid = threadIdx.x;
    const int wid = tid >> 5, lid = tid & 31;
    const int gid = lid >> 2, tig = lid & 3;
    const int lrow = lid & 15, lko = (lid >> 4) << 3;

    for (;;) {
        if (tid == 0) s_item = atomicAdd(&g_tick, 1);
        __syncthreads();                 // also fences smem reuse between items
        const int item = s_item;
        if (item >= N_ITEMS) return;

        const int qt = 15 - (item >> 5);     // heavy first
        const int bh = item & 31;
        const int q0 = qt * 128;
        const size_t hb = (size_t)bh * (Sc * DHc);

        // --- stage Q (hi/lo) into buffer-1 K area ---
#pragma unroll
        for (int j = 0; j < 8; j++) {
            const int tile = j >> 2;              // 0 Qh, 1 Ql
            const int idx = (j & 3) * 256 + tid;
            const int row = idx >> 3, ch = idx & 7;
            const bf16* g = (tile ? g_Ql : g_Qh) + hb + (size_t)(q0 + row) * DHc + ch * 8;
            cpa16(sb + (uint32_t)((4 + tile) * (int)AT_TILE + row * 144 + ch * 16), g);
        }
        cpa_commit();
        cpa_wait<0>();
        __syncthreads();

        uint32_t qh[4][4], ql[4][4];
#pragma unroll
        for (int ks = 0; ks < 4; ks++) {
            uint32_t ad = sb + 4u * AT_TILE + ((uint32_t)(wid * 16 + lrow) * AT_STRIDE +
                                               (uint32_t)(ks * 16 + lko)) * 2u;
            ldsm4(qh[ks], ad);
            ldsm4(ql[ks], ad + AT_TILE);
        }

        auto issue_kv = [&](int kt, int buf) {
            const uint32_t bbase = sb + (uint32_t)buf * (4u * AT_TILE);
            const int k0 = kt * 128;
#pragma unroll
            for (int j = 0; j < 16; j++) {
                const int tile = j >> 2;          // 0 Kh 1 Kl 2 Vh 3 Vl
                const int idx = (j & 3) * 256 + tid;
                const int row = idx >> 3, ch = idx & 7;
                const bf16* g;
                if (tile == 0)      g = g_Kh;
                else if (tile == 1) g = g_Kl;
                else if (tile == 2) g = g_Vh;
                else                g = g_Vl;
                g += hb + (size_t)(k0 + row) * DHc + ch * 8;
                cpa16(bbase + (uint32_t)(tile * (int)AT_TILE + row * 144 + ch * 16), g);
            }
            cpa_commit();
        };

        issue_kv(0, 0);

        float m_i[2] = {-1e30f, -1e30f}, l_i[2] = {0.f, 0.f};
        float oacc[8][4];
#pragma unroll
        for (int n8 = 0; n8 < 8; n8++)
#pragma unroll
            for (int e = 0; e < 4; e++) oacc[n8][e] = 0.f;

        for (int kt = 0; kt <= qt; kt++) {
            cpa_wait<0>();
            __syncthreads();
            if (kt < qt) issue_kv(kt + 1, (kt + 1) & 1);

            const uint32_t bbuf = sb + (uint32_t)(kt & 1) * (4u * AT_TILE);

            // --- S = Q K^T ---
            float sacc[16][4];
#pragma unroll
            for (int j = 0; j < 16; j++)
#pragma unroll
                for (int e = 0; e < 4; e++) sacc[j][e] = 0.f;

#pragma unroll
            for (int ks = 0; ks < 4; ks++) {
#pragma unroll
                for (int nt2 = 0; nt2 < 8; nt2++) {
                    uint32_t bh4[4], bl4[4];
                    uint32_t bd = bbuf + ((uint32_t)(nt2 * 16 + lrow) * AT_STRIDE +
                                          (uint32_t)(ks * 16 + lko)) * 2u;
                    ldsm4(bh4, bd);
                    ldsm4(bl4, bd + AT_TILE);
#pragma unroll
                    for (int sel = 0; sel < 2; sel++) {
                        const int j = nt2 * 2 + sel;
                        mma16816(sacc[j], qh[ks], bh4[sel], bh4[sel + 2]);
                        mma16816(sacc[j], qh[ks], bl4[sel], bl4[sel + 2]);
                        mma16816(sacc[j], ql[ks], bh4[sel], bh4[sel + 2]);
                    }
                }
            }

            // --- scale (base-2 domain) + causal mask ---
            const float scale = 0.18033688f;      // 0.125 * log2(e)
            if (kt == qt) {
#pragma unroll
                for (int j = 0; j < 16; j++)
#pragma unroll
                    for (int e = 0; e < 4; e++) {
                        int row = wid * 16 + gid + ((e >> 1) << 3);
                        int col = j * 8 + tig * 2 + (e & 1);
                        sacc[j][e] = (col <= row) ? sacc[j][e] * scale : -1e30f;
                    }
            } else {
#pragma unroll
                for (int j = 0; j < 16; j++)
#pragma unroll
                    for (int e = 0; e < 4; e++) sacc[j][e] *= scale;
            }

            // --- online softmax (exp2 domain) ---
#pragma unroll
            for (int hrow = 0; hrow < 2; hrow++) {
                const int e0 = hrow * 2;
                float mx = sacc[0][e0];
#pragma unroll
                for (int j = 0; j < 16; j++) {
                    mx = fmaxf(mx, sacc[j][e0]);
                    mx = fmaxf(mx, sacc[j][e0 + 1]);
                }
                mx = fmaxf(mx, __shfl_xor_sync(0xffffffffu, mx, 1));
                mx = fmaxf(mx, __shfl_xor_sync(0xffffffffu, mx, 2));
                float mnew = fmaxf(m_i[hrow], mx);
                float corr = ex2f(m_i[hrow] - mnew);
                float rs = 0.f;
#pragma unroll
                for (int j = 0; j < 16; j++) {
                    float p0 = ex2f(sacc[j][e0]     - mnew);
                    float p1 = ex2f(sacc[j][e0 + 1] - mnew);
                    sacc[j][e0] = p0; sacc[j][e0 + 1] = p1;
                    rs += p0 + p1;
                }
                rs += __shfl_xor_sync(0xffffffffu, rs, 1);
                rs += __shfl_xor_sync(0xffffffffu, rs, 2);
                l_i[hrow] = l_i[hrow] * corr + rs;
                m_i[hrow] = mnew;
#pragma unroll
                for (int n8 = 0; n8 < 8; n8++) {
                    oacc[n8][e0]     *= corr;
                    oacc[n8][e0 + 1] *= corr;
                }
            }

            // --- O += P V ---
#pragma unroll
            for (int ks2 = 0; ks2 < 8; ks2++) {
                uint32_t pa[4], pl[4];
                split2(sacc[2*ks2][0],   sacc[2*ks2][1],   pa[0], pl[0]);
                split2(sacc[2*ks2][2],   sacc[2*ks2][3],   pa[1], pl[1]);
                split2(sacc[2*ks2+1][0], sacc[2*ks2+1][1], pa[2], pl[2]);
                split2(sacc[2*ks2+1][2], sacc[2*ks2+1][3], pa[3], pl[3]);

                const int mat = lid >> 3, rin = lid & 7;
                const uint32_t vrow = (uint32_t)(ks2 * 16 + (mat & 1) * 8 + rin);
#pragma unroll
                for (int n2 = 0; n2 < 4; n2++) {
                    uint32_t vh4[4], vl4[4];
                    uint32_t vd = bbuf + 2u * AT_TILE +
                                  (vrow * AT_STRIDE + (uint32_t)(n2 * 16 + (mat >> 1) * 8)) * 2u;
                    ldsm4t(vh4, vd);
                    ldsm4t(vl4, vd + AT_TILE);
#pragma unroll
                    for (int sel = 0; sel < 2; sel++) {
                        const int n8 = n2 * 2 + sel;
                        mma16816(oacc[n8], pa, vh4[sel * 2], vh4[sel * 2 + 1]);
                        mma16816(oacc[n8], pl, vh4[sel * 2], vh4[sel * 2 + 1]);
                        mma16816(oacc[n8], pa, vl4[sel * 2], vl4[sel * 2 + 1]);
                    }
                }
            }
        }

        // --- epilogue: normalize + write AO hi/lo ---
        const int b = bh >> 4, h = bh & 15;
        const float inv0 = 1.f / l_i[0], inv1 = 1.f / l_i[1];
        const int row0 = q0 + wid * 16 + gid;
#pragma unroll
        for (int n8 = 0; n8 < 8; n8++) {
            const int col = h * DHc + n8 * 8 + tig * 2;
            size_t p0 = ((size_t)b * Sc + row0) * Dc + col;
            size_t p1 = ((size_t)b * Sc + row0 + 8) * Dc + col;
            uint32_t uh, ul;
            split2(oacc[n8][0] * inv0, oacc[n8][1] * inv0, uh, ul);
            *(uint32_t*)(g_AOh + p0) = uh; *(uint32_t*)(g_AOl + p0) = ul;
            split2(oacc[n8][2] * inv1, oacc[n8][3] * inv1, uh, ul);
            *(uint32_t*)(g_AOh + p1) = uh; *(uint32_t*)(g_AOl + p1) = ul;
        }
    }
}

// ---------------------------------------------------------------------------
extern "C" void kernel_launch(void* const* d_in, const int* in_sizes, int n_in,
                              void* d_out, int out_size)
{
    const float* x  = (const float*)d_in[0];
    const float* Wq = (const float*)d_in[2];
    const float* bq = (const float*)d_in[3];
    const float* Wk = (const float*)d_in[4];
    const float* bk = (const float*)d_in[5];
    const float* Wv = (const float*)d_in[6];
    const float* bv = (const float*)d_in[7];
    const float* Wo = (const float*)d_in[8];
    const float* bo = (const float*)d_in[9];
    float* out = (float*)d_out;

    split_x_kernel<<<Mrows * Dc / 1024, 256>>>(x);
    dim3 tb(32, 8), tg(32, 32);
    transpose_split_kernel<<<tg, tb>>>(Wq, 0);
    transpose_split_kernel<<<tg, tb>>>(Wk, 1);
    transpose_split_kernel<<<tg, tb>>>(Wv, 2);
    transpose_split_kernel<<<tg, tb>>>(Wo, 3);

    const int gsmem = 4 * GT_STAGE;     // 163840
    const int asmem = 8 * AT_TILE;      // 147456
    cudaFuncSetAttribute(gemm_mma<0>, cudaFuncAttributeMaxDynamicSharedMemorySize, gsmem);
    cudaFuncSetAttribute(gemm_mma<1>, cudaFuncAttributeMaxDynamicSharedMemorySize, gsmem);
    cudaFuncSetAttribute(attn_mma, cudaFuncAttributeMaxDynamicSharedMemorySize, asmem);

    gemm_mma<1><<<dim3(24, 32), 256, gsmem>>>(bq, bk, bv, nullptr);
    attn_mma<<<184, 256, asmem>>>();
    gemm_mma<0><<<dim3(8, 32), 256, gsmem>>>(bo, nullptr, nullptr, out);
}

// round 9
// speedup vs baseline: 3.8225x; 1.3062x over previous
#include <cuda_runtime.h>
#include <cuda_fp16.h>
#include <cstdint>

#define Bc  2
#define Sc  2048
#define Dc  1024
#define Hc  16
#define DHc 64
#define Mrows (Bc*Sc)          // 4096
typedef __half fp16;

// ---------------- device scratch (no allocation allowed) ----------------
__device__ fp16 g_xh [Mrows*Dc];                        // x hi only (2-term QKV)
__device__ fp16 g_Wh [4*Dc*Dc],  g_Wl [4*Dc*Dc];        // W^T hi/lo, [n][k]
__device__ fp16 g_Qh [Bc*Hc*Sc*DHc], g_Ql [Bc*Hc*Sc*DHc];
__device__ fp16 g_Kh [Bc*Hc*Sc*DHc], g_Kl [Bc*Hc*Sc*DHc];
__device__ fp16 g_Vh [Bc*Hc*Sc*DHc], g_Vl [Bc*Hc*Sc*DHc];
__device__ fp16 g_AOh[Mrows*Dc];                        // AO hi only (2-term out)
__device__ int  g_tick;

// ---------------- helpers ----------------
__device__ __forceinline__ uint32_t smem_u32(const void* p) {
    uint32_t a;
    asm("{ .reg .u64 t; cvta.to.shared.u64 t, %1; cvt.u32.u64 %0, t; }" : "=r"(a) : "l"(p));
    return a;
}
__device__ __forceinline__ void ldsm4(uint32_t* r, uint32_t addr) {
    asm volatile("ldmatrix.sync.aligned.m8n8.x4.shared.b16 {%0,%1,%2,%3}, [%4];"
        : "=r"(r[0]), "=r"(r[1]), "=r"(r[2]), "=r"(r[3]) : "r"(addr));
}
__device__ __forceinline__ void ldsm4t(uint32_t* r, uint32_t addr) {
    asm volatile("ldmatrix.sync.aligned.m8n8.x4.trans.shared.b16 {%0,%1,%2,%3}, [%4];"
        : "=r"(r[0]), "=r"(r[1]), "=r"(r[2]), "=r"(r[3]) : "r"(addr));
}
__device__ __forceinline__ void mma16816(float* d, const uint32_t* a,
                                         uint32_t b0, uint32_t b1) {
    asm volatile("mma.sync.aligned.m16n8k16.row.col.f32.f16.f16.f32 "
        "{%0,%1,%2,%3}, {%4,%5,%6,%7}, {%8,%9}, {%0,%1,%2,%3};"
        : "+f"(d[0]), "+f"(d[1]), "+f"(d[2]), "+f"(d[3])
        : "r"(a[0]), "r"(a[1]), "r"(a[2]), "r"(a[3]), "r"(b0), "r"(b1));
}
__device__ __forceinline__ uint32_t pack2h(float x, float y) {
    __half2 h = __floats2half2_rn(x, y);
    return *(uint32_t*)&h;
}
__device__ __forceinline__ void split2h(float x, float y, uint32_t& hi, uint32_t& lo) {
    float hx = __half2float(__float2half_rn(x));
    float hy = __half2float(__float2half_rn(y));
    hi = pack2h(hx, hy);
    lo = pack2h(x - hx, y - hy);
}
__device__ __forceinline__ float ex2f(float x) {
    float y;
    asm("ex2.approx.f32 %0, %1;" : "=f"(y) : "f"(x));
    return y;
}
__device__ __forceinline__ void cpa16(uint32_t s, const void* g) {
    asm volatile("cp.async.cg.shared.global [%0], [%1], 16;" :: "r"(s), "l"(g));
}
__device__ __forceinline__ void cpa_commit() {
    asm volatile("cp.async.commit_group;" ::: "memory");
}
template<int N>
__device__ __forceinline__ void cpa_wait() {
    asm volatile("cp.async.wait_group %0;" :: "n"(N) : "memory");
}

// ---------------- prep: x -> fp16 hi (+ticket reset) ----------------
__global__ void split_x_kernel(const float* __restrict__ src)
{
    if (blockIdx.x == 0 && threadIdx.x == 0) g_tick = 0;
    size_t i = ((size_t)blockIdx.x * 256 + threadIdx.x) * 4;
    float4 v = *(const float4*)(src + i);
    *(uint2*)(g_xh + i) = make_uint2(pack2h(v.x, v.y), pack2h(v.z, v.w));
}

// ---------------- prep: transpose + split W (fp16 hi/lo) ----------------
__global__ void transpose_split_kernel(const float* __restrict__ src, int wsel)
{
    __shared__ float t[32][33];
    fp16* dh = g_Wh + (size_t)wsel * Dc * Dc;
    fp16* dl = g_Wl + (size_t)wsel * Dc * Dc;
    int x = blockIdx.x * 32 + threadIdx.x;
    int y = blockIdx.y * 32 + threadIdx.y;
#pragma unroll
    for (int i = 0; i < 32; i += 8) t[threadIdx.y + i][threadIdx.x] = src[(y + i) * Dc + x];
    __syncthreads();
    x = blockIdx.y * 32 + threadIdx.x;
    y = blockIdx.x * 32 + threadIdx.y;
#pragma unroll
    for (int i = 0; i < 32; i += 8) {
        float v = t[threadIdx.x][threadIdx.y + i];
        fp16 h = __float2half_rn(v);
        dh[(size_t)(y + i) * Dc + x] = h;
        dl[(size_t)(y + i) * Dc + x] = __float2half_rn(v - __half2float(h));
    }
}

// ---------------------------------------------------------------------------
// fp16 2-term GEMM: C = Ah @ (Bh + Bl) + bias. Tile 128x128, BK=32, 256 thr,
// cp.async 4-stage pipeline, 3 tiles/stage (Ah, Bh, Bl).
// MODE 1: fused QKV (grid.x=24), epilogue splits to fp16 hi/lo head layout.
// MODE 0: AOh @ Wo^T + bo -> fp32 out (grid.x=8).
// ---------------------------------------------------------------------------
#define GT_TILE  10240u    // 128*40*2
#define GT_STAGE 30720u    // 3 tiles

template <int MODE>
__global__ __launch_bounds__(256)
void gemm_mma(const float* __restrict__ b0, const float* __restrict__ b1,
              const float* __restrict__ b2, float* __restrict__ outf)
{
    extern __shared__ unsigned char smraw[];
    const uint32_t sb = smem_u32(smraw);
    const int tid = threadIdx.x;
    const int wid = tid >> 5, lid = tid & 31;
    const int wr = wid >> 2, wc = wid & 3;
    const int m0 = blockIdx.y * 128;

    int wsel, n0;
    const fp16 *Ah_, *Bh_, *Bl_;
    const float* bias;
    if (MODE == 1) {
        wsel = blockIdx.x >> 3; n0 = (blockIdx.x & 7) * 128;
        Ah_ = g_xh;
        Bh_ = g_Wh + (size_t)wsel * Dc * Dc; Bl_ = g_Wl + (size_t)wsel * Dc * Dc;
        bias = (wsel == 0) ? b0 : (wsel == 1) ? b1 : b2;
    } else {
        wsel = 3; n0 = blockIdx.x * 128;
        Ah_ = g_AOh;
        Bh_ = g_Wh + (size_t)3 * Dc * Dc; Bl_ = g_Wl + (size_t)3 * Dc * Dc;
        bias = b0;
    }

    auto issue = [&](int c, int st) {
#pragma unroll
        for (int j = 0; j < 6; j++) {
            const int tile = j >> 1;                 // 0 Ah 1 Bh 2 Bl
            const int idx = (j & 1) * 256 + tid;     // 0..511
            const int row = idx >> 2, ch = idx & 3;
            const fp16* g;
            if (tile == 0)      g = Ah_ + (size_t)(m0 + row) * Dc + c * 32 + ch * 8;
            else if (tile == 1) g = Bh_ + (size_t)(n0 + row) * Dc + c * 32 + ch * 8;
            else                g = Bl_ + (size_t)(n0 + row) * Dc + c * 32 + ch * 8;
            cpa16(sb + (uint32_t)st * GT_STAGE +
                  (uint32_t)(tile * (int)GT_TILE + row * 80 + ch * 16), g);
        }
        cpa_commit();
    };

    float acc[4][4][4];
#pragma unroll
    for (int mt = 0; mt < 4; mt++)
#pragma unroll
        for (int nt = 0; nt < 4; nt++)
#pragma unroll
            for (int e = 0; e < 4; e++) acc[mt][nt][e] = 0.f;

    issue(0, 0);
    issue(1, 1);
    issue(2, 2);

    const int lrow = lid & 15;
    const int lko  = (lid >> 4) << 3;

    for (int c = 0; c < 32; c++) {
        if (c <= 29)      { cpa_wait<2>(); }
        else if (c == 30) { cpa_wait<1>(); }
        else              { cpa_wait<0>(); }
        __syncthreads();
        if (c < 29) issue(c + 3, (c + 3) & 3);

        const uint32_t base = sb + (uint32_t)(c & 3) * GT_STAGE;
#pragma unroll
        for (int ks = 0; ks < 2; ks++) {
            const uint32_t lk = (uint32_t)(ks * 16 + lko);
            uint32_t af[4][4], bf2[2][4], bl2[2][4];
#pragma unroll
            for (int mt = 0; mt < 4; mt++) {
                uint32_t ad = base + ((uint32_t)(wr * 64 + mt * 16 + lrow) * 40u + lk) * 2u;
                ldsm4(af[mt], ad);
            }
#pragma unroll
            for (int nt2 = 0; nt2 < 2; nt2++) {
                uint32_t bd = base + GT_TILE +
                              ((uint32_t)(wc * 32 + nt2 * 16 + lrow) * 40u + lk) * 2u;
                ldsm4(bf2[nt2], bd);
                ldsm4(bl2[nt2], bd + GT_TILE);
            }
#pragma unroll
            for (int mt = 0; mt < 4; mt++)
#pragma unroll
                for (int n8 = 0; n8 < 4; n8++) {
                    const int nt2 = n8 >> 1, sel = n8 & 1;
                    mma16816(acc[mt][n8], af[mt], bf2[nt2][sel], bf2[nt2][sel + 2]);
                    mma16816(acc[mt][n8], af[mt], bl2[nt2][sel], bl2[nt2][sel + 2]);
                }
        }
    }

    // epilogue
    fp16* Oh = (wsel == 0) ? g_Qh : (wsel == 1) ? g_Kh : g_Vh;
    fp16* Ol = (wsel == 0) ? g_Ql : (wsel == 1) ? g_Kl : g_Vl;
    const int gid = lid >> 2, tig = lid & 3;
#pragma unroll
    for (int mt = 0; mt < 4; mt++) {
#pragma unroll
        for (int nt = 0; nt < 4; nt++) {
            int row = m0 + wr * 64 + mt * 16 + gid;
            int col = n0 + wc * 32 + nt * 8 + tig * 2;
            float bx = bias[col], by = bias[col + 1];
            float v00 = acc[mt][nt][0] + bx, v01 = acc[mt][nt][1] + by;
            float v10 = acc[mt][nt][2] + bx, v11 = acc[mt][nt][3] + by;
            if (MODE == 0) {
                *(float2*)(outf + (size_t)row * Dc + col) = make_float2(v00, v01);
                *(float2*)(outf + (size_t)(row + 8) * Dc + col) = make_float2(v10, v11);
            } else {
                int h = col >> 6, dh = col & 63;
                int bb = row >> 11, s = row & (Sc - 1);
                size_t p0 = ((size_t)(bb * Hc + h) * Sc + s) * DHc + dh;
                size_t p1 = ((size_t)(bb * Hc + h) * Sc + (s + 8)) * DHc + dh;
                uint32_t uh, ul;
                split2h(v00, v01, uh, ul);
                *(uint32_t*)(Oh + p0) = uh; *(uint32_t*)(Ol + p0) = ul;
                split2h(v10, v11, uh, ul);
                *(uint32_t*)(Oh + p1) = uh; *(uint32_t*)(Ol + p1) = ul;
            }
        }
    }
}

// ---------------------------------------------------------------------------
// Persistent ticket-scheduled flash attention (fp16 mma).
// S = Q K^T 3-term; PV 2-term (P truncated to fp16). 256 thr, 1 CTA/SM.
// ---------------------------------------------------------------------------
#define AT_STRIDE 72u
#define AT_TILE   18432u   // 128*72*2
#define N_ITEMS   512      // 16 qt * 32 bh

__global__ __launch_bounds__(256, 1)
void attn_mma()
{
    extern __shared__ unsigned char smraw[];
    __shared__ int s_item;
    const uint32_t sb = smem_u32(smraw);

    const int tid = threadIdx.x;
    const int wid = tid >> 5, lid = tid & 31;
    const int gid = lid >> 2, tig = lid & 3;
    const int lrow = lid & 15, lko = (lid >> 4) << 3;

    for (;;) {
        if (tid == 0) s_item = atomicAdd(&g_tick, 1);
        __syncthreads();
        const int item = s_item;
        if (item >= N_ITEMS) return;

        const int qt = 15 - (item >> 5);     // heavy first (LPT)
        const int bh = item & 31;
        const int q0 = qt * 128;
        const size_t hb = (size_t)bh * (Sc * DHc);

        // --- stage Q (hi/lo) into buffer-1 K area ---
#pragma unroll
        for (int j = 0; j < 8; j++) {
            const int tile = j >> 2;              // 0 Qh, 1 Ql
            const int idx = (j & 3) * 256 + tid;
            const int row = idx >> 3, ch = idx & 7;
            const fp16* g = (tile ? g_Ql : g_Qh) + hb + (size_t)(q0 + row) * DHc + ch * 8;
            cpa16(sb + (uint32_t)((4 + tile) * (int)AT_TILE + row * 144 + ch * 16), g);
        }
        cpa_commit();
        cpa_wait<0>();
        __syncthreads();

        uint32_t qh[4][4], ql[4][4];
#pragma unroll
        for (int ks = 0; ks < 4; ks++) {
            uint32_t ad = sb + 4u * AT_TILE + ((uint32_t)(wid * 16 + lrow) * AT_STRIDE +
                                               (uint32_t)(ks * 16 + lko)) * 2u;
            ldsm4(qh[ks], ad);
            ldsm4(ql[ks], ad + AT_TILE);
        }

        auto issue_kv = [&](int kt, int buf) {
            const uint32_t bbase = sb + (uint32_t)buf * (4u * AT_TILE);
            const int k0 = kt * 128;
#pragma unroll
            for (int j = 0; j < 16; j++) {
                const int tile = j >> 2;          // 0 Kh 1 Kl 2 Vh 3 Vl
                const int idx = (j & 3) * 256 + tid;
                const int row = idx >> 3, ch = idx & 7;
                const fp16* g;
                if (tile == 0)      g = g_Kh;
                else if (tile == 1) g = g_Kl;
                else if (tile == 2) g = g_Vh;
                else                g = g_Vl;
                g += hb + (size_t)(k0 + row) * DHc + ch * 8;
                cpa16(bbase + (uint32_t)(tile * (int)AT_TILE + row * 144 + ch * 16), g);
            }
            cpa_commit();
        };

        issue_kv(0, 0);

        float m_i[2] = {-1e30f, -1e30f}, l_i[2] = {0.f, 0.f};
        float oacc[8][4];
#pragma unroll
        for (int n8 = 0; n8 < 8; n8++)
#pragma unroll
            for (int e = 0; e < 4; e++) oacc[n8][e] = 0.f;

        for (int kt = 0; kt <= qt; kt++) {
            cpa_wait<0>();
            __syncthreads();
            if (kt < qt) issue_kv(kt + 1, (kt + 1) & 1);

            const uint32_t bbuf = sb + (uint32_t)(kt & 1) * (4u * AT_TILE);

            // --- S = Q K^T (3-term) ---
            float sacc[16][4];
#pragma unroll
            for (int j = 0; j < 16; j++)
#pragma unroll
                for (int e = 0; e < 4; e++) sacc[j][e] = 0.f;

#pragma unroll
            for (int ks = 0; ks < 4; ks++) {
#pragma unroll
                for (int nt2 = 0; nt2 < 8; nt2++) {
                    uint32_t bh4[4], bl4[4];
                    uint32_t bd = bbuf + ((uint32_t)(nt2 * 16 + lrow) * AT_STRIDE +
                                          (uint32_t)(ks * 16 + lko)) * 2u;
                    ldsm4(bh4, bd);
                    ldsm4(bl4, bd + AT_TILE);
#pragma unroll
                    for (int sel = 0; sel < 2; sel++) {
                        const int j = nt2 * 2 + sel;
                        mma16816(sacc[j], qh[ks], bh4[sel], bh4[sel + 2]);
                        mma16816(sacc[j], qh[ks], bl4[sel], bl4[sel + 2]);
                        mma16816(sacc[j], ql[ks], bh4[sel], bh4[sel + 2]);
                    }
                }
            }

            // --- scale (base-2) + causal mask ---
            const float scale = 0.18033688f;      // 0.125 * log2(e)
            if (kt == qt) {
#pragma unroll
                for (int j = 0; j < 16; j++)
#pragma unroll
                    for (int e = 0; e < 4; e++) {
                        int row = wid * 16 + gid + ((e >> 1) << 3);
                        int col = j * 8 + tig * 2 + (e & 1);
                        sacc[j][e] = (col <= row) ? sacc[j][e] * scale : -1e30f;
                    }
            } else {
#pragma unroll
                for (int j = 0; j < 16; j++)
#pragma unroll
                    for (int e = 0; e < 4; e++) sacc[j][e] *= scale;
            }

            // --- online softmax (exp2 domain) ---
#pragma unroll
            for (int hrow = 0; hrow < 2; hrow++) {
                const int e0 = hrow * 2;
                float mx = sacc[0][e0];
#pragma unroll
                for (int j = 0; j < 16; j++) {
                    mx = fmaxf(mx, sacc[j][e0]);
                    mx = fmaxf(mx, sacc[j][e0 + 1]);
                }
                mx = fmaxf(mx, __shfl_xor_sync(0xffffffffu, mx, 1));
                mx = fmaxf(mx, __shfl_xor_sync(0xffffffffu, mx, 2));
                float mnew = fmaxf(m_i[hrow], mx);
                float corr = ex2f(m_i[hrow] - mnew);
                float rs = 0.f;
#pragma unroll
                for (int j = 0; j < 16; j++) {
                    float p0 = ex2f(sacc[j][e0]     - mnew);
                    float p1 = ex2f(sacc[j][e0 + 1] - mnew);
                    sacc[j][e0] = p0; sacc[j][e0 + 1] = p1;
                    rs += p0 + p1;
                }
                rs += __shfl_xor_sync(0xffffffffu, rs, 1);
                rs += __shfl_xor_sync(0xffffffffu, rs, 2);
                l_i[hrow] = l_i[hrow] * corr + rs;
                m_i[hrow] = mnew;
#pragma unroll
                for (int n8 = 0; n8 < 8; n8++) {
                    oacc[n8][e0]     *= corr;
                    oacc[n8][e0 + 1] *= corr;
                }
            }

            // --- O += P V (2-term: P fp16, V hi+lo) ---
#pragma unroll
            for (int ks2 = 0; ks2 < 8; ks2++) {
                uint32_t pa[4];
                pa[0] = pack2h(sacc[2*ks2][0],   sacc[2*ks2][1]);
                pa[1] = pack2h(sacc[2*ks2][2],   sacc[2*ks2][3]);
                pa[2] = pack2h(sacc[2*ks2+1][0], sacc[2*ks2+1][1]);
                pa[3] = pack2h(sacc[2*ks2+1][2], sacc[2*ks2+1][3]);

                const int mat = lid >> 3, rin = lid & 7;
                const uint32_t vrow = (uint32_t)(ks2 * 16 + (mat & 1) * 8 + rin);
#pragma unroll
                for (int n2 = 0; n2 < 4; n2++) {
                    uint32_t vh4[4], vl4[4];
                    uint32_t vd = bbuf + 2u * AT_TILE +
                                  (vrow * AT_STRIDE + (uint32_t)(n2 * 16 + (mat >> 1) * 8)) * 2u;
                    ldsm4t(vh4, vd);
                    ldsm4t(vl4, vd + AT_TILE);
#pragma unroll
                    for (int sel = 0; sel < 2; sel++) {
                        const int n8 = n2 * 2 + sel;
                        mma16816(oacc[n8], pa, vh4[sel * 2], vh4[sel * 2 + 1]);
                        mma16816(oacc[n8], pa, vl4[sel * 2], vl4[sel * 2 + 1]);
                    }
                }
            }
        }

        // --- epilogue: normalize + write AO hi (fp16) ---
        const int b = bh >> 4, h = bh & 15;
        const float inv0 = 1.f / l_i[0], inv1 = 1.f / l_i[1];
        const int row0 = q0 + wid * 16 + gid;
#pragma unroll
        for (int n8 = 0; n8 < 8; n8++) {
            const int col = h * DHc + n8 * 8 + tig * 2;
            size_t p0 = ((size_t)b * Sc + row0) * Dc + col;
            size_t p1 = ((size_t)b * Sc + row0 + 8) * Dc + col;
            *(uint32_t*)(g_AOh + p0) = pack2h(oacc[n8][0] * inv0, oacc[n8][1] * inv0);
            *(uint32_t*)(g_AOh + p1) = pack2h(oacc[n8][2] * inv1, oacc[n8][3] * inv1);
        }
    }
}

// ---------------------------------------------------------------------------
extern "C" void kernel_launch(void* const* d_in, const int* in_sizes, int n_in,
                              void* d_out, int out_size)
{
    const float* x  = (const float*)d_in[0];
    const float* Wq = (const float*)d_in[2];
    const float* bq = (const float*)d_in[3];
    const float* Wk = (const float*)d_in[4];
    const float* bk = (const float*)d_in[5];
    const float* Wv = (const float*)d_in[6];
    const float* bv = (const float*)d_in[7];
    const float* Wo = (const float*)d_in[8];
    const float* bo = (const float*)d_in[9];
    float* out = (float*)d_out;

    split_x_kernel<<<Mrows * Dc / 1024, 256>>>(x);
    dim3 tb(32, 8), tg(32, 32);
    transpose_split_kernel<<<tg, tb>>>(Wq, 0);
    transpose_split_kernel<<<tg, tb>>>(Wk, 1);
    transpose_split_kernel<<<tg, tb>>>(Wv, 2);
    transpose_split_kernel<<<tg, tb>>>(Wo, 3);

    const int gsmem = 4 * GT_STAGE;     // 122880
    const int asmem = 8 * AT_TILE;      // 147456
    cudaFuncSetAttribute(gemm_mma<0>, cudaFuncAttributeMaxDynamicSharedMemorySize, gsmem);
    cudaFuncSetAttribute(gemm_mma<1>, cudaFuncAttributeMaxDynamicSharedMemorySize, gsmem);
    cudaFuncSetAttribute(attn_mma, cudaFuncAttributeMaxDynamicSharedMemorySize, asmem);

    gemm_mma<1><<<dim3(24, 32), 256, gsmem>>>(bq, bk, bv, nullptr);
    attn_mma<<<184, 256, asmem>>>();
    gemm_mma<0><<<dim3(8, 32), 256, gsmem>>>(bo, nullptr, nullptr, out);
}

// round 10
// speedup vs baseline: 5.5652x; 1.4559x over previous
#include <cuda_runtime.h>
#include <cuda_fp16.h>
#include <cstdint>

#define Bc  2
#define Sc  2048
#define Dc  1024
#define Hc  16
#define DHc 64
#define Mrows (Bc*Sc)          // 4096
typedef __half fp16;

// ---------------- device scratch (no allocation allowed) ----------------
__device__ fp16 g_xh [Mrows*Dc];                        // x hi (1-term QKV)
__device__ fp16 g_Wh [4*Dc*Dc], g_Wl [4*Dc*Dc];         // W^T hi (all), lo (Wo only)
__device__ fp16 g_Qh [Bc*Hc*Sc*DHc];                    // Q hi (scale folded in)
__device__ fp16 g_Kh [Bc*Hc*Sc*DHc], g_Kl [Bc*Hc*Sc*DHc];
__device__ fp16 g_Vh [Bc*Hc*Sc*DHc], g_Vl [Bc*Hc*Sc*DHc];
__device__ fp16 g_AOh[Mrows*Dc];                        // AO hi (2-term out)
__device__ int  g_tick;

#define SCALE_L2E 0.18033688f   // 0.125 * log2(e), folded into Q

// ---------------- helpers ----------------
__device__ __forceinline__ uint32_t smem_u32(const void* p) {
    uint32_t a;
    asm("{ .reg .u64 t; cvta.to.shared.u64 t, %1; cvt.u32.u64 %0, t; }" : "=r"(a) : "l"(p));
    return a;
}
__device__ __forceinline__ void ldsm4(uint32_t* r, uint32_t addr) {
    asm volatile("ldmatrix.sync.aligned.m8n8.x4.shared.b16 {%0,%1,%2,%3}, [%4];"
        : "=r"(r[0]), "=r"(r[1]), "=r"(r[2]), "=r"(r[3]) : "r"(addr));
}
__device__ __forceinline__ void ldsm4t(uint32_t* r, uint32_t addr) {
    asm volatile("ldmatrix.sync.aligned.m8n8.x4.trans.shared.b16 {%0,%1,%2,%3}, [%4];"
        : "=r"(r[0]), "=r"(r[1]), "=r"(r[2]), "=r"(r[3]) : "r"(addr));
}
__device__ __forceinline__ void mma16816(float* d, const uint32_t* a,
                                         uint32_t b0, uint32_t b1) {
    asm volatile("mma.sync.aligned.m16n8k16.row.col.f32.f16.f16.f32 "
        "{%0,%1,%2,%3}, {%4,%5,%6,%7}, {%8,%9}, {%0,%1,%2,%3};"
        : "+f"(d[0]), "+f"(d[1]), "+f"(d[2]), "+f"(d[3])
        : "r"(a[0]), "r"(a[1]), "r"(a[2]), "r"(a[3]), "r"(b0), "r"(b1));
}
__device__ __forceinline__ uint32_t pack2h(float x, float y) {
    __half2 h = __floats2half2_rn(x, y);
    return *(uint32_t*)&h;
}
__device__ __forceinline__ void split2h(float x, float y, uint32_t& hi, uint32_t& lo) {
    float hx = __half2float(__float2half_rn(x));
    float hy = __half2float(__float2half_rn(y));
    hi = pack2h(hx, hy);
    lo = pack2h(x - hx, y - hy);
}
__device__ __forceinline__ float ex2f(float x) {
    float y;
    asm("ex2.approx.f32 %0, %1;" : "=f"(y) : "f"(x));
    return y;
}
__device__ __forceinline__ void cpa16(uint32_t s, const void* g) {
    asm volatile("cp.async.cg.shared.global [%0], [%1], 16;" :: "r"(s), "l"(g));
}
__device__ __forceinline__ void cpa_commit() {
    asm volatile("cp.async.commit_group;" ::: "memory");
}
template<int N>
__device__ __forceinline__ void cpa_wait() {
    asm volatile("cp.async.wait_group %0;" :: "n"(N) : "memory");
}

// ---------------- prep: x -> fp16 hi (+ticket reset) ----------------
__global__ void split_x_kernel(const float* __restrict__ src)
{
    if (blockIdx.x == 0 && threadIdx.x == 0) g_tick = 0;
    size_t i = ((size_t)blockIdx.x * 256 + threadIdx.x) * 4;
    float4 v = *(const float4*)(src + i);
    *(uint2*)(g_xh + i) = make_uint2(pack2h(v.x, v.y), pack2h(v.z, v.w));
}

// ---------------- prep: transpose + split W (lo only for Wo) ----------------
__global__ void transpose_split_kernel(const float* __restrict__ src, int wsel)
{
    __shared__ float t[32][33];
    fp16* dh = g_Wh + (size_t)wsel * Dc * Dc;
    fp16* dl = g_Wl + (size_t)wsel * Dc * Dc;
    int x = blockIdx.x * 32 + threadIdx.x;
    int y = blockIdx.y * 32 + threadIdx.y;
#pragma unroll
    for (int i = 0; i < 32; i += 8) t[threadIdx.y + i][threadIdx.x] = src[(y + i) * Dc + x];
    __syncthreads();
    x = blockIdx.y * 32 + threadIdx.x;
    y = blockIdx.x * 32 + threadIdx.y;
#pragma unroll
    for (int i = 0; i < 32; i += 8) {
        float v = t[threadIdx.x][threadIdx.y + i];
        fp16 h = __float2half_rn(v);
        dh[(size_t)(y + i) * Dc + x] = h;
        if (wsel == 3)
            dl[(size_t)(y + i) * Dc + x] = __float2half_rn(v - __half2float(h));
    }
}

// ---------------------------------------------------------------------------
// fp16 GEMM, tile 128x128, BK=32, 256 thr (8 warps 2x4), cp.async pipeline.
// MODE 1 (QKV, 1-term, 4 stages x 2 tiles): C = xh @ Wh + bias -> head layout
//        Q: *SCALE_L2E, hi only.  K,V: hi/lo split.
// MODE 0 (out, 2-term, 3 stages x 3 tiles): AOh @ (Wh+Wl) + bo -> fp32 out.
// ---------------------------------------------------------------------------
#define GT_TILE  10240u    // 128*40*2

template <int MODE>
__global__ __launch_bounds__(256, 2)
void gemm_mma(const float* __restrict__ b0, const float* __restrict__ b1,
              const float* __restrict__ b2, float* __restrict__ outf)
{
    constexpr int NT  = (MODE == 1) ? 2 : 3;       // tiles per stage
    constexpr int NST = (MODE == 1) ? 4 : 3;       // stages
    constexpr uint32_t STAGE = NT * GT_TILE;

    extern __shared__ unsigned char smraw[];
    const uint32_t sb = smem_u32(smraw);
    const int tid = threadIdx.x;
    const int wid = tid >> 5, lid = tid & 31;
    const int wr = wid >> 2, wc = wid & 3;
    const int m0 = blockIdx.y * 128;

    int wsel, n0;
    const fp16 *Ah_, *Bh_, *Bl_;
    const float* bias;
    if (MODE == 1) {
        wsel = blockIdx.x >> 3; n0 = (blockIdx.x & 7) * 128;
        Ah_ = g_xh;
        Bh_ = g_Wh + (size_t)wsel * Dc * Dc; Bl_ = nullptr;
        bias = (wsel == 0) ? b0 : (wsel == 1) ? b1 : b2;
    } else {
        wsel = 3; n0 = blockIdx.x * 128;
        Ah_ = g_AOh;
        Bh_ = g_Wh + (size_t)3 * Dc * Dc; Bl_ = g_Wl + (size_t)3 * Dc * Dc;
        bias = b0;
    }

    auto issue = [&](int c, int st) {
#pragma unroll
        for (int j = 0; j < 2 * NT; j++) {
            const int tile = j >> 1;                 // 0 A, 1 Bh, 2 Bl
            const int idx = (j & 1) * 256 + tid;     // 0..511
            const int row = idx >> 2, ch = idx & 3;
            const fp16* g;
            if (tile == 0)      g = Ah_ + (size_t)(m0 + row) * Dc + c * 32 + ch * 8;
            else if (tile == 1) g = Bh_ + (size_t)(n0 + row) * Dc + c * 32 + ch * 8;
            else                g = Bl_ + (size_t)(n0 + row) * Dc + c * 32 + ch * 8;
            cpa16(sb + (uint32_t)st * STAGE +
                  (uint32_t)(tile * (int)GT_TILE + row * 80 + ch * 16), g);
        }
        cpa_commit();
    };

    float acc[4][4][4];
#pragma unroll
    for (int mt = 0; mt < 4; mt++)
#pragma unroll
        for (int nt = 0; nt < 4; nt++)
#pragma unroll
            for (int e = 0; e < 4; e++) acc[mt][nt][e] = 0.f;

#pragma unroll
    for (int s = 0; s < NST - 1; s++) issue(s, s);

    const int lrow = lid & 15;
    const int lko  = (lid >> 4) << 3;

    for (int c = 0; c < 32; c++) {
        const int rem = 31 - c;
        if (rem >= NST - 2)  { cpa_wait<NST - 2>(); }
        else if (rem == 1)   { cpa_wait<1>(); }
        else                 { cpa_wait<0>(); }
        __syncthreads();
        if (c + NST - 1 < 32) issue(c + NST - 1, (c + NST - 1) % NST);

        const uint32_t base = sb + (uint32_t)(c % NST) * STAGE;
#pragma unroll
        for (int ks = 0; ks < 2; ks++) {
            const uint32_t lk = (uint32_t)(ks * 16 + lko);
            uint32_t af[4][4], bf2[2][4], bl2[2][4];
#pragma unroll
            for (int mt = 0; mt < 4; mt++) {
                uint32_t ad = base + ((uint32_t)(wr * 64 + mt * 16 + lrow) * 40u + lk) * 2u;
                ldsm4(af[mt], ad);
            }
#pragma unroll
            for (int nt2 = 0; nt2 < 2; nt2++) {
                uint32_t bd = base + GT_TILE +
                              ((uint32_t)(wc * 32 + nt2 * 16 + lrow) * 40u + lk) * 2u;
                ldsm4(bf2[nt2], bd);
                if (MODE == 0) ldsm4(bl2[nt2], bd + GT_TILE);
            }
#pragma unroll
            for (int mt = 0; mt < 4; mt++)
#pragma unroll
                for (int n8 = 0; n8 < 4; n8++) {
                    const int nt2 = n8 >> 1, sel = n8 & 1;
                    mma16816(acc[mt][n8], af[mt], bf2[nt2][sel], bf2[nt2][sel + 2]);
                    if (MODE == 0)
                        mma16816(acc[mt][n8], af[mt], bl2[nt2][sel], bl2[nt2][sel + 2]);
                }
        }
    }

    // epilogue
    const int gid = lid >> 2, tig = lid & 3;
#pragma unroll
    for (int mt = 0; mt < 4; mt++) {
#pragma unroll
        for (int nt = 0; nt < 4; nt++) {
            int row = m0 + wr * 64 + mt * 16 + gid;
            int col = n0 + wc * 32 + nt * 8 + tig * 2;
            float bx = bias[col], by = bias[col + 1];
            float v00 = acc[mt][nt][0] + bx, v01 = acc[mt][nt][1] + by;
            float v10 = acc[mt][nt][2] + bx, v11 = acc[mt][nt][3] + by;
            if (MODE == 0) {
                *(float2*)(outf + (size_t)row * Dc + col) = make_float2(v00, v01);
                *(float2*)(outf + (size_t)(row + 8) * Dc + col) = make_float2(v10, v11);
            } else {
                int h = col >> 6, dh = col & 63;
                int bb = row >> 11, s = row & (Sc - 1);
                size_t p0 = ((size_t)(bb * Hc + h) * Sc + s) * DHc + dh;
                size_t p1 = ((size_t)(bb * Hc + h) * Sc + (s + 8)) * DHc + dh;
                if (wsel == 0) {        // Q: fold softmax scale, hi only
                    *(uint32_t*)(g_Qh + p0) = pack2h(v00 * SCALE_L2E, v01 * SCALE_L2E);
                    *(uint32_t*)(g_Qh + p1) = pack2h(v10 * SCALE_L2E, v11 * SCALE_L2E);
                } else {
                    fp16* Oh = (wsel == 1) ? g_Kh : g_Vh;
                    fp16* Ol = (wsel == 1) ? g_Kl : g_Vl;
                    uint32_t uh, ul;
                    split2h(v00, v01, uh, ul);
                    *(uint32_t*)(Oh + p0) = uh; *(uint32_t*)(Ol + p0) = ul;
                    split2h(v10, v11, uh, ul);
                    *(uint32_t*)(Oh + p1) = uh; *(uint32_t*)(Ol + p1) = ul;
                }
            }
        }
    }
}

// ---------------------------------------------------------------------------
// Persistent ticket-scheduled flash attention (fp16 mma).
// S = qh @ (Kh + Kl)^T (2-term, scale pre-folded into Q);
// PV = P(fp16) @ (Vh + Vl) (2-term). 256 thr, 1 CTA/SM, LPT order.
// ---------------------------------------------------------------------------
#define AT_STRIDE 72u
#define AT_TILE   18432u   // 128*72*2
#define N_ITEMS   512      // 16 qt * 32 bh

__global__ __launch_bounds__(256, 1)
void attn_mma()
{
    extern __shared__ unsigned char smraw[];
    __shared__ int s_item;
    const uint32_t sb = smem_u32(smraw);

    const int tid = threadIdx.x;
    const int wid = tid >> 5, lid = tid & 31;
    const int gid = lid >> 2, tig = lid & 3;
    const int lrow = lid & 15, lko = (lid >> 4) << 3;

    for (;;) {
        if (tid == 0) s_item = atomicAdd(&g_tick, 1);
        __syncthreads();
        const int item = s_item;
        if (item >= N_ITEMS) return;

        const int qt = 15 - (item >> 5);     // heavy first (LPT)
        const int bh = item & 31;
        const int q0 = qt * 128;
        const size_t hb = (size_t)bh * (Sc * DHc);

        // --- stage Q (hi only) into buffer-1 Kh slot (tile 4) ---
#pragma unroll
        for (int j = 0; j < 4; j++) {
            const int idx = j * 256 + tid;        // 0..1023
            const int row = idx >> 3, ch = idx & 7;
            const fp16* g = g_Qh + hb + (size_t)(q0 + row) * DHc + ch * 8;
            cpa16(sb + (uint32_t)(4 * (int)AT_TILE + row * 144 + ch * 16), g);
        }
        cpa_commit();
        cpa_wait<0>();
        __syncthreads();

        uint32_t qh[4][4];
#pragma unroll
        for (int ks = 0; ks < 4; ks++) {
            uint32_t ad = sb + 4u * AT_TILE + ((uint32_t)(wid * 16 + lrow) * AT_STRIDE +
                                               (uint32_t)(ks * 16 + lko)) * 2u;
            ldsm4(qh[ks], ad);
        }

        auto issue_kv = [&](int kt, int buf) {
            const uint32_t bbase = sb + (uint32_t)buf * (4u * AT_TILE);
            const int k0 = kt * 128;
#pragma unroll
            for (int j = 0; j < 16; j++) {
                const int tile = j >> 2;          // 0 Kh 1 Kl 2 Vh 3 Vl
                const int idx = (j & 3) * 256 + tid;
                const int row = idx >> 3, ch = idx & 7;
                const fp16* g;
                if (tile == 0)      g = g_Kh;
                else if (tile == 1) g = g_Kl;
                else if (tile == 2) g = g_Vh;
                else                g = g_Vl;
                g += hb + (size_t)(k0 + row) * DHc + ch * 8;
                cpa16(bbase + (uint32_t)(tile * (int)AT_TILE + row * 144 + ch * 16), g);
            }
            cpa_commit();
        };

        issue_kv(0, 0);

        float m_i[2] = {-1e30f, -1e30f}, l_i[2] = {0.f, 0.f};
        float oacc[8][4];
#pragma unroll
        for (int n8 = 0; n8 < 8; n8++)
#pragma unroll
            for (int e = 0; e < 4; e++) oacc[n8][e] = 0.f;

        for (int kt = 0; kt <= qt; kt++) {
            cpa_wait<0>();
            __syncthreads();
            if (kt < qt) issue_kv(kt + 1, (kt + 1) & 1);

            const uint32_t bbuf = sb + (uint32_t)(kt & 1) * (4u * AT_TILE);

            // --- S = Q K^T (2-term: K hi+lo; scale pre-folded) ---
            float sacc[16][4];
#pragma unroll
            for (int j = 0; j < 16; j++)
#pragma unroll
                for (int e = 0; e < 4; e++) sacc[j][e] = 0.f;

#pragma unroll
            for (int ks = 0; ks < 4; ks++) {
#pragma unroll
                for (int nt2 = 0; nt2 < 8; nt2++) {
                    uint32_t bh4[4], bl4[4];
                    uint32_t bd = bbuf + ((uint32_t)(nt2 * 16 + lrow) * AT_STRIDE +
                                          (uint32_t)(ks * 16 + lko)) * 2u;
                    ldsm4(bh4, bd);
                    ldsm4(bl4, bd + AT_TILE);
#pragma unroll
                    for (int sel = 0; sel < 2; sel++) {
                        const int j = nt2 * 2 + sel;
                        mma16816(sacc[j], qh[ks], bh4[sel], bh4[sel + 2]);
                        mma16816(sacc[j], qh[ks], bl4[sel], bl4[sel + 2]);
                    }
                }
            }

            // --- causal mask on diagonal tile only (scale already in Q) ---
            if (kt == qt) {
#pragma unroll
                for (int j = 0; j < 16; j++)
#pragma unroll
                    for (int e = 0; e < 4; e++) {
                        int row = wid * 16 + gid + ((e >> 1) << 3);
                        int col = j * 8 + tig * 2 + (e & 1);
                        if (col > row) sacc[j][e] = -1e30f;
                    }
            }

            // --- online softmax (exp2 domain) ---
#pragma unroll
            for (int hrow = 0; hrow < 2; hrow++) {
                const int e0 = hrow * 2;
                float mx = sacc[0][e0];
#pragma unroll
                for (int j = 0; j < 16; j++) {
                    mx = fmaxf(mx, sacc[j][e0]);
                    mx = fmaxf(mx, sacc[j][e0 + 1]);
                }
                mx = fmaxf(mx, __shfl_xor_sync(0xffffffffu, mx, 1));
                mx = fmaxf(mx, __shfl_xor_sync(0xffffffffu, mx, 2));
                float mnew = fmaxf(m_i[hrow], mx);
                float corr = ex2f(m_i[hrow] - mnew);
                float rs = 0.f;
#pragma unroll
                for (int j = 0; j < 16; j++) {
                    float p0 = ex2f(sacc[j][e0]     - mnew);
                    float p1 = ex2f(sacc[j][e0 + 1] - mnew);
                    sacc[j][e0] = p0; sacc[j][e0 + 1] = p1;
                    rs += p0 + p1;
                }
                rs += __shfl_xor_sync(0xffffffffu, rs, 1);
                rs += __shfl_xor_sync(0xffffffffu, rs, 2);
                l_i[hrow] = l_i[hrow] * corr + rs;
                m_i[hrow] = mnew;
#pragma unroll
                for (int n8 = 0; n8 < 8; n8++) {
                    oacc[n8][e0]     *= corr;
                    oacc[n8][e0 + 1] *= corr;
                }
            }

            // --- O += P V (2-term: P fp16, V hi+lo) ---
#pragma unroll
            for (int ks2 = 0; ks2 < 8; ks2++) {
                uint32_t pa[4];
                pa[0] = pack2h(sacc[2*ks2][0],   sacc[2*ks2][1]);
                pa[1] = pack2h(sacc[2*ks2][2],   sacc[2*ks2][3]);
                pa[2] = pack2h(sacc[2*ks2+1][0], sacc[2*ks2+1][1]);
                pa[3] = pack2h(sacc[2*ks2+1][2], sacc[2*ks2+1][3]);

                const int mat = lid >> 3, rin = lid & 7;
                const uint32_t vrow = (uint32_t)(ks2 * 16 + (mat & 1) * 8 + rin);
#pragma unroll
                for (int n2 = 0; n2 < 4; n2++) {
                    uint32_t vh4[4], vl4[4];
                    uint32_t vd = bbuf + 2u * AT_TILE +
                                  (vrow * AT_STRIDE + (uint32_t)(n2 * 16 + (mat >> 1) * 8)) * 2u;
                    ldsm4t(vh4, vd);
                    ldsm4t(vl4, vd + AT_TILE);
#pragma unroll
                    for (int sel = 0; sel < 2; sel++) {
                        const int n8 = n2 * 2 + sel;
                        mma16816(oacc[n8], pa, vh4[sel * 2], vh4[sel * 2 + 1]);
                        mma16816(oacc[n8], pa, vl4[sel * 2], vl4[sel * 2 + 1]);
                    }
                }
            }
        }

        // --- epilogue: normalize + write AO hi (fp16) ---
        const int b = bh >> 4, h = bh & 15;
        const float inv0 = 1.f / l_i[0], inv1 = 1.f / l_i[1];
        const int row0 = q0 + wid * 16 + gid;
#pragma unroll
        for (int n8 = 0; n8 < 8; n8++) {
            const int col = h * DHc + n8 * 8 + tig * 2;
            size_t p0 = ((size_t)b * Sc + row0) * Dc + col;
            size_t p1 = ((size_t)b * Sc + row0 + 8) * Dc + col;
            *(uint32_t*)(g_AOh + p0) = pack2h(oacc[n8][0] * inv0, oacc[n8][1] * inv0);
            *(uint32_t*)(g_AOh + p1) = pack2h(oacc[n8][2] * inv1, oacc[n8][3] * inv1);
        }
    }
}

// ---------------------------------------------------------------------------
extern "C" void kernel_launch(void* const* d_in, const int* in_sizes, int n_in,
                              void* d_out, int out_size)
{
    const float* x  = (const float*)d_in[0];
    const float* Wq = (const float*)d_in[2];
    const float* bq = (const float*)d_in[3];
    const float* Wk = (const float*)d_in[4];
    const float* bk = (const float*)d_in[5];
    const float* Wv = (const float*)d_in[6];
    const float* bv = (const float*)d_in[7];
    const float* Wo = (const float*)d_in[8];
    const float* bo = (const float*)d_in[9];
    float* out = (float*)d_out;

    split_x_kernel<<<Mrows * Dc / 1024, 256>>>(x);
    dim3 tb(32, 8), tg(32, 32);
    transpose_split_kernel<<<tg, tb>>>(Wq, 0);
    transpose_split_kernel<<<tg, tb>>>(Wk, 1);
    transpose_split_kernel<<<tg, tb>>>(Wv, 2);
    transpose_split_kernel<<<tg, tb>>>(Wo, 3);

    const int gsmem1 = 4 * 2 * GT_TILE;   // 81920  (QKV: 4 stages x 2 tiles)
    const int gsmem0 = 3 * 3 * GT_TILE;   // 92160  (out: 3 stages x 3 tiles)
    const int asmem  = 8 * AT_TILE;       // 147456
    cudaFuncSetAttribute(gemm_mma<1>, cudaFuncAttributeMaxDynamicSharedMemorySize, gsmem1);
    cudaFuncSetAttribute(gemm_mma<0>, cudaFuncAttributeMaxDynamicSharedMemorySize, gsmem0);
    cudaFuncSetAttribute(attn_mma, cudaFuncAttributeMaxDynamicSharedMemorySize, asmem);

    gemm_mma<1><<<dim3(24, 32), 256, gsmem1>>>(bq, bk, bv, nullptr);
    attn_mma<<<152, 256, asmem>>>();
    gemm_mma<0><<<dim3(8, 32), 256, gsmem0>>>(bo, nullptr, nullptr, out);
}

// round 11
// speedup vs baseline: 6.6783x; 1.2000x over previous
#include <cuda_runtime.h>
#include <cuda_fp16.h>
#include <cstdint>

#define Bc  2
#define Sc  2048
#define Dc  1024
#define Hc  16
#define DHc 64
#define Mrows (Bc*Sc)          // 4096
typedef __half fp16;

// ---------------- device scratch (no allocation allowed) ----------------
__device__ fp16 g_xh [Mrows*Dc];                        // x hi (1-term QKV)
__device__ fp16 g_Wh [4*Dc*Dc];                         // W^T hi, [n][k]
__device__ fp16 g_Wl [Dc*Dc];                           // Wo^T lo only
__device__ fp16 g_Qh [Bc*Hc*Sc*DHc];                    // Q hi (scale folded in)
__device__ fp16 g_Kh [Bc*Hc*Sc*DHc];                    // K hi (1-term S)
__device__ fp16 g_Vh [Bc*Hc*Sc*DHc];                    // V hi (1-term PV)
__device__ fp16 g_AOh[Mrows*Dc];                        // AO hi (2-term out)
__device__ int  g_tick;

#define SCALE_L2E 0.18033688f   // 0.125 * log2(e), folded into Q

// ---------------- helpers ----------------
__device__ __forceinline__ uint32_t smem_u32(const void* p) {
    uint32_t a;
    asm("{ .reg .u64 t; cvta.to.shared.u64 t, %1; cvt.u32.u64 %0, t; }" : "=r"(a) : "l"(p));
    return a;
}
__device__ __forceinline__ void ldsm4(uint32_t* r, uint32_t addr) {
    asm volatile("ldmatrix.sync.aligned.m8n8.x4.shared.b16 {%0,%1,%2,%3}, [%4];"
        : "=r"(r[0]), "=r"(r[1]), "=r"(r[2]), "=r"(r[3]) : "r"(addr));
}
__device__ __forceinline__ void ldsm4t(uint32_t* r, uint32_t addr) {
    asm volatile("ldmatrix.sync.aligned.m8n8.x4.trans.shared.b16 {%0,%1,%2,%3}, [%4];"
        : "=r"(r[0]), "=r"(r[1]), "=r"(r[2]), "=r"(r[3]) : "r"(addr));
}
__device__ __forceinline__ void mma16816(float* d, const uint32_t* a,
                                         uint32_t b0, uint32_t b1) {
    asm volatile("mma.sync.aligned.m16n8k16.row.col.f32.f16.f16.f32 "
        "{%0,%1,%2,%3}, {%4,%5,%6,%7}, {%8,%9}, {%0,%1,%2,%3};"
        : "+f"(d[0]), "+f"(d[1]), "+f"(d[2]), "+f"(d[3])
        : "r"(a[0]), "r"(a[1]), "r"(a[2]), "r"(a[3]), "r"(b0), "r"(b1));
}
__device__ __forceinline__ uint32_t pack2h(float x, float y) {
    __half2 h = __floats2half2_rn(x, y);
    return *(uint32_t*)&h;
}
__device__ __forceinline__ float ex2f(float x) {
    float y;
    asm("ex2.approx.f32 %0, %1;" : "=f"(y) : "f"(x));
    return y;
}
__device__ __forceinline__ void cpa16(uint32_t s, const void* g) {
    asm volatile("cp.async.cg.shared.global [%0], [%1], 16;" :: "r"(s), "l"(g));
}
__device__ __forceinline__ void cpa_commit() {
    asm volatile("cp.async.commit_group;" ::: "memory");
}
template<int N>
__device__ __forceinline__ void cpa_wait() {
    asm volatile("cp.async.wait_group %0;" :: "n"(N) : "memory");
}

// ---------------- prep: x -> fp16 hi (+ticket reset) ----------------
__global__ void split_x_kernel(const float* __restrict__ src)
{
    if (blockIdx.x == 0 && threadIdx.x == 0) g_tick = 0;
    size_t i = ((size_t)blockIdx.x * 256 + threadIdx.x) * 4;
    float4 v = *(const float4*)(src + i);
    *(uint2*)(g_xh + i) = make_uint2(pack2h(v.x, v.y), pack2h(v.z, v.w));
}

// ---------------- prep: fused transpose of all 4 weights ----------------
__global__ void transpose_all_kernel(const float* __restrict__ Wq,
                                     const float* __restrict__ Wk,
                                     const float* __restrict__ Wv,
                                     const float* __restrict__ Wo)
{
    __shared__ float t[32][33];
    const int wsel = blockIdx.z;
    const float* src = (wsel == 0) ? Wq : (wsel == 1) ? Wk : (wsel == 2) ? Wv : Wo;
    fp16* dh = g_Wh + (size_t)wsel * Dc * Dc;
    int x = blockIdx.x * 32 + threadIdx.x;
    int y = blockIdx.y * 32 + threadIdx.y;
#pragma unroll
    for (int i = 0; i < 32; i += 8) t[threadIdx.y + i][threadIdx.x] = src[(y + i) * Dc + x];
    __syncthreads();
    x = blockIdx.y * 32 + threadIdx.x;
    y = blockIdx.x * 32 + threadIdx.y;
#pragma unroll
    for (int i = 0; i < 32; i += 8) {
        float v = t[threadIdx.x][threadIdx.y + i];
        fp16 h = __float2half_rn(v);
        dh[(size_t)(y + i) * Dc + x] = h;
        if (wsel == 3)
            g_Wl[(size_t)(y + i) * Dc + x] = __float2half_rn(v - __half2float(h));
    }
}

// ---------------------------------------------------------------------------
// fp16 GEMM, tile 128x128, BK=32, 256 thr (8 warps 2x4), cp.async pipeline.
// MODE 1 (QKV, 1-term, 4 stages x 2 tiles): C = xh @ Wh + bias -> head layout
//        Q: *SCALE_L2E.  All outputs hi-only fp16.
// MODE 0 (out, 2-term, 3 stages x 3 tiles): AOh @ (Wh+Wl) + bo -> fp32 out.
// ---------------------------------------------------------------------------
#define GT_TILE  10240u    // 128*40*2

template <int MODE>
__global__ __launch_bounds__(256, 2)
void gemm_mma(const float* __restrict__ b0, const float* __restrict__ b1,
              const float* __restrict__ b2, float* __restrict__ outf)
{
    constexpr int NT  = (MODE == 1) ? 2 : 3;       // tiles per stage
    constexpr int NST = (MODE == 1) ? 4 : 3;       // stages
    constexpr uint32_t STAGE = NT * GT_TILE;

    extern __shared__ unsigned char smraw[];
    const uint32_t sb = smem_u32(smraw);
    const int tid = threadIdx.x;
    const int wid = tid >> 5, lid = tid & 31;
    const int wr = wid >> 2, wc = wid & 3;
    const int m0 = blockIdx.y * 128;

    int wsel, n0;
    const fp16 *Ah_, *Bh_, *Bl_;
    const float* bias;
    if (MODE == 1) {
        wsel = blockIdx.x >> 3; n0 = (blockIdx.x & 7) * 128;
        Ah_ = g_xh;
        Bh_ = g_Wh + (size_t)wsel * Dc * Dc; Bl_ = nullptr;
        bias = (wsel == 0) ? b0 : (wsel == 1) ? b1 : b2;
    } else {
        wsel = 3; n0 = blockIdx.x * 128;
        Ah_ = g_AOh;
        Bh_ = g_Wh + (size_t)3 * Dc * Dc; Bl_ = g_Wl;
        bias = b0;
    }

    auto issue = [&](int c, int st) {
#pragma unroll
        for (int j = 0; j < 2 * NT; j++) {
            const int tile = j >> 1;                 // 0 A, 1 Bh, 2 Bl
            const int idx = (j & 1) * 256 + tid;     // 0..511
            const int row = idx >> 2, ch = idx & 3;
            const fp16* g;
            if (tile == 0)      g = Ah_ + (size_t)(m0 + row) * Dc + c * 32 + ch * 8;
            else if (tile == 1) g = Bh_ + (size_t)(n0 + row) * Dc + c * 32 + ch * 8;
            else                g = Bl_ + (size_t)(n0 + row) * Dc + c * 32 + ch * 8;
            cpa16(sb + (uint32_t)st * STAGE +
                  (uint32_t)(tile * (int)GT_TILE + row * 80 + ch * 16), g);
        }
        cpa_commit();
    };

    float acc[4][4][4];
#pragma unroll
    for (int mt = 0; mt < 4; mt++)
#pragma unroll
        for (int nt = 0; nt < 4; nt++)
#pragma unroll
            for (int e = 0; e < 4; e++) acc[mt][nt][e] = 0.f;

#pragma unroll
    for (int s = 0; s < NST - 1; s++) issue(s, s);

    const int lrow = lid & 15;
    const int lko  = (lid >> 4) << 3;

    for (int c = 0; c < 32; c++) {
        const int rem = 31 - c;
        if (rem >= NST - 2)  { cpa_wait<NST - 2>(); }
        else if (rem == 1)   { cpa_wait<1>(); }
        else                 { cpa_wait<0>(); }
        __syncthreads();
        if (c + NST - 1 < 32) issue(c + NST - 1, (c + NST - 1) % NST);

        const uint32_t base = sb + (uint32_t)(c % NST) * STAGE;
#pragma unroll
        for (int ks = 0; ks < 2; ks++) {
            const uint32_t lk = (uint32_t)(ks * 16 + lko);
            uint32_t af[4][4], bf2[2][4], bl2[2][4];
#pragma unroll
            for (int mt = 0; mt < 4; mt++) {
                uint32_t ad = base + ((uint32_t)(wr * 64 + mt * 16 + lrow) * 40u + lk) * 2u;
                ldsm4(af[mt], ad);
            }
#pragma unroll
            for (int nt2 = 0; nt2 < 2; nt2++) {
                uint32_t bd = base + GT_TILE +
                              ((uint32_t)(wc * 32 + nt2 * 16 + lrow) * 40u + lk) * 2u;
                ldsm4(bf2[nt2], bd);
                if (MODE == 0) ldsm4(bl2[nt2], bd + GT_TILE);
            }
#pragma unroll
            for (int mt = 0; mt < 4; mt++)
#pragma unroll
                for (int n8 = 0; n8 < 4; n8++) {
                    const int nt2 = n8 >> 1, sel = n8 & 1;
                    mma16816(acc[mt][n8], af[mt], bf2[nt2][sel], bf2[nt2][sel + 2]);
                    if (MODE == 0)
                        mma16816(acc[mt][n8], af[mt], bl2[nt2][sel], bl2[nt2][sel + 2]);
                }
        }
    }

    // epilogue
    const int gid = lid >> 2, tig = lid & 3;
#pragma unroll
    for (int mt = 0; mt < 4; mt++) {
#pragma unroll
        for (int nt = 0; nt < 4; nt++) {
            int row = m0 + wr * 64 + mt * 16 + gid;
            int col = n0 + wc * 32 + nt * 8 + tig * 2;
            float bx = bias[col], by = bias[col + 1];
            float v00 = acc[mt][nt][0] + bx, v01 = acc[mt][nt][1] + by;
            float v10 = acc[mt][nt][2] + bx, v11 = acc[mt][nt][3] + by;
            if (MODE == 0) {
                *(float2*)(outf + (size_t)row * Dc + col) = make_float2(v00, v01);
                *(float2*)(outf + (size_t)(row + 8) * Dc + col) = make_float2(v10, v11);
            } else {
                int h = col >> 6, dh = col & 63;
                int bb = row >> 11, s = row & (Sc - 1);
                size_t p0 = ((size_t)(bb * Hc + h) * Sc + s) * DHc + dh;
                size_t p1 = ((size_t)(bb * Hc + h) * Sc + (s + 8)) * DHc + dh;
                if (wsel == 0) {        // Q: fold softmax scale
                    *(uint32_t*)(g_Qh + p0) = pack2h(v00 * SCALE_L2E, v01 * SCALE_L2E);
                    *(uint32_t*)(g_Qh + p1) = pack2h(v10 * SCALE_L2E, v11 * SCALE_L2E);
                } else {
                    fp16* Oh = (wsel == 1) ? g_Kh : g_Vh;
                    *(uint32_t*)(Oh + p0) = pack2h(v00, v01);
                    *(uint32_t*)(Oh + p1) = pack2h(v10, v11);
                }
            }
        }
    }
}

// ---------------------------------------------------------------------------
// Persistent ticket-scheduled flash attention (fp16 mma, all 1-term).
// S = qh @ kh^T (scale pre-folded); PV = P @ vh. 256 thr, 1 CTA/SM, LPT.
// smem: 2 buffers x {Kh, Vh} + Q = 5 tiles x 18432B = 92160B.
// ---------------------------------------------------------------------------
#define AT_STRIDE 72u
#define AT_TILE   18432u   // 128*72*2
#define N_ITEMS   512      // 16 qt * 32 bh

__global__ __launch_bounds__(256, 1)
void attn_mma()
{
    extern __shared__ unsigned char smraw[];
    __shared__ int s_item;
    const uint32_t sb = smem_u32(smraw);

    const int tid = threadIdx.x;
    const int wid = tid >> 5, lid = tid & 31;
    const int gid = lid >> 2, tig = lid & 3;
    const int lrow = lid & 15, lko = (lid >> 4) << 3;

    for (;;) {
        if (tid == 0) s_item = atomicAdd(&g_tick, 1);
        __syncthreads();
        const int item = s_item;
        if (item >= N_ITEMS) return;

        const int qt = 15 - (item >> 5);     // heavy first (LPT)
        const int bh = item & 31;
        const int q0 = qt * 128;
        const size_t hb = (size_t)bh * (Sc * DHc);

        // --- stage Q (hi) into tile 4 ---
#pragma unroll
        for (int j = 0; j < 4; j++) {
            const int idx = j * 256 + tid;        // 0..1023
            const int row = idx >> 3, ch = idx & 7;
            const fp16* g = g_Qh + hb + (size_t)(q0 + row) * DHc + ch * 8;
            cpa16(sb + (uint32_t)(4 * (int)AT_TILE + row * 144 + ch * 16), g);
        }
        cpa_commit();
        cpa_wait<0>();
        __syncthreads();

        uint32_t qh[4][4];
#pragma unroll
        for (int ks = 0; ks < 4; ks++) {
            uint32_t ad = sb + 4u * AT_TILE + ((uint32_t)(wid * 16 + lrow) * AT_STRIDE +
                                               (uint32_t)(ks * 16 + lko)) * 2u;
            ldsm4(qh[ks], ad);
        }

        auto issue_kv = [&](int kt, int buf) {
            const uint32_t bbase = sb + (uint32_t)buf * (2u * AT_TILE);
            const int k0 = kt * 128;
#pragma unroll
            for (int j = 0; j < 8; j++) {
                const int tile = j >> 2;          // 0 Kh, 1 Vh
                const int idx = (j & 3) * 256 + tid;
                const int row = idx >> 3, ch = idx & 7;
                const fp16* g = (tile == 0 ? g_Kh : g_Vh) + hb +
                                (size_t)(k0 + row) * DHc + ch * 8;
                cpa16(bbase + (uint32_t)(tile * (int)AT_TILE + row * 144 + ch * 16), g);
            }
            cpa_commit();
        };

        issue_kv(0, 0);

        float m_i[2] = {-1e30f, -1e30f}, l_i[2] = {0.f, 0.f};
        float oacc[8][4];
#pragma unroll
        for (int n8 = 0; n8 < 8; n8++)
#pragma unroll
            for (int e = 0; e < 4; e++) oacc[n8][e] = 0.f;

        for (int kt = 0; kt <= qt; kt++) {
            cpa_wait<0>();
            __syncthreads();
            if (kt < qt) issue_kv(kt + 1, (kt + 1) & 1);

            const uint32_t bbuf = sb + (uint32_t)(kt & 1) * (2u * AT_TILE);

            // --- S = Q K^T (1-term, scale pre-folded) ---
            float sacc[16][4];
#pragma unroll
            for (int j = 0; j < 16; j++)
#pragma unroll
                for (int e = 0; e < 4; e++) sacc[j][e] = 0.f;

#pragma unroll
            for (int ks = 0; ks < 4; ks++) {
#pragma unroll
                for (int nt2 = 0; nt2 < 8; nt2++) {
                    uint32_t bh4[4];
                    uint32_t bd = bbuf + ((uint32_t)(nt2 * 16 + lrow) * AT_STRIDE +
                                          (uint32_t)(ks * 16 + lko)) * 2u;
                    ldsm4(bh4, bd);
#pragma unroll
                    for (int sel = 0; sel < 2; sel++)
                        mma16816(sacc[nt2 * 2 + sel], qh[ks], bh4[sel], bh4[sel + 2]);
                }
            }

            // --- causal mask on diagonal tile only ---
            if (kt == qt) {
#pragma unroll
                for (int j = 0; j < 16; j++)
#pragma unroll
                    for (int e = 0; e < 4; e++) {
                        int row = wid * 16 + gid + ((e >> 1) << 3);
                        int col = j * 8 + tig * 2 + (e & 1);
                        if (col > row) sacc[j][e] = -1e30f;
                    }
            }

            // --- online softmax (exp2 domain) ---
#pragma unroll
            for (int hrow = 0; hrow < 2; hrow++) {
                const int e0 = hrow * 2;
                float mx = sacc[0][e0];
#pragma unroll
                for (int j = 0; j < 16; j++) {
                    mx = fmaxf(mx, sacc[j][e0]);
                    mx = fmaxf(mx, sacc[j][e0 + 1]);
                }
                mx = fmaxf(mx, __shfl_xor_sync(0xffffffffu, mx, 1));
                mx = fmaxf(mx, __shfl_xor_sync(0xffffffffu, mx, 2));
                float mnew = fmaxf(m_i[hrow], mx);
                float corr = ex2f(m_i[hrow] - mnew);
                float rs = 0.f;
#pragma unroll
                for (int j = 0; j < 16; j++) {
                    float p0 = ex2f(sacc[j][e0]     - mnew);
                    float p1 = ex2f(sacc[j][e0 + 1] - mnew);
                    sacc[j][e0] = p0; sacc[j][e0 + 1] = p1;
                    rs += p0 + p1;
                }
                rs += __shfl_xor_sync(0xffffffffu, rs, 1);
                rs += __shfl_xor_sync(0xffffffffu, rs, 2);
                l_i[hrow] = l_i[hrow] * corr + rs;
                m_i[hrow] = mnew;
#pragma unroll
                for (int n8 = 0; n8 < 8; n8++) {
                    oacc[n8][e0]     *= corr;
                    oacc[n8][e0 + 1] *= corr;
                }
            }

            // --- O += P V (1-term) ---
#pragma unroll
            for (int ks2 = 0; ks2 < 8; ks2++) {
                uint32_t pa[4];
                pa[0] = pack2h(sacc[2*ks2][0],   sacc[2*ks2][1]);
                pa[1] = pack2h(sacc[2*ks2][2],   sacc[2*ks2][3]);
                pa[2] = pack2h(sacc[2*ks2+1][0], sacc[2*ks2+1][1]);
                pa[3] = pack2h(sacc[2*ks2+1][2], sacc[2*ks2+1][3]);

                const int mat = lid >> 3, rin = lid & 7;
                const uint32_t vrow = (uint32_t)(ks2 * 16 + (mat & 1) * 8 + rin);
#pragma unroll
                for (int n2 = 0; n2 < 4; n2++) {
                    uint32_t vh4[4];
                    uint32_t vd = bbuf + AT_TILE +
                                  (vrow * AT_STRIDE + (uint32_t)(n2 * 16 + (mat >> 1) * 8)) * 2u;
                    ldsm4t(vh4, vd);
#pragma unroll
                    for (int sel = 0; sel < 2; sel++)
                        mma16816(oacc[n2 * 2 + sel], pa, vh4[sel * 2], vh4[sel * 2 + 1]);
                }
            }
        }

        // --- epilogue: normalize + write AO hi (fp16) ---
        const int b = bh >> 4, h = bh & 15;
        const float inv0 = 1.f / l_i[0], inv1 = 1.f / l_i[1];
        const int row0 = q0 + wid * 16 + gid;
#pragma unroll
        for (int n8 = 0; n8 < 8; n8++) {
            const int col = h * DHc + n8 * 8 + tig * 2;
            size_t p0 = ((size_t)b * Sc + row0) * Dc + col;
            size_t p1 = ((size_t)b * Sc + row0 + 8) * Dc + col;
            *(uint32_t*)(g_AOh + p0) = pack2h(oacc[n8][0] * inv0, oacc[n8][1] * inv0);
            *(uint32_t*)(g_AOh + p1) = pack2h(oacc[n8][2] * inv1, oacc[n8][3] * inv1);
        }
    }
}

// ---------------------------------------------------------------------------
extern "C" void kernel_launch(void* const* d_in, const int* in_sizes, int n_in,
                              void* d_out, int out_size)
{
    const float* x  = (const float*)d_in[0];
    const float* Wq = (const float*)d_in[2];
    const float* bq = (const float*)d_in[3];
    const float* Wk = (const float*)d_in[4];
    const float* bk = (const float*)d_in[5];
    const float* Wv = (const float*)d_in[6];
    const float* bv = (const float*)d_in[7];
    const float* Wo = (const float*)d_in[8];
    const float* bo = (const float*)d_in[9];
    float* out = (float*)d_out;

    split_x_kernel<<<Mrows * Dc / 1024, 256>>>(x);
    transpose_all_kernel<<<dim3(32, 32, 4), dim3(32, 8)>>>(Wq, Wk, Wv, Wo);

    const int gsmem1 = 4 * 2 * GT_TILE;   // 81920  (QKV: 4 stages x 2 tiles)
    const int gsmem0 = 3 * 3 * GT_TILE;   // 92160  (out: 3 stages x 3 tiles)
    const int asmem  = 5 * AT_TILE;       // 92160
    cudaFuncSetAttribute(gemm_mma<1>, cudaFuncAttributeMaxDynamicSharedMemorySize, gsmem1);
    cudaFuncSetAttribute(gemm_mma<0>, cudaFuncAttributeMaxDynamicSharedMemorySize, gsmem0);
    cudaFuncSetAttribute(attn_mma, cudaFuncAttributeMaxDynamicSharedMemorySize, asmem);

    gemm_mma<1><<<dim3(24, 32), 256, gsmem1>>>(bq, bk, bv, nullptr);
    attn_mma<<<152, 256, asmem>>>();
    gemm_mma<0><<<dim3(8, 32), 256, gsmem0>>>(bo, nullptr, nullptr, out);
}

// round 12
// speedup vs baseline: 7.4463x; 1.1150x over previous
#include <cuda_runtime.h>
#include <cuda_fp16.h>
#include <cstdint>

#define Bc  2
#define Sc  2048
#define Dc  1024
#define Hc  16
#define DHc 64
#define Mrows (Bc*Sc)          // 4096
typedef __half fp16;

// ---------------- device scratch (no allocation allowed) ----------------
__device__ fp16 g_xh [Mrows*Dc];                        // x hi
__device__ fp16 g_Wh [4*Dc*Dc];                         // W^T hi, [n][k]
__device__ fp16 g_Qh [Bc*Hc*Sc*DHc];                    // Q hi (scale folded in)
__device__ fp16 g_Kh [Bc*Hc*Sc*DHc];                    // K hi
__device__ fp16 g_Vh [Bc*Hc*Sc*DHc];                    // V hi
__device__ fp16 g_AOh[Mrows*Dc];                        // AO hi
__device__ int  g_tick;

#define SCALE_L2E 0.18033688f   // 0.125 * log2(e), folded into Q

// ---------------- helpers ----------------
__device__ __forceinline__ uint32_t smem_u32(const void* p) {
    uint32_t a;
    asm("{ .reg .u64 t; cvta.to.shared.u64 t, %1; cvt.u32.u64 %0, t; }" : "=r"(a) : "l"(p));
    return a;
}
__device__ __forceinline__ void ldsm4(uint32_t* r, uint32_t addr) {
    asm volatile("ldmatrix.sync.aligned.m8n8.x4.shared.b16 {%0,%1,%2,%3}, [%4];"
        : "=r"(r[0]), "=r"(r[1]), "=r"(r[2]), "=r"(r[3]) : "r"(addr));
}
__device__ __forceinline__ void ldsm4t(uint32_t* r, uint32_t addr) {
    asm volatile("ldmatrix.sync.aligned.m8n8.x4.trans.shared.b16 {%0,%1,%2,%3}, [%4];"
        : "=r"(r[0]), "=r"(r[1]), "=r"(r[2]), "=r"(r[3]) : "r"(addr));
}
__device__ __forceinline__ void mma16816(float* d, const uint32_t* a,
                                         uint32_t b0, uint32_t b1) {
    asm volatile("mma.sync.aligned.m16n8k16.row.col.f32.f16.f16.f32 "
        "{%0,%1,%2,%3}, {%4,%5,%6,%7}, {%8,%9}, {%0,%1,%2,%3};"
        : "+f"(d[0]), "+f"(d[1]), "+f"(d[2]), "+f"(d[3])
        : "r"(a[0]), "r"(a[1]), "r"(a[2]), "r"(a[3]), "r"(b0), "r"(b1));
}
__device__ __forceinline__ uint32_t pack2h(float x, float y) {
    __half2 h = __floats2half2_rn(x, y);
    return *(uint32_t*)&h;
}
__device__ __forceinline__ float ex2f(float x) {
    float y;
    asm("ex2.approx.f32 %0, %1;" : "=f"(y) : "f"(x));
    return y;
}
__device__ __forceinline__ void cpa16(uint32_t s, const void* g) {
    asm volatile("cp.async.cg.shared.global [%0], [%1], 16;" :: "r"(s), "l"(g));
}
__device__ __forceinline__ void cpa_commit() {
    asm volatile("cp.async.commit_group;" ::: "memory");
}
template<int N>
__device__ __forceinline__ void cpa_wait() {
    asm volatile("cp.async.wait_group %0;" :: "n"(N) : "memory");
}

// ---------------- prep: x -> fp16 hi (+ticket reset) ----------------
__global__ void split_x_kernel(const float* __restrict__ src)
{
    if (blockIdx.x == 0 && threadIdx.x == 0) g_tick = 0;
    size_t i = ((size_t)blockIdx.x * 256 + threadIdx.x) * 8;
    float4 v0 = *(const float4*)(src + i);
    float4 v1 = *(const float4*)(src + i + 4);
    uint4 o;
    o.x = pack2h(v0.x, v0.y); o.y = pack2h(v0.z, v0.w);
    o.z = pack2h(v1.x, v1.y); o.w = pack2h(v1.z, v1.w);
    *(uint4*)(g_xh + i) = o;
}

// ---------------- prep: fused transpose of all 4 weights ----------------
__global__ void transpose_all_kernel(const float* __restrict__ Wq,
                                     const float* __restrict__ Wk,
                                     const float* __restrict__ Wv,
                                     const float* __restrict__ Wo)
{
    __shared__ float t[32][33];
    const int wsel = blockIdx.z;
    const float* src = (wsel == 0) ? Wq : (wsel == 1) ? Wk : (wsel == 2) ? Wv : Wo;
    fp16* dh = g_Wh + (size_t)wsel * Dc * Dc;
    int x = blockIdx.x * 32 + threadIdx.x;
    int y = blockIdx.y * 32 + threadIdx.y;
#pragma unroll
    for (int i = 0; i < 32; i += 8) t[threadIdx.y + i][threadIdx.x] = src[(y + i) * Dc + x];
    __syncthreads();
    x = blockIdx.y * 32 + threadIdx.x;
    y = blockIdx.x * 32 + threadIdx.y;
#pragma unroll
    for (int i = 0; i < 32; i += 8)
        dh[(size_t)(y + i) * Dc + x] = __float2half_rn(t[threadIdx.x][threadIdx.y + i]);
}

// ---------------------------------------------------------------------------
// fp16 1-term GEMM, tile 128x128, BK=32, 256 thr (8 warps 2x4),
// cp.async 4-stage x 2-tile pipeline, 2 CTAs/SM.
// MODE 1 (QKV, grid.x=24): C = xh @ Wh + bias -> head layout (Q *SCALE_L2E).
// MODE 0 (out, grid.x=8):  C = AOh @ Wo_h + bo -> fp32 out.
// ---------------------------------------------------------------------------
#define GT_TILE  10240u    // 128*40*2
#define GT_STAGE 20480u    // 2 tiles
#define GT_NST   4

template <int MODE>
__global__ __launch_bounds__(256, 2)
void gemm_mma(const float* __restrict__ b0, const float* __restrict__ b1,
              const float* __restrict__ b2, float* __restrict__ outf)
{
    extern __shared__ unsigned char smraw[];
    const uint32_t sb = smem_u32(smraw);
    const int tid = threadIdx.x;
    const int wid = tid >> 5, lid = tid & 31;
    const int wr = wid >> 2, wc = wid & 3;
    const int m0 = blockIdx.y * 128;

    int wsel, n0;
    const fp16 *Ah_, *Bh_;
    const float* bias;
    if (MODE == 1) {
        wsel = blockIdx.x >> 3; n0 = (blockIdx.x & 7) * 128;
        Ah_ = g_xh;
        Bh_ = g_Wh + (size_t)wsel * Dc * Dc;
        bias = (wsel == 0) ? b0 : (wsel == 1) ? b1 : b2;
    } else {
        wsel = 3; n0 = blockIdx.x * 128;
        Ah_ = g_AOh;
        Bh_ = g_Wh + (size_t)3 * Dc * Dc;
        bias = b0;
    }

    auto issue = [&](int c, int st) {
#pragma unroll
        for (int j = 0; j < 4; j++) {
            const int tile = j >> 1;                 // 0 A, 1 B
            const int idx = (j & 1) * 256 + tid;     // 0..511
            const int row = idx >> 2, ch = idx & 3;
            const fp16* g = (tile == 0)
                ? Ah_ + (size_t)(m0 + row) * Dc + c * 32 + ch * 8
                : Bh_ + (size_t)(n0 + row) * Dc + c * 32 + ch * 8;
            cpa16(sb + (uint32_t)st * GT_STAGE +
                  (uint32_t)(tile * (int)GT_TILE + row * 80 + ch * 16), g);
        }
        cpa_commit();
    };

    float acc[4][4][4];
#pragma unroll
    for (int mt = 0; mt < 4; mt++)
#pragma unroll
        for (int nt = 0; nt < 4; nt++)
#pragma unroll
            for (int e = 0; e < 4; e++) acc[mt][nt][e] = 0.f;

#pragma unroll
    for (int s = 0; s < GT_NST - 1; s++) issue(s, s);

    const int lrow = lid & 15;
    const int lko  = (lid >> 4) << 3;

    for (int c = 0; c < 32; c++) {
        const int rem = 31 - c;
        if (rem >= GT_NST - 2)  { cpa_wait<GT_NST - 2>(); }
        else if (rem == 1)      { cpa_wait<1>(); }
        else                    { cpa_wait<0>(); }
        __syncthreads();
        if (c + GT_NST - 1 < 32) issue(c + GT_NST - 1, (c + GT_NST - 1) & (GT_NST - 1));

        const uint32_t base = sb + (uint32_t)(c & (GT_NST - 1)) * GT_STAGE;
#pragma unroll
        for (int ks = 0; ks < 2; ks++) {
            const uint32_t lk = (uint32_t)(ks * 16 + lko);
            uint32_t af[4][4], bf2[2][4];
#pragma unroll
            for (int mt = 0; mt < 4; mt++) {
                uint32_t ad = base + ((uint32_t)(wr * 64 + mt * 16 + lrow) * 40u + lk) * 2u;
                ldsm4(af[mt], ad);
            }
#pragma unroll
            for (int nt2 = 0; nt2 < 2; nt2++) {
                uint32_t bd = base + GT_TILE +
                              ((uint32_t)(wc * 32 + nt2 * 16 + lrow) * 40u + lk) * 2u;
                ldsm4(bf2[nt2], bd);
            }
#pragma unroll
            for (int mt = 0; mt < 4; mt++)
#pragma unroll
                for (int n8 = 0; n8 < 4; n8++) {
                    const int nt2 = n8 >> 1, sel = n8 & 1;
                    mma16816(acc[mt][n8], af[mt], bf2[nt2][sel], bf2[nt2][sel + 2]);
                }
        }
    }

    // epilogue
    const int gid = lid >> 2, tig = lid & 3;
#pragma unroll
    for (int mt = 0; mt < 4; mt++) {
#pragma unroll
        for (int nt = 0; nt < 4; nt++) {
            int row = m0 + wr * 64 + mt * 16 + gid;
            int col = n0 + wc * 32 + nt * 8 + tig * 2;
            float bx = bias[col], by = bias[col + 1];
            float v00 = acc[mt][nt][0] + bx, v01 = acc[mt][nt][1] + by;
            float v10 = acc[mt][nt][2] + bx, v11 = acc[mt][nt][3] + by;
            if (MODE == 0) {
                *(float2*)(outf + (size_t)row * Dc + col) = make_float2(v00, v01);
                *(float2*)(outf + (size_t)(row + 8) * Dc + col) = make_float2(v10, v11);
            } else {
                int h = col >> 6, dh = col & 63;
                int bb = row >> 11, s = row & (Sc - 1);
                size_t p0 = ((size_t)(bb * Hc + h) * Sc + s) * DHc + dh;
                size_t p1 = ((size_t)(bb * Hc + h) * Sc + (s + 8)) * DHc + dh;
                if (wsel == 0) {        // Q: fold softmax scale
                    *(uint32_t*)(g_Qh + p0) = pack2h(v00 * SCALE_L2E, v01 * SCALE_L2E);
                    *(uint32_t*)(g_Qh + p1) = pack2h(v10 * SCALE_L2E, v11 * SCALE_L2E);
                } else {
                    fp16* Oh = (wsel == 1) ? g_Kh : g_Vh;
                    *(uint32_t*)(Oh + p0) = pack2h(v00, v01);
                    *(uint32_t*)(Oh + p1) = pack2h(v10, v11);
                }
            }
        }
    }
}

// ---------------------------------------------------------------------------
// Persistent ticket-scheduled flash attention (fp16 mma, 1-term).
// S = qh @ kh^T (scale pre-folded); PV = P @ vh. 256 thr, 1 CTA/SM, LPT.
// smem: 2 buffers x {Kh, Vh} + Q = 5 tiles x 18432B = 92160B.
// ---------------------------------------------------------------------------
#define AT_STRIDE 72u
#define AT_TILE   18432u   // 128*72*2
#define N_ITEMS   512      // 16 qt * 32 bh

__global__ __launch_bounds__(256, 1)
void attn_mma()
{
    extern __shared__ unsigned char smraw[];
    __shared__ int s_item;
    const uint32_t sb = smem_u32(smraw);

    const int tid = threadIdx.x;
    const int wid = tid >> 5, lid = tid & 31;
    const int gid = lid >> 2, tig = lid & 3;
    const int lrow = lid & 15, lko = (lid >> 4) << 3;

    for (;;) {
        if (tid == 0) s_item = atomicAdd(&g_tick, 1);
        __syncthreads();
        const int item = s_item;
        if (item >= N_ITEMS) return;

        const int qt = 15 - (item >> 5);     // heavy first (LPT)
        const int bh = item & 31;
        const int q0 = qt * 128;
        const size_t hb = (size_t)bh * (Sc * DHc);

        // --- stage Q (hi) into tile 4 ---
#pragma unroll
        for (int j = 0; j < 4; j++) {
            const int idx = j * 256 + tid;        // 0..1023
            const int row = idx >> 3, ch = idx & 7;
            const fp16* g = g_Qh + hb + (size_t)(q0 + row) * DHc + ch * 8;
            cpa16(sb + (uint32_t)(4 * (int)AT_TILE + row * 144 + ch * 16), g);
        }
        cpa_commit();
        cpa_wait<0>();
        __syncthreads();

        uint32_t qh[4][4];
#pragma unroll
        for (int ks = 0; ks < 4; ks++) {
            uint32_t ad = sb + 4u * AT_TILE + ((uint32_t)(wid * 16 + lrow) * AT_STRIDE +
                                               (uint32_t)(ks * 16 + lko)) * 2u;
            ldsm4(qh[ks], ad);
        }

        auto issue_kv = [&](int kt, int buf) {
            const uint32_t bbase = sb + (uint32_t)buf * (2u * AT_TILE);
            const int k0 = kt * 128;
#pragma unroll
            for (int j = 0; j < 8; j++) {
                const int tile = j >> 2;          // 0 Kh, 1 Vh
                const int idx = (j & 3) * 256 + tid;
                const int row = idx >> 3, ch = idx & 7;
                const fp16* g = (tile == 0 ? g_Kh : g_Vh) + hb +
                                (size_t)(k0 + row) * DHc + ch * 8;
                cpa16(bbase + (uint32_t)(tile * (int)AT_TILE + row * 144 + ch * 16), g);
            }
            cpa_commit();
        };

        issue_kv(0, 0);

        float m_i[2] = {-1e30f, -1e30f}, l_i[2] = {0.f, 0.f};
        float oacc[8][4];
#pragma unroll
        for (int n8 = 0; n8 < 8; n8++)
#pragma unroll
            for (int e = 0; e < 4; e++) oacc[n8][e] = 0.f;

        for (int kt = 0; kt <= qt; kt++) {
            cpa_wait<0>();
            __syncthreads();
            if (kt < qt) issue_kv(kt + 1, (kt + 1) & 1);

            const uint32_t bbuf = sb + (uint32_t)(kt & 1) * (2u * AT_TILE);

            // --- S = Q K^T (1-term, scale pre-folded) ---
            float sacc[16][4];
#pragma unroll
            for (int j = 0; j < 16; j++)
#pragma unroll
                for (int e = 0; e < 4; e++) sacc[j][e] = 0.f;

#pragma unroll
            for (int ks = 0; ks < 4; ks++) {
#pragma unroll
                for (int nt2 = 0; nt2 < 8; nt2++) {
                    uint32_t bh4[4];
                    uint32_t bd = bbuf + ((uint32_t)(nt2 * 16 + lrow) * AT_STRIDE +
                                          (uint32_t)(ks * 16 + lko)) * 2u;
                    ldsm4(bh4, bd);
#pragma unroll
                    for (int sel = 0; sel < 2; sel++)
                        mma16816(sacc[nt2 * 2 + sel], qh[ks], bh4[sel], bh4[sel + 2]);
                }
            }

            // --- causal mask on diagonal tile only ---
            if (kt == qt) {
#pragma unroll
                for (int j = 0; j < 16; j++)
#pragma unroll
                    for (int e = 0; e < 4; e++) {
                        int row = wid * 16 + gid + ((e >> 1) << 3);
                        int col = j * 8 + tig * 2 + (e & 1);
                        if (col > row) sacc[j][e] = -1e30f;
                    }
            }

            // --- online softmax (exp2 domain) ---
#pragma unroll
            for (int hrow = 0; hrow < 2; hrow++) {
                const int e0 = hrow * 2;
                float mx = sacc[0][e0];
#pragma unroll
                for (int j = 0; j < 16; j++) {
                    mx = fmaxf(mx, sacc[j][e0]);
                    mx = fmaxf(mx, sacc[j][e0 + 1]);
                }
                mx = fmaxf(mx, __shfl_xor_sync(0xffffffffu, mx, 1));
                mx = fmaxf(mx, __shfl_xor_sync(0xffffffffu, mx, 2));
                float mnew = fmaxf(m_i[hrow], mx);
                float corr = ex2f(m_i[hrow] - mnew);
                float rs = 0.f;
#pragma unroll
                for (int j = 0; j < 16; j++) {
                    float p0 = ex2f(sacc[j][e0]     - mnew);
                    float p1 = ex2f(sacc[j][e0 + 1] - mnew);
                    sacc[j][e0] = p0; sacc[j][e0 + 1] = p1;
                    rs += p0 + p1;
                }
                rs += __shfl_xor_sync(0xffffffffu, rs, 1);
                rs += __shfl_xor_sync(0xffffffffu, rs, 2);
                l_i[hrow] = l_i[hrow] * corr + rs;
                m_i[hrow] = mnew;
#pragma unroll
                for (int n8 = 0; n8 < 8; n8++) {
                    oacc[n8][e0]     *= corr;
                    oacc[n8][e0 + 1] *= corr;
                }
            }

            // --- O += P V (1-term) ---
#pragma unroll
            for (int ks2 = 0; ks2 < 8; ks2++) {
                uint32_t pa[4];
                pa[0] = pack2h(sacc[2*ks2][0],   sacc[2*ks2][1]);
                pa[1] = pack2h(sacc[2*ks2][2],   sacc[2*ks2][3]);
                pa[2] = pack2h(sacc[2*ks2+1][0], sacc[2*ks2+1][1]);
                pa[3] = pack2h(sacc[2*ks2+1][2], sacc[2*ks2+1][3]);

                const int mat = lid >> 3, rin = lid & 7;
                const uint32_t vrow = (uint32_t)(ks2 * 16 + (mat & 1) * 8 + rin);
#pragma unroll
                for (int n2 = 0; n2 < 4; n2++) {
                    uint32_t vh4[4];
                    uint32_t vd = bbuf + AT_TILE +
                                  (vrow * AT_STRIDE + (uint32_t)(n2 * 16 + (mat >> 1) * 8)) * 2u;
                    ldsm4t(vh4, vd);
#pragma unroll
                    for (int sel = 0; sel < 2; sel++)
                        mma16816(oacc[n2 * 2 + sel], pa, vh4[sel * 2], vh4[sel * 2 + 1]);
                }
            }
        }

        // --- epilogue: normalize + write AO hi (fp16) ---
        const int b = bh >> 4, h = bh & 15;
        const float inv0 = 1.f / l_i[0], inv1 = 1.f / l_i[1];
        const int row0 = q0 + wid * 16 + gid;
#pragma unroll
        for (int n8 = 0; n8 < 8; n8++) {
            const int col = h * DHc + n8 * 8 + tig * 2;
            size_t p0 = ((size_t)b * Sc + row0) * Dc + col;
            size_t p1 = ((size_t)b * Sc + row0 + 8) * Dc + col;
            *(uint32_t*)(g_AOh + p0) = pack2h(oacc[n8][0] * inv0, oacc[n8][1] * inv0);
            *(uint32_t*)(g_AOh + p1) = pack2h(oacc[n8][2] * inv1, oacc[n8][3] * inv1);
        }
    }
}

// ---------------------------------------------------------------------------
extern "C" void kernel_launch(void* const* d_in, const int* in_sizes, int n_in,
                              void* d_out, int out_size)
{
    const float* x  = (const float*)d_in[0];
    const float* Wq = (const float*)d_in[2];
    const float* bq = (const float*)d_in[3];
    const float* Wk = (const float*)d_in[4];
    const float* bk = (const float*)d_in[5];
    const float* Wv = (const float*)d_in[6];
    const float* bv = (const float*)d_in[7];
    const float* Wo = (const float*)d_in[8];
    const float* bo = (const float*)d_in[9];
    float* out = (float*)d_out;

    split_x_kernel<<<Mrows * Dc / 2048, 256>>>(x);
    transpose_all_kernel<<<dim3(32, 32, 4), dim3(32, 8)>>>(Wq, Wk, Wv, Wo);

    const int gsmem = GT_NST * GT_STAGE;  // 81920
    const int asmem = 5 * AT_TILE;        // 92160
    cudaFuncSetAttribute(gemm_mma<1>, cudaFuncAttributeMaxDynamicSharedMemorySize, gsmem);
    cudaFuncSetAttribute(gemm_mma<0>, cudaFuncAttributeMaxDynamicSharedMemorySize, gsmem);
    cudaFuncSetAttribute(attn_mma, cudaFuncAttributeMaxDynamicSharedMemorySize, asmem);

    gemm_mma<1><<<dim3(24, 32), 256, gsmem>>>(bq, bk, bv, nullptr);
    attn_mma<<<152, 256, asmem>>>();
    gemm_mma<0><<<dim3(8, 32), 256, gsmem>>>(bo, nullptr, nullptr, out);
}

// round 13
// speedup vs baseline: 7.7380x; 1.0392x over previous
#include <cuda_runtime.h>
#include <cuda_fp16.h>
#include <cstdint>

#define Bc  2
#define Sc  2048
#define Dc  1024
#define Hc  16
#define DHc 64
#define Mrows (Bc*Sc)          // 4096
typedef __half fp16;

// ---------------- device scratch (no allocation allowed) ----------------
__device__ fp16 g_xh [Mrows*Dc];                        // x hi
__device__ fp16 g_Wh [4*Dc*Dc];                         // W^T hi, [n][k]
__device__ fp16 g_Qh [Bc*Hc*Sc*DHc];                    // Q hi (scale folded in)
__device__ fp16 g_Kh [Bc*Hc*Sc*DHc];                    // K hi
__device__ fp16 g_Vh [Bc*Hc*Sc*DHc];                    // V hi
__device__ fp16 g_AOh[Mrows*Dc];                        // AO hi
__device__ int  g_tick;

#define SCALE_L2E 0.18033688f   // 0.125 * log2(e), folded into Q

// ---------------- helpers ----------------
__device__ __forceinline__ uint32_t smem_u32(const void* p) {
    uint32_t a;
    asm("{ .reg .u64 t; cvta.to.shared.u64 t, %1; cvt.u32.u64 %0, t; }" : "=r"(a) : "l"(p));
    return a;
}
__device__ __forceinline__ void ldsm4(uint32_t* r, uint32_t addr) {
    asm volatile("ldmatrix.sync.aligned.m8n8.x4.shared.b16 {%0,%1,%2,%3}, [%4];"
        : "=r"(r[0]), "=r"(r[1]), "=r"(r[2]), "=r"(r[3]) : "r"(addr));
}
__device__ __forceinline__ void ldsm4t(uint32_t* r, uint32_t addr) {
    asm volatile("ldmatrix.sync.aligned.m8n8.x4.trans.shared.b16 {%0,%1,%2,%3}, [%4];"
        : "=r"(r[0]), "=r"(r[1]), "=r"(r[2]), "=r"(r[3]) : "r"(addr));
}
__device__ __forceinline__ void mma16816(float* d, const uint32_t* a,
                                         uint32_t b0, uint32_t b1) {
    asm volatile("mma.sync.aligned.m16n8k16.row.col.f32.f16.f16.f32 "
        "{%0,%1,%2,%3}, {%4,%5,%6,%7}, {%8,%9}, {%0,%1,%2,%3};"
        : "+f"(d[0]), "+f"(d[1]), "+f"(d[2]), "+f"(d[3])
        : "r"(a[0]), "r"(a[1]), "r"(a[2]), "r"(a[3]), "r"(b0), "r"(b1));
}
__device__ __forceinline__ uint32_t pack2h(float x, float y) {
    __half2 h = __floats2half2_rn(x, y);
    return *(uint32_t*)&h;
}
__device__ __forceinline__ float ex2f(float x) {
    float y;
    asm("ex2.approx.f32 %0, %1;" : "=f"(y) : "f"(x));
    return y;
}
__device__ __forceinline__ uint32_t hmax2(uint32_t a, uint32_t b) {
    uint32_t d;
    asm("max.f16x2 %0, %1, %2;" : "=r"(d) : "r"(a), "r"(b));
    return d;
}
__device__ __forceinline__ uint32_t hsub2(uint32_t a, uint32_t b) {
    uint32_t d;
    asm("sub.f16x2 %0, %1, %2;" : "=r"(d) : "r"(a), "r"(b));
    return d;
}
__device__ __forceinline__ uint32_t hex2(uint32_t a) {
    uint32_t d;
    asm("ex2.approx.f16x2 %0, %1;" : "=r"(d) : "r"(a));
    return d;
}
__device__ __forceinline__ void cpa16(uint32_t s, const void* g) {
    asm volatile("cp.async.cg.shared.global [%0], [%1], 16;" :: "r"(s), "l"(g));
}
__device__ __forceinline__ void cpa_commit() {
    asm volatile("cp.async.commit_group;" ::: "memory");
}
template<int N>
__device__ __forceinline__ void cpa_wait() {
    asm volatile("cp.async.wait_group %0;" :: "n"(N) : "memory");
}

// ---------------- prep: fused x-convert + 4 weight transposes ----------------
__global__ void prep_kernel(const float* __restrict__ x,
                            const float* __restrict__ Wq,
                            const float* __restrict__ Wk,
                            const float* __restrict__ Wv,
                            const float* __restrict__ Wo)
{
    if (blockIdx.z == 4) {
        // x -> fp16, 1024 blocks x 256 thr x 16 elems
        const int blk = blockIdx.y * 32 + blockIdx.x;
        const int t = threadIdx.y * 32 + threadIdx.x;
        if (blk == 0 && t == 0) g_tick = 0;
        size_t i = ((size_t)blk * 256 + t) * 16;
#pragma unroll
        for (int j = 0; j < 2; j++) {
            float4 v0 = *(const float4*)(x + i + j * 8);
            float4 v1 = *(const float4*)(x + i + j * 8 + 4);
            uint4 o;
            o.x = pack2h(v0.x, v0.y); o.y = pack2h(v0.z, v0.w);
            o.z = pack2h(v1.x, v1.y); o.w = pack2h(v1.z, v1.w);
            *(uint4*)(g_xh + i + j * 8) = o;
        }
        return;
    }
    __shared__ float t[32][33];
    const int wsel = blockIdx.z;
    const float* src = (wsel == 0) ? Wq : (wsel == 1) ? Wk : (wsel == 2) ? Wv : Wo;
    fp16* dh = g_Wh + (size_t)wsel * Dc * Dc;
    int x0 = blockIdx.x * 32 + threadIdx.x;
    int y0 = blockIdx.y * 32 + threadIdx.y;
#pragma unroll
    for (int i = 0; i < 32; i += 8) t[threadIdx.y + i][threadIdx.x] = src[(y0 + i) * Dc + x0];
    __syncthreads();
    x0 = blockIdx.y * 32 + threadIdx.x;
    y0 = blockIdx.x * 32 + threadIdx.y;
#pragma unroll
    for (int i = 0; i < 32; i += 8)
        dh[(size_t)(y0 + i) * Dc + x0] = __float2half_rn(t[threadIdx.x][threadIdx.y + i]);
}

// ---------------------------------------------------------------------------
// fp16 1-term GEMM, tile 128x128, BK=32, 256 thr (8 warps 2x4),
// cp.async 4-stage x 2-tile pipeline, 2 CTAs/SM.
// MODE 1 (QKV, grid.x=24): C = xh @ Wh + bias -> head layout (Q *SCALE_L2E).
// MODE 0 (out, grid.x=8):  C = AOh @ Wo_h + bo -> fp32 out.
// ---------------------------------------------------------------------------
#define GT_TILE  10240u    // 128*40*2
#define GT_STAGE 20480u    // 2 tiles
#define GT_NST   4

template <int MODE>
__global__ __launch_bounds__(256, 2)
void gemm_mma(const float* __restrict__ b0, const float* __restrict__ b1,
              const float* __restrict__ b2, float* __restrict__ outf)
{
    extern __shared__ unsigned char smraw[];
    const uint32_t sb = smem_u32(smraw);
    const int tid = threadIdx.x;
    const int wid = tid >> 5, lid = tid & 31;
    const int wr = wid >> 2, wc = wid & 3;
    const int m0 = blockIdx.y * 128;

    int wsel, n0;
    const fp16 *Ah_, *Bh_;
    const float* bias;
    if (MODE == 1) {
        wsel = blockIdx.x >> 3; n0 = (blockIdx.x & 7) * 128;
        Ah_ = g_xh;
        Bh_ = g_Wh + (size_t)wsel * Dc * Dc;
        bias = (wsel == 0) ? b0 : (wsel == 1) ? b1 : b2;
    } else {
        wsel = 3; n0 = blockIdx.x * 128;
        Ah_ = g_AOh;
        Bh_ = g_Wh + (size_t)3 * Dc * Dc;
        bias = b0;
    }

    auto issue = [&](int c, int st) {
#pragma unroll
        for (int j = 0; j < 4; j++) {
            const int tile = j >> 1;                 // 0 A, 1 B
            const int idx = (j & 1) * 256 + tid;     // 0..511
            const int row = idx >> 2, ch = idx & 3;
            const fp16* g = (tile == 0)
                ? Ah_ + (size_t)(m0 + row) * Dc + c * 32 + ch * 8
                : Bh_ + (size_t)(n0 + row) * Dc + c * 32 + ch * 8;
            cpa16(sb + (uint32_t)st * GT_STAGE +
                  (uint32_t)(tile * (int)GT_TILE + row * 80 + ch * 16), g);
        }
        cpa_commit();
    };

    float acc[4][4][4];
#pragma unroll
    for (int mt = 0; mt < 4; mt++)
#pragma unroll
        for (int nt = 0; nt < 4; nt++)
#pragma unroll
            for (int e = 0; e < 4; e++) acc[mt][nt][e] = 0.f;

#pragma unroll
    for (int s = 0; s < GT_NST - 1; s++) issue(s, s);

    const int lrow = lid & 15;
    const int lko  = (lid >> 4) << 3;

    for (int c = 0; c < 32; c++) {
        const int rem = 31 - c;
        if (rem >= GT_NST - 2)  { cpa_wait<GT_NST - 2>(); }
        else if (rem == 1)      { cpa_wait<1>(); }
        else                    { cpa_wait<0>(); }
        __syncthreads();
        if (c + GT_NST - 1 < 32) issue(c + GT_NST - 1, (c + GT_NST - 1) & (GT_NST - 1));

        const uint32_t base = sb + (uint32_t)(c & (GT_NST - 1)) * GT_STAGE;
#pragma unroll
        for (int ks = 0; ks < 2; ks++) {
            const uint32_t lk = (uint32_t)(ks * 16 + lko);
            uint32_t af[4][4], bf2[2][4];
#pragma unroll
            for (int mt = 0; mt < 4; mt++) {
                uint32_t ad = base + ((uint32_t)(wr * 64 + mt * 16 + lrow) * 40u + lk) * 2u;
                ldsm4(af[mt], ad);
            }
#pragma unroll
            for (int nt2 = 0; nt2 < 2; nt2++) {
                uint32_t bd = base + GT_TILE +
                              ((uint32_t)(wc * 32 + nt2 * 16 + lrow) * 40u + lk) * 2u;
                ldsm4(bf2[nt2], bd);
            }
#pragma unroll
            for (int mt = 0; mt < 4; mt++)
#pragma unroll
                for (int n8 = 0; n8 < 4; n8++) {
                    const int nt2 = n8 >> 1, sel = n8 & 1;
                    mma16816(acc[mt][n8], af[mt], bf2[nt2][sel], bf2[nt2][sel + 2]);
                }
        }
    }

    // epilogue
    const int gid = lid >> 2, tig = lid & 3;
#pragma unroll
    for (int mt = 0; mt < 4; mt++) {
#pragma unroll
        for (int nt = 0; nt < 4; nt++) {
            int row = m0 + wr * 64 + mt * 16 + gid;
            int col = n0 + wc * 32 + nt * 8 + tig * 2;
            float bx = bias[col], by = bias[col + 1];
            float v00 = acc[mt][nt][0] + bx, v01 = acc[mt][nt][1] + by;
            float v10 = acc[mt][nt][2] + bx, v11 = acc[mt][nt][3] + by;
            if (MODE == 0) {
                *(float2*)(outf + (size_t)row * Dc + col) = make_float2(v00, v01);
                *(float2*)(outf + (size_t)(row + 8) * Dc + col) = make_float2(v10, v11);
            } else {
                int h = col >> 6, dh = col & 63;
                int bb = row >> 11, s = row & (Sc - 1);
                size_t p0 = ((size_t)(bb * Hc + h) * Sc + s) * DHc + dh;
                size_t p1 = ((size_t)(bb * Hc + h) * Sc + (s + 8)) * DHc + dh;
                if (wsel == 0) {        // Q: fold softmax scale
                    *(uint32_t*)(g_Qh + p0) = pack2h(v00 * SCALE_L2E, v01 * SCALE_L2E);
                    *(uint32_t*)(g_Qh + p1) = pack2h(v10 * SCALE_L2E, v11 * SCALE_L2E);
                } else {
                    fp16* Oh = (wsel == 1) ? g_Kh : g_Vh;
                    *(uint32_t*)(Oh + p0) = pack2h(v00, v01);
                    *(uint32_t*)(Oh + p1) = pack2h(v10, v11);
                }
            }
        }
    }
}

// ---------------------------------------------------------------------------
// Persistent ticket-scheduled flash attention (fp16 mma, 1-term).
// S = qh @ kh^T (scale pre-folded); softmax in f16x2 (ex2.approx.f16x2);
// row sums via ones-column MMA fragment; PV = P @ vh. 256 thr, 1 CTA/SM, LPT.
// smem: 2 buffers x {Kh, Vh} + Q = 5 tiles x 18432B = 92160B.
// ---------------------------------------------------------------------------
#define AT_STRIDE 72u
#define AT_TILE   18432u   // 128*72*2
#define N_ITEMS   512      // 16 qt * 32 bh

__global__ __launch_bounds__(256, 1)
void attn_mma()
{
    extern __shared__ unsigned char smraw[];
    __shared__ int s_item;
    const uint32_t sb = smem_u32(smraw);

    const int tid = threadIdx.x;
    const int wid = tid >> 5, lid = tid & 31;
    const int gid = lid >> 2, tig = lid & 3;
    const int lrow = lid & 15, lko = (lid >> 4) << 3;
    const uint32_t s_one = (lid < 4) ? 0x3C003C00u : 0u;   // ones col-0 B frag

    for (;;) {
        if (tid == 0) s_item = atomicAdd(&g_tick, 1);
        __syncthreads();
        const int item = s_item;
        if (item >= N_ITEMS) return;

        const int qt = 15 - (item >> 5);     // heavy first (LPT)
        const int bh = item & 31;
        const int q0 = qt * 128;
        const size_t hb = (size_t)bh * (Sc * DHc);

        auto issue_kv = [&](int kt, int buf) {
            const uint32_t bbase = sb + (uint32_t)buf * (2u * AT_TILE);
            const int k0 = kt * 128;
#pragma unroll
            for (int j = 0; j < 8; j++) {
                const int tile = j >> 2;          // 0 Kh, 1 Vh
                const int idx = (j & 3) * 256 + tid;
                const int row = idx >> 3, ch = idx & 7;
                const fp16* g = (tile == 0 ? g_Kh : g_Vh) + hb +
                                (size_t)(k0 + row) * DHc + ch * 8;
                cpa16(bbase + (uint32_t)(tile * (int)AT_TILE + row * 144 + ch * 16), g);
            }
            cpa_commit();
        };

        // --- stage Q (group 1), then prefetch KV tile 0 (group 2) ---
#pragma unroll
        for (int j = 0; j < 4; j++) {
            const int idx = j * 256 + tid;        // 0..1023
            const int row = idx >> 3, ch = idx & 7;
            const fp16* g = g_Qh + hb + (size_t)(q0 + row) * DHc + ch * 8;
            cpa16(sb + (uint32_t)(4 * (int)AT_TILE + row * 144 + ch * 16), g);
        }
        cpa_commit();
        issue_kv(0, 0);
        cpa_wait<1>();                            // Q ready (KV0 may be in flight)
        __syncthreads();

        uint32_t qh[4][4];
#pragma unroll
        for (int ks = 0; ks < 4; ks++) {
            uint32_t ad = sb + 4u * AT_TILE + ((uint32_t)(wid * 16 + lrow) * AT_STRIDE +
                                               (uint32_t)(ks * 16 + lko)) * 2u;
            ldsm4(qh[ks], ad);
        }

        float m_i[2] = {-1e30f, -1e30f}, l_i[2] = {0.f, 0.f};
        float oacc[8][4];
#pragma unroll
        for (int n8 = 0; n8 < 8; n8++)
#pragma unroll
            for (int e = 0; e < 4; e++) oacc[n8][e] = 0.f;

        for (int kt = 0; kt <= qt; kt++) {
            cpa_wait<0>();
            __syncthreads();
            if (kt < qt) issue_kv(kt + 1, (kt + 1) & 1);

            const uint32_t bbuf = sb + (uint32_t)(kt & 1) * (2u * AT_TILE);

            // --- S = Q K^T (1-term, scale pre-folded) ---
            float sacc[16][4];
#pragma unroll
            for (int j = 0; j < 16; j++)
#pragma unroll
                for (int e = 0; e < 4; e++) sacc[j][e] = 0.f;

#pragma unroll
            for (int ks = 0; ks < 4; ks++) {
#pragma unroll
                for (int nt2 = 0; nt2 < 8; nt2++) {
                    uint32_t bh4[4];
                    uint32_t bd = bbuf + ((uint32_t)(nt2 * 16 + lrow) * AT_STRIDE +
                                          (uint32_t)(ks * 16 + lko)) * 2u;
                    ldsm4(bh4, bd);
#pragma unroll
                    for (int sel = 0; sel < 2; sel++)
                        mma16816(sacc[nt2 * 2 + sel], qh[ks], bh4[sel], bh4[sel + 2]);
                }
            }

            // --- causal mask on diagonal tile only ---
            if (kt == qt) {
#pragma unroll
                for (int j = 0; j < 16; j++)
#pragma unroll
                    for (int e = 0; e < 4; e++) {
                        int row = wid * 16 + gid + ((e >> 1) << 3);
                        int col = j * 8 + tig * 2 + (e & 1);
                        if (col > row) sacc[j][e] = -1e30f;
                    }
            }

            // --- pack to half2 per row group: h0 = rows gid, h1 = rows gid+8 ---
            uint32_t h0[16], h1[16];
#pragma unroll
            for (int j = 0; j < 16; j++) {
                h0[j] = pack2h(sacc[j][0], sacc[j][1]);
                h1[j] = pack2h(sacc[j][2], sacc[j][3]);
            }

            // --- fp16 online softmax (exp2 domain), rs deferred to ones-MMA ---
            float corr[2];
#pragma unroll
            for (int hrow = 0; hrow < 2; hrow++) {
                uint32_t* hx = hrow ? h1 : h0;
                uint32_t m2 = hx[0];
#pragma unroll
                for (int j = 1; j < 16; j++) m2 = hmax2(m2, hx[j]);
                __half2 hm = *(__half2*)&m2;
                float mxf = fmaxf(__half2float(__low2half(hm)),
                                  __half2float(__high2half(hm)));
                mxf = fmaxf(mxf, __shfl_xor_sync(0xffffffffu, mxf, 1));
                mxf = fmaxf(mxf, __shfl_xor_sync(0xffffffffu, mxf, 2));
                float mnew = fmaxf(m_i[hrow], mxf);
                corr[hrow] = ex2f(m_i[hrow] - mnew);
                m_i[hrow] = mnew;
                const uint32_t mn2 = pack2h(mnew, mnew);
#pragma unroll
                for (int j = 0; j < 16; j++) hx[j] = hex2(hsub2(hx[j], mn2));
                const int e0 = hrow * 2;
#pragma unroll
                for (int n8 = 0; n8 < 8; n8++) {
                    oacc[n8][e0]     *= corr[hrow];
                    oacc[n8][e0 + 1] *= corr[hrow];
                }
            }

            // --- O += P V (1-term) + row sums via ones fragment ---
            float lacc[4] = {0.f, 0.f, 0.f, 0.f};
#pragma unroll
            for (int ks2 = 0; ks2 < 8; ks2++) {
                uint32_t pa[4];
                pa[0] = h0[2 * ks2];     pa[1] = h1[2 * ks2];
                pa[2] = h0[2 * ks2 + 1]; pa[3] = h1[2 * ks2 + 1];

                mma16816(lacc, pa, s_one, s_one);   // rs accumulation

                const int mat = lid >> 3, rin = lid & 7;
                const uint32_t vrow = (uint32_t)(ks2 * 16 + (mat & 1) * 8 + rin);
#pragma unroll
                for (int n2 = 0; n2 < 4; n2++) {
                    uint32_t vh4[4];
                    uint32_t vd = bbuf + AT_TILE +
                                  (vrow * AT_STRIDE + (uint32_t)(n2 * 16 + (mat >> 1) * 8)) * 2u;
                    ldsm4t(vh4, vd);
#pragma unroll
                    for (int sel = 0; sel < 2; sel++)
                        mma16816(oacc[n2 * 2 + sel], pa, vh4[sel * 2], vh4[sel * 2 + 1]);
                }
            }

            // broadcast col-0 sums (held by tig==0 lane of each row group)
            const int src = (lid >> 2) << 2;
            float rs0 = __shfl_sync(0xffffffffu, lacc[0], src);
            float rs1 = __shfl_sync(0xffffffffu, lacc[2], src);
            l_i[0] = l_i[0] * corr[0] + rs0;
            l_i[1] = l_i[1] * corr[1] + rs1;
        }

        // --- epilogue: normalize + write AO hi (fp16) ---
        const int b = bh >> 4, h = bh & 15;
        const float inv0 = 1.f / l_i[0], inv1 = 1.f / l_i[1];
        const int row0 = q0 + wid * 16 + gid;
#pragma unroll
        for (int n8 = 0; n8 < 8; n8++) {
            const int col = h * DHc + n8 * 8 + tig * 2;
            size_t p0 = ((size_t)b * Sc + row0) * Dc + col;
            size_t p1 = ((size_t)b * Sc + row0 + 8) * Dc + col;
            *(uint32_t*)(g_AOh + p0) = pack2h(oacc[n8][0] * inv0, oacc[n8][1] * inv0);
            *(uint32_t*)(g_AOh + p1) = pack2h(oacc[n8][2] * inv1, oacc[n8][3] * inv1);
        }
    }
}

// ---------------------------------------------------------------------------
extern "C" void kernel_launch(void* const* d_in, const int* in_sizes, int n_in,
                              void* d_out, int out_size)
{
    const float* x  = (const float*)d_in[0];
    const float* Wq = (const float*)d_in[2];
    const float* bq = (const float*)d_in[3];
    const float* Wk = (const float*)d_in[4];
    const float* bk = (const float*)d_in[5];
    const float* Wv = (const float*)d_in[6];
    const float* bv = (const float*)d_in[7];
    const float* Wo = (const float*)d_in[8];
    const float* bo = (const float*)d_in[9];
    float* out = (float*)d_out;

    prep_kernel<<<dim3(32, 32, 5), dim3(32, 8)>>>(x, Wq, Wk, Wv, Wo);

    const int gsmem = GT_NST * GT_STAGE;  // 81920
    const int asmem = 5 * AT_TILE;        // 92160
    cudaFuncSetAttribute(gemm_mma<1>, cudaFuncAttributeMaxDynamicSharedMemorySize, gsmem);
    cudaFuncSetAttribute(gemm_mma<0>, cudaFuncAttributeMaxDynamicSharedMemorySize, gsmem);
    cudaFuncSetAttribute(attn_mma, cudaFuncAttributeMaxDynamicSharedMemorySize, asmem);

    gemm_mma<1><<<dim3(24, 32), 256, gsmem>>>(bq, bk, bv, nullptr);
    attn_mma<<<152, 256, asmem>>>();
    gemm_mma<0><<<dim3(8, 32), 256, gsmem>>>(bo, nullptr, nullptr, out);
}